// round 2
// baseline (speedup 1.0000x reference)
#include <cuda_runtime.h>
#include <mma.h>

using namespace nvcuda;

// Problem constants
#define BATCH 4
#define SEQ   2048
#define EMB   1024
#define NH    16
#define DH    64
#define ROWS  (BATCH * SEQ)        // 8192
#define QKVN  (3 * EMB)            // 3072

// Scratch (allocation-guard-safe device globals)
__device__ float g_qkv[(size_t)ROWS * QKVN];   // 96 MB
__device__ float g_att[(size_t)ROWS * EMB];    // 32 MB

// ---------------------------------------------------------------------------
// tf32 WMMA GEMM: C[M,N] = A[M,K] @ B[K,N], all row-major fp32 in gmem.
// Block tile 128x128, K-step 16. 256 threads = 8 warps (2x4), warp tile 64x32.
// ---------------------------------------------------------------------------
__global__ __launch_bounds__(256)
void gemm_tf32_kernel(const float* __restrict__ A, const float* __restrict__ Bm,
                      float* __restrict__ C, int M, int N, int K) {
    constexpr int BM = 128, BN = 128, BK = 16;
    constexpr int LDA_S = BK + 8;   // 24 floats
    constexpr int LDB_S = BN + 8;   // 136 floats
    __shared__ float As[BM * LDA_S];
    __shared__ float Bs[BK * LDB_S];

    const int tid = threadIdx.x;
    const int wid = tid >> 5;
    const int warp_m = wid >> 2;    // 0..1
    const int warp_n = wid & 3;     // 0..3
    const int m0 = blockIdx.y * BM;
    const int n0 = blockIdx.x * BN;

    wmma::fragment<wmma::accumulator, 16, 16, 8, float> acc[4][2];
    #pragma unroll
    for (int i = 0; i < 4; i++)
        #pragma unroll
        for (int j = 0; j < 2; j++)
            wmma::fill_fragment(acc[i][j], 0.0f);

    for (int k0 = 0; k0 < K; k0 += BK) {
        // Stage A tile: 128 rows x 16 cols (tf32-converted)
        #pragma unroll
        for (int i = tid; i < BM * 4; i += 256) {
            int r = i >> 2, c = (i & 3) * 4;
            float4 v = *(const float4*)&A[(size_t)(m0 + r) * K + k0 + c];
            v.x = wmma::__float_to_tf32(v.x);
            v.y = wmma::__float_to_tf32(v.y);
            v.z = wmma::__float_to_tf32(v.z);
            v.w = wmma::__float_to_tf32(v.w);
            *(float4*)&As[r * LDA_S + c] = v;
        }
        // Stage B tile: 16 rows x 128 cols
        #pragma unroll
        for (int i = tid; i < BK * 32; i += 256) {
            int r = i >> 5, c = (i & 31) * 4;
            float4 v = *(const float4*)&Bm[(size_t)(k0 + r) * N + n0 + c];
            v.x = wmma::__float_to_tf32(v.x);
            v.y = wmma::__float_to_tf32(v.y);
            v.z = wmma::__float_to_tf32(v.z);
            v.w = wmma::__float_to_tf32(v.w);
            *(float4*)&Bs[r * LDB_S + c] = v;
        }
        __syncthreads();

        #pragma unroll
        for (int kk = 0; kk < BK; kk += 8) {
            wmma::fragment<wmma::matrix_a, 16, 16, 8, wmma::precision::tf32, wmma::row_major> af[4];
            wmma::fragment<wmma::matrix_b, 16, 16, 8, wmma::precision::tf32, wmma::row_major> bf[2];
            #pragma unroll
            for (int i = 0; i < 4; i++)
                wmma::load_matrix_sync(af[i], &As[(warp_m * 64 + i * 16) * LDA_S + kk], LDA_S);
            #pragma unroll
            for (int j = 0; j < 2; j++)
                wmma::load_matrix_sync(bf[j], &Bs[kk * LDB_S + warp_n * 32 + j * 16], LDB_S);
            #pragma unroll
            for (int i = 0; i < 4; i++)
                #pragma unroll
                for (int j = 0; j < 2; j++)
                    wmma::mma_sync(acc[i][j], af[i], bf[j], acc[i][j]);
        }
        __syncthreads();
    }

    #pragma unroll
    for (int i = 0; i < 4; i++)
        #pragma unroll
        for (int j = 0; j < 2; j++)
            wmma::store_matrix_sync(
                &C[(size_t)(m0 + warp_m * 64 + i * 16) * N + n0 + warp_n * 32 + j * 16],
                acc[i][j], N, wmma::mem_row_major);
}

// ---------------------------------------------------------------------------
// Flash attention: one block per (bh, 64-query tile). 256 threads = 8 warps.
// Q/K/V/S/O tiles in dynamic smem, wmma tf32 for QK^T and PV, fp32 softmax.
// ---------------------------------------------------------------------------
#define ALD 72  // smem leading dim (floats)

__global__ __launch_bounds__(256)
void flash_attn_kernel() {
    extern __shared__ float sm[];
    float* Qs = sm;                 // 64 x ALD
    float* Ks = Qs + 64 * ALD;
    float* Vs = Ks + 64 * ALD;
    float* Ss = Vs + 64 * ALD;
    float* Os = Ss + 64 * ALD;
    float* m_s = Os + 64 * ALD;     // 64
    float* l_s = m_s + 64;          // 64

    const int tid = threadIdx.x;
    const int wid = tid >> 5;
    const int bh = blockIdx.y;
    const int b = bh >> 4, h = bh & 15;
    const int qb = blockIdx.x;

    const float* qbase = g_qkv + (size_t)(b * SEQ + qb * 64) * QKVN + h * DH;
    const float* kbase = g_qkv + (size_t)(b * SEQ) * QKVN + EMB + h * DH;
    const float* vbase = g_qkv + (size_t)(b * SEQ) * QKVN + 2 * EMB + h * DH;

    // Load Q tile (scaled by 1/sqrt(dh)), init O/m/l
    #pragma unroll
    for (int i = tid; i < 64 * 16; i += 256) {
        int r = i >> 4, c = (i & 15) * 4;
        float4 v = *(const float4*)&qbase[(size_t)r * QKVN + c];
        v.x = wmma::__float_to_tf32(v.x * 0.125f);
        v.y = wmma::__float_to_tf32(v.y * 0.125f);
        v.z = wmma::__float_to_tf32(v.z * 0.125f);
        v.w = wmma::__float_to_tf32(v.w * 0.125f);
        *(float4*)&Qs[r * ALD + c] = v;
        *(float4*)&Os[r * ALD + c] = make_float4(0.f, 0.f, 0.f, 0.f);
    }
    if (tid < 64) { m_s[tid] = -1e30f; l_s[tid] = 0.0f; }
    __syncthreads();

    const int row = tid >> 2;         // 0..63 (softmax row)
    const int qc  = (tid & 3) * 16;   // this thread's 16-col slice

    const int tm  = wid >> 1;         // warp's output tile row  (0..3)
    const int tn0 = (wid & 1) * 2;    // warp's first tile col   (0 or 2)

    for (int j = 0; j < SEQ / 64; j++) {
        // Stage K and V tiles
        #pragma unroll
        for (int i = tid; i < 64 * 16; i += 256) {
            int r = i >> 4, c = (i & 15) * 4;
            size_t goff = (size_t)(j * 64 + r) * QKVN + c;
            float4 kv = *(const float4*)&kbase[goff];
            kv.x = wmma::__float_to_tf32(kv.x);
            kv.y = wmma::__float_to_tf32(kv.y);
            kv.z = wmma::__float_to_tf32(kv.z);
            kv.w = wmma::__float_to_tf32(kv.w);
            *(float4*)&Ks[r * ALD + c] = kv;
            float4 vv = *(const float4*)&vbase[goff];
            vv.x = wmma::__float_to_tf32(vv.x);
            vv.y = wmma::__float_to_tf32(vv.y);
            vv.z = wmma::__float_to_tf32(vv.z);
            vv.w = wmma::__float_to_tf32(vv.w);
            *(float4*)&Vs[r * ALD + c] = vv;
        }
        __syncthreads();

        // S = Q @ K^T  (already scaled via Q)
        {
            wmma::fragment<wmma::accumulator, 16, 16, 8, float> sacc[2];
            wmma::fill_fragment(sacc[0], 0.0f);
            wmma::fill_fragment(sacc[1], 0.0f);
            #pragma unroll
            for (int k = 0; k < 8; k++) {
                wmma::fragment<wmma::matrix_a, 16, 16, 8, wmma::precision::tf32, wmma::row_major> aq;
                wmma::load_matrix_sync(aq, &Qs[tm * 16 * ALD + k * 8], ALD);
                #pragma unroll
                for (int t = 0; t < 2; t++) {
                    wmma::fragment<wmma::matrix_b, 16, 16, 8, wmma::precision::tf32, wmma::col_major> bk;
                    wmma::load_matrix_sync(bk, &Ks[(tn0 + t) * 16 * ALD + k * 8], ALD);
                    wmma::mma_sync(sacc[t], aq, bk, sacc[t]);
                }
            }
            #pragma unroll
            for (int t = 0; t < 2; t++)
                wmma::store_matrix_sync(&Ss[tm * 16 * ALD + (tn0 + t) * 16], sacc[t],
                                        ALD, wmma::mem_row_major);
        }
        __syncthreads();

        // Online softmax (4 threads per row, 16 cols each)
        {
            float sv[16];
            float mloc = -1e30f;
            #pragma unroll
            for (int c = 0; c < 16; c++) {
                sv[c] = Ss[row * ALD + qc + c];
                mloc = fmaxf(mloc, sv[c]);
            }
            mloc = fmaxf(mloc, __shfl_xor_sync(0xffffffffu, mloc, 1));
            mloc = fmaxf(mloc, __shfl_xor_sync(0xffffffffu, mloc, 2));
            float mold = m_s[row];
            float mnew = fmaxf(mold, mloc);
            float corr = __expf(mold - mnew);
            float ssum = 0.0f;
            #pragma unroll
            for (int c = 0; c < 16; c++) {
                float p = __expf(sv[c] - mnew);
                ssum += p;
                Ss[row * ALD + qc + c] = wmma::__float_to_tf32(p);
            }
            ssum += __shfl_xor_sync(0xffffffffu, ssum, 1);
            ssum += __shfl_xor_sync(0xffffffffu, ssum, 2);
            if ((tid & 3) == 0) {
                m_s[row] = mnew;
                l_s[row] = l_s[row] * corr + ssum;
            }
            // Rescale accumulated O rows (corr identical on all 4 lanes of row)
            #pragma unroll
            for (int c = 0; c < 16; c++)
                Os[row * ALD + qc + c] *= corr;
        }
        __syncthreads();

        // O += P @ V
        {
            #pragma unroll
            for (int t = 0; t < 2; t++) {
                wmma::fragment<wmma::accumulator, 16, 16, 8, float> oacc;
                wmma::load_matrix_sync(oacc, &Os[tm * 16 * ALD + (tn0 + t) * 16],
                                       ALD, wmma::mem_row_major);
                #pragma unroll
                for (int k = 0; k < 8; k++) {
                    wmma::fragment<wmma::matrix_a, 16, 16, 8, wmma::precision::tf32, wmma::row_major> ap;
                    wmma::load_matrix_sync(ap, &Ss[tm * 16 * ALD + k * 8], ALD);
                    wmma::fragment<wmma::matrix_b, 16, 16, 8, wmma::precision::tf32, wmma::row_major> bv;
                    wmma::load_matrix_sync(bv, &Vs[k * 8 * ALD + (tn0 + t) * 16], ALD);
                    wmma::mma_sync(oacc, ap, bv, oacc);
                }
                wmma::store_matrix_sync(&Os[tm * 16 * ALD + (tn0 + t) * 16], oacc,
                                        ALD, wmma::mem_row_major);
            }
        }
        __syncthreads();
    }

    // Normalize and write out
    const float inv_l = 1.0f / l_s[row];
    const size_t orow = (size_t)(b * SEQ + qb * 64 + row) * EMB + h * DH + qc;
    #pragma unroll
    for (int c = 0; c < 16; c += 4) {
        float4 v = *(float4*)&Os[row * ALD + qc + c];
        v.x *= inv_l; v.y *= inv_l; v.z *= inv_l; v.w *= inv_l;
        *(float4*)&g_att[orow + c] = v;
    }
}

// ---------------------------------------------------------------------------
// Launch
// ---------------------------------------------------------------------------
extern "C" void kernel_launch(void* const* d_in, const int* in_sizes, int n_in,
                              void* d_out, int out_size) {
    const float* x     = (const float*)d_in[0];   // [4,2048,1024]
    const float* w_qkv = (const float*)d_in[1];   // [1024,3072]
    const float* w_out = (const float*)d_in[2];   // [1024,1024]
    float* out = (float*)d_out;                   // [4,2048,1024]

    float* qkv;
    float* att;
    cudaGetSymbolAddress((void**)&qkv, g_qkv);
    cudaGetSymbolAddress((void**)&att, g_att);

    const int attn_smem = (5 * 64 * ALD + 128) * (int)sizeof(float);  // ~91 KB
    cudaFuncSetAttribute(flash_attn_kernel,
                         cudaFuncAttributeMaxDynamicSharedMemorySize, attn_smem);

    // 1) QKV projection: [8192,1024] @ [1024,3072] -> g_qkv
    {
        dim3 grid(QKVN / 128, ROWS / 128);
        gemm_tf32_kernel<<<grid, 256>>>(x, w_qkv, qkv, ROWS, QKVN, EMB);
    }
    // 2) Flash attention: g_qkv -> g_att
    {
        dim3 grid(SEQ / 64, BATCH * NH);
        flash_attn_kernel<<<grid, 256, attn_smem>>>();
    }
    // 3) Output projection: [8192,1024] @ [1024,1024] -> d_out
    {
        dim3 grid(EMB / 128, ROWS / 128);
        gemm_tf32_kernel<<<grid, 256>>>(att, w_out, out, ROWS, EMB, EMB);
    }
}

// round 4
// speedup vs baseline: 1.8020x; 1.8020x over previous
#include <cuda_runtime.h>
#include <mma.h>

using namespace nvcuda;

// Problem constants
#define BATCH 4
#define SEQ   2048
#define EMB   1024
#define NH    16
#define DH    64
#define ROWS  (BATCH * SEQ)        // 8192
#define QKVN  (3 * EMB)            // 3072

// Scratch (allocation-guard-safe device globals)
__device__ float g_qkv[(size_t)ROWS * QKVN];   // 96 MB
__device__ float g_att[(size_t)ROWS * EMB];    // 32 MB

// ---------------------------------------------------------------------------
// tf32 WMMA GEMM: C[M,N] = A[M,K] @ B[K,N]  (unchanged from round 2)
// ---------------------------------------------------------------------------
__global__ __launch_bounds__(256)
void gemm_tf32_kernel(const float* __restrict__ A, const float* __restrict__ Bm,
                      float* __restrict__ C, int M, int N, int K) {
    constexpr int BM = 128, BN = 128, BK = 16;
    constexpr int LDA_S = BK + 8;
    constexpr int LDB_S = BN + 8;
    __shared__ float As[BM * LDA_S];
    __shared__ float Bs[BK * LDB_S];

    const int tid = threadIdx.x;
    const int wid = tid >> 5;
    const int warp_m = wid >> 2;
    const int warp_n = wid & 3;
    const int m0 = blockIdx.y * BM;
    const int n0 = blockIdx.x * BN;

    wmma::fragment<wmma::accumulator, 16, 16, 8, float> acc[4][2];
    #pragma unroll
    for (int i = 0; i < 4; i++)
        #pragma unroll
        for (int j = 0; j < 2; j++)
            wmma::fill_fragment(acc[i][j], 0.0f);

    for (int k0 = 0; k0 < K; k0 += BK) {
        #pragma unroll
        for (int i = tid; i < BM * 4; i += 256) {
            int r = i >> 2, c = (i & 3) * 4;
            float4 v = *(const float4*)&A[(size_t)(m0 + r) * K + k0 + c];
            v.x = wmma::__float_to_tf32(v.x);
            v.y = wmma::__float_to_tf32(v.y);
            v.z = wmma::__float_to_tf32(v.z);
            v.w = wmma::__float_to_tf32(v.w);
            *(float4*)&As[r * LDA_S + c] = v;
        }
        #pragma unroll
        for (int i = tid; i < BK * 32; i += 256) {
            int r = i >> 5, c = (i & 31) * 4;
            float4 v = *(const float4*)&Bm[(size_t)(k0 + r) * N + n0 + c];
            v.x = wmma::__float_to_tf32(v.x);
            v.y = wmma::__float_to_tf32(v.y);
            v.z = wmma::__float_to_tf32(v.z);
            v.w = wmma::__float_to_tf32(v.w);
            *(float4*)&Bs[r * LDB_S + c] = v;
        }
        __syncthreads();

        #pragma unroll
        for (int kk = 0; kk < BK; kk += 8) {
            wmma::fragment<wmma::matrix_a, 16, 16, 8, wmma::precision::tf32, wmma::row_major> af[4];
            wmma::fragment<wmma::matrix_b, 16, 16, 8, wmma::precision::tf32, wmma::row_major> bf[2];
            #pragma unroll
            for (int i = 0; i < 4; i++)
                wmma::load_matrix_sync(af[i], &As[(warp_m * 64 + i * 16) * LDA_S + kk], LDA_S);
            #pragma unroll
            for (int j = 0; j < 2; j++)
                wmma::load_matrix_sync(bf[j], &Bs[kk * LDB_S + warp_n * 32 + j * 16], LDB_S);
            #pragma unroll
            for (int i = 0; i < 4; i++)
                #pragma unroll
                for (int j = 0; j < 2; j++)
                    wmma::mma_sync(acc[i][j], af[i], bf[j], acc[i][j]);
        }
        __syncthreads();
    }

    #pragma unroll
    for (int i = 0; i < 4; i++)
        #pragma unroll
        for (int j = 0; j < 2; j++)
            wmma::store_matrix_sync(
                &C[(size_t)(m0 + warp_m * 64 + i * 16) * N + n0 + warp_n * 32 + j * 16],
                acc[i][j], N, wmma::mem_row_major);
}

// ---------------------------------------------------------------------------
// Flash attention v2: raw PTX m16n8k8 tf32 mma, register-resident S and O.
// Block = 128 threads = 4 warps. Each warp owns 16 query rows (Br=64 total).
// KV tile Bc=64. Documented fragment layouts:
//   A (16x8):  a0:(r=l/4,   c=l%4)  a1:(r=l/4+8, c=l%4)
//              a2:(r=l/4,   c=l%4+4) a3:(r=l/4+8, c=l%4+4)
//   B (8x8,col): b0:(k=l%4, n=l/4)  b1:(k=l%4+4, n=l/4)
//   C (16x8):  c0,c1:(r=l/4, c=2*(l%4)+{0,1})  c2,c3:(r=l/4+8, same cols)
// ---------------------------------------------------------------------------
#define SLD 72                         // smem leading dim (floats)
#define K_OFF 0
#define V_OFF (64 * SLD)
#define P_OFF (2 * 64 * SLD)
#define ATTN_SMEM_BYTES ((2 * 64 * SLD + 4 * 16 * SLD) * 4)   // 55296 B

__device__ __forceinline__ void mma_m16n8k8(float d[4], const float a[4],
                                            float b0, float b1) {
    const unsigned* A = reinterpret_cast<const unsigned*>(a);
    asm volatile(
        "mma.sync.aligned.m16n8k8.row.col.f32.tf32.tf32.f32 "
        "{%0,%1,%2,%3}, {%4,%5,%6,%7}, {%8,%9}, {%0,%1,%2,%3};\n"
        : "+f"(d[0]), "+f"(d[1]), "+f"(d[2]), "+f"(d[3])
        : "r"(A[0]), "r"(A[1]), "r"(A[2]), "r"(A[3]),
          "r"(__float_as_uint(b0)), "r"(__float_as_uint(b1)));
}

__global__ __launch_bounds__(128)
void flash_attn2_kernel() {
    extern __shared__ float sm[];
    float* Ks = sm + K_OFF;
    float* Vs = sm + V_OFF;

    const int tid  = threadIdx.x;
    const int lane = tid & 31;
    const int wid  = tid >> 5;
    const int gi   = lane >> 2;    // group id  0..7
    const int ti   = lane & 3;     // thread-in-group 0..3
    const int bh = blockIdx.y;
    const int b = bh >> 4, h = bh & 15;
    const int qb = blockIdx.x;

    const float* qbase = g_qkv + (size_t)(b * SEQ + qb * 64) * QKVN + h * DH;
    const float* kbase = g_qkv + (size_t)(b * SEQ) * QKVN + EMB + h * DH;
    const float* vbase = g_qkv + (size_t)(b * SEQ) * QKVN + 2 * EMB + h * DH;

    // ---- Stage Q (scaled by 1/8, tf32) via Ks buffer, then pull into A-frags
    #pragma unroll
    for (int i = tid; i < 64 * 16; i += 128) {
        int r = i >> 4, c = (i & 15) * 4;
        float4 v = *(const float4*)&qbase[(size_t)r * QKVN + c];
        v.x = wmma::__float_to_tf32(v.x * 0.125f);
        v.y = wmma::__float_to_tf32(v.y * 0.125f);
        v.z = wmma::__float_to_tf32(v.z * 0.125f);
        v.w = wmma::__float_to_tf32(v.w * 0.125f);
        *(float4*)&Ks[r * SLD + c] = v;
    }
    __syncthreads();

    const int r0 = wid * 16 + gi;   // warp-local query rows (within 64-tile)
    const int r1 = r0 + 8;

    float qa[8][4];
    #pragma unroll
    for (int kc = 0; kc < 8; kc++) {
        qa[kc][0] = Ks[r0 * SLD + kc * 8 + ti];
        qa[kc][1] = Ks[r1 * SLD + kc * 8 + ti];
        qa[kc][2] = Ks[r0 * SLD + kc * 8 + ti + 4];
        qa[kc][3] = Ks[r1 * SLD + kc * 8 + ti + 4];
    }
    __syncthreads();

    float o[8][4];
    #pragma unroll
    for (int j = 0; j < 8; j++)
        o[j][0] = o[j][1] = o[j][2] = o[j][3] = 0.0f;
    float m0 = -1e30f, m1 = -1e30f, l0 = 0.0f, l1 = 0.0f;

    float* Pw = sm + P_OFF + wid * 16 * SLD;   // warp-private P tile

    for (int jt = 0; jt < SEQ / 64; jt++) {
        // ---- Stage K, V tile (tf32-converted)
        #pragma unroll
        for (int i = tid; i < 64 * 16; i += 128) {
            int r = i >> 4, c = (i & 15) * 4;
            size_t g = (size_t)(jt * 64 + r) * QKVN + c;
            float4 kv = *(const float4*)&kbase[g];
            kv.x = wmma::__float_to_tf32(kv.x);
            kv.y = wmma::__float_to_tf32(kv.y);
            kv.z = wmma::__float_to_tf32(kv.z);
            kv.w = wmma::__float_to_tf32(kv.w);
            *(float4*)&Ks[r * SLD + c] = kv;
            float4 vv = *(const float4*)&vbase[g];
            vv.x = wmma::__float_to_tf32(vv.x);
            vv.y = wmma::__float_to_tf32(vv.y);
            vv.z = wmma::__float_to_tf32(vv.z);
            vv.w = wmma::__float_to_tf32(vv.w);
            *(float4*)&Vs[r * SLD + c] = vv;
        }
        __syncthreads();

        // ---- S = Q @ K^T   (16 x 64 per warp, register-resident)
        float s[8][4];
        #pragma unroll
        for (int j = 0; j < 8; j++)
            s[j][0] = s[j][1] = s[j][2] = s[j][3] = 0.0f;
        #pragma unroll
        for (int kc = 0; kc < 8; kc++) {
            #pragma unroll
            for (int j = 0; j < 8; j++) {
                float b0 = Ks[(j * 8 + gi) * SLD + kc * 8 + ti];
                float b1 = Ks[(j * 8 + gi) * SLD + kc * 8 + ti + 4];
                mma_m16n8k8(s[j], qa[kc], b0, b1);
            }
        }

        // ---- Online softmax (rows r0, r1 per thread; quad reduction)
        float a0 = -1e30f, a1 = -1e30f;
        #pragma unroll
        for (int j = 0; j < 8; j++) {
            a0 = fmaxf(a0, fmaxf(s[j][0], s[j][1]));
            a1 = fmaxf(a1, fmaxf(s[j][2], s[j][3]));
        }
        a0 = fmaxf(a0, __shfl_xor_sync(0xffffffffu, a0, 1));
        a0 = fmaxf(a0, __shfl_xor_sync(0xffffffffu, a0, 2));
        a1 = fmaxf(a1, __shfl_xor_sync(0xffffffffu, a1, 1));
        a1 = fmaxf(a1, __shfl_xor_sync(0xffffffffu, a1, 2));

        float mn0 = fmaxf(m0, a0), mn1 = fmaxf(m1, a1);
        float c0 = __expf(m0 - mn0), c1 = __expf(m1 - mn1);
        float sum0 = 0.0f, sum1 = 0.0f;
        #pragma unroll
        for (int j = 0; j < 8; j++) {
            float p00 = __expf(s[j][0] - mn0);
            float p01 = __expf(s[j][1] - mn0);
            float p10 = __expf(s[j][2] - mn1);
            float p11 = __expf(s[j][3] - mn1);
            sum0 += p00 + p01;
            sum1 += p10 + p11;
            s[j][0] = wmma::__float_to_tf32(p00);
            s[j][1] = wmma::__float_to_tf32(p01);
            s[j][2] = wmma::__float_to_tf32(p10);
            s[j][3] = wmma::__float_to_tf32(p11);
        }
        sum0 += __shfl_xor_sync(0xffffffffu, sum0, 1);
        sum0 += __shfl_xor_sync(0xffffffffu, sum0, 2);
        sum1 += __shfl_xor_sync(0xffffffffu, sum1, 1);
        sum1 += __shfl_xor_sync(0xffffffffu, sum1, 2);

        m0 = mn0; m1 = mn1;
        l0 = l0 * c0 + sum0;
        l1 = l1 * c1 + sum1;

        // Rescale register-resident O (row ownership known from C layout)
        #pragma unroll
        for (int j = 0; j < 8; j++) {
            o[j][0] *= c0; o[j][1] *= c0;
            o[j][2] *= c1; o[j][3] *= c1;
        }

        // ---- P: C-layout regs -> warp-private smem -> A-layout regs
        #pragma unroll
        for (int j = 0; j < 8; j++) {
            *(float2*)&Pw[gi * SLD + j * 8 + 2 * ti]       = make_float2(s[j][0], s[j][1]);
            *(float2*)&Pw[(gi + 8) * SLD + j * 8 + 2 * ti] = make_float2(s[j][2], s[j][3]);
        }
        __syncwarp();

        // ---- O += P @ V
        #pragma unroll
        for (int kc = 0; kc < 8; kc++) {
            float pa[4];
            pa[0] = Pw[gi * SLD + kc * 8 + ti];
            pa[1] = Pw[(gi + 8) * SLD + kc * 8 + ti];
            pa[2] = Pw[gi * SLD + kc * 8 + ti + 4];
            pa[3] = Pw[(gi + 8) * SLD + kc * 8 + ti + 4];
            #pragma unroll
            for (int j = 0; j < 8; j++) {
                float b0 = Vs[(kc * 8 + ti) * SLD + j * 8 + gi];
                float b1 = Vs[(kc * 8 + ti + 4) * SLD + j * 8 + gi];
                mma_m16n8k8(o[j], pa, b0, b1);
            }
        }
        __syncthreads();   // protects Ks/Vs (next stage) and Pw (next write)
    }

    // ---- Epilogue: normalize and write to g_att
    const float inv0 = 1.0f / l0;
    const float inv1 = 1.0f / l1;
    const size_t row0 = (size_t)(b * SEQ + qb * 64 + r0);
    const size_t row1 = row0 + 8;
    #pragma unroll
    for (int j = 0; j < 8; j++) {
        size_t col = h * DH + j * 8 + 2 * ti;
        *(float2*)&g_att[row0 * EMB + col] = make_float2(o[j][0] * inv0, o[j][1] * inv0);
        *(float2*)&g_att[row1 * EMB + col] = make_float2(o[j][2] * inv1, o[j][3] * inv1);
    }
}

// ---------------------------------------------------------------------------
// Launch
// ---------------------------------------------------------------------------
extern "C" void kernel_launch(void* const* d_in, const int* in_sizes, int n_in,
                              void* d_out, int out_size) {
    const float* x     = (const float*)d_in[0];   // [4,2048,1024]
    const float* w_qkv = (const float*)d_in[1];   // [1024,3072]
    const float* w_out = (const float*)d_in[2];   // [1024,1024]
    float* out = (float*)d_out;                   // [4,2048,1024]

    float* qkv;
    float* att;
    cudaGetSymbolAddress((void**)&qkv, g_qkv);
    cudaGetSymbolAddress((void**)&att, g_att);

    cudaFuncSetAttribute(flash_attn2_kernel,
                         cudaFuncAttributeMaxDynamicSharedMemorySize,
                         ATTN_SMEM_BYTES);

    // 1) QKV projection: [8192,1024] @ [1024,3072] -> g_qkv
    {
        dim3 grid(QKVN / 128, ROWS / 128);
        gemm_tf32_kernel<<<grid, 256>>>(x, w_qkv, qkv, ROWS, QKVN, EMB);
    }
    // 2) Flash attention: g_qkv -> g_att
    {
        dim3 grid(SEQ / 64, BATCH * NH);
        flash_attn2_kernel<<<grid, 128, ATTN_SMEM_BYTES>>>();
    }
    // 3) Output projection: [8192,1024] @ [1024,1024] -> d_out
    {
        dim3 grid(EMB / 128, ROWS / 128);
        gemm_tf32_kernel<<<grid, 256>>>(att, w_out, out, ROWS, EMB, EMB);
    }
}

// round 6
// speedup vs baseline: 2.5343x; 1.4064x over previous
#include <cuda_runtime.h>
#include <cstdint>

// Problem constants
#define BATCH 4
#define SEQ   2048
#define EMB   1024
#define NH    16
#define DH    64
#define ROWS  (BATCH * SEQ)        // 8192
#define QKVN  (3 * EMB)            // 3072

// Scratch (allocation-guard-safe device globals)
__device__ float g_qkv[(size_t)ROWS * QKVN];   // 96 MB (tf32-rounded)
__device__ float g_att[(size_t)ROWS * EMB];    // 32 MB (tf32-rounded)
__device__ float g_x  [(size_t)ROWS * EMB];    // 32 MB (tf32-rounded x)
__device__ float g_wq [(size_t)EMB * QKVN];    // 12 MB (tf32-rounded w_qkv)
__device__ float g_wo [(size_t)EMB * EMB];     //  4 MB (tf32-rounded w_out)

// ---------------------------------------------------------------------------
// Helpers
// ---------------------------------------------------------------------------
__device__ __forceinline__ float to_tf32(float x) {
    float r;
    asm("cvt.rna.tf32.f32 %0, %1;" : "=f"(r) : "f"(x));
    return r;
}

__device__ __forceinline__ unsigned smem_u32(const void* p) {
    return (unsigned)__cvta_generic_to_shared(p);
}

__device__ __forceinline__ void cp16(unsigned dst, const void* src) {
    asm volatile("cp.async.cg.shared.global [%0], [%1], 16;"
                 :: "r"(dst), "l"(__cvta_generic_to_global(src)));
}
#define CP_COMMIT() asm volatile("cp.async.commit_group;" ::: "memory")
#define CP_WAIT(n)  asm volatile("cp.async.wait_group %0;" :: "n"(n) : "memory")

__device__ __forceinline__ void mma_m16n8k8(float d[4], const float a[4],
                                            float b0, float b1) {
    const unsigned* A = reinterpret_cast<const unsigned*>(a);
    asm volatile(
        "mma.sync.aligned.m16n8k8.row.col.f32.tf32.tf32.f32 "
        "{%0,%1,%2,%3}, {%4,%5,%6,%7}, {%8,%9}, {%0,%1,%2,%3};\n"
        : "+f"(d[0]), "+f"(d[1]), "+f"(d[2]), "+f"(d[3])
        : "r"(A[0]), "r"(A[1]), "r"(A[2]), "r"(A[3]),
          "r"(__float_as_uint(b0)), "r"(__float_as_uint(b1)));
}

// ---------------------------------------------------------------------------
// Pre-round pass: out[i] = tf32(in[i]) (float4 granularity, exact-size grid)
// ---------------------------------------------------------------------------
__global__ __launch_bounds__(256)
void round_tf32_kernel(const float* __restrict__ in, float* __restrict__ out) {
    size_t i = ((size_t)blockIdx.x * 256 + threadIdx.x) * 4;
    float4 v = *(const float4*)(in + i);
    v.x = to_tf32(v.x); v.y = to_tf32(v.y);
    v.z = to_tf32(v.z); v.w = to_tf32(v.w);
    *(float4*)(out + i) = v;
}

// ---------------------------------------------------------------------------
// tf32 mma.sync GEMM: C[M,N] = A[M,K] @ B[K,N], A/B already tf32-rounded.
// Block tile 128x128, BK=32, cp.async double-buffered, 256 threads = 8 warps
// (2x4), warp tile 64x32 register-resident (m16n8k8).
//   A smem: [128][36] floats (row-major, K-contig)   18432 B
//   B smem: [32][136] floats (row-major, N-contig)   17408 B
// ---------------------------------------------------------------------------
#define G_LDSA 36
#define G_LDSB 136
#define G_ABYTES (128 * G_LDSA * 4)
#define G_STAGE  (G_ABYTES + 32 * G_LDSB * 4)     // 35840
#define GEMM_SMEM_BYTES (2 * G_STAGE)             // 71680

template<bool ROUND>
__global__ __launch_bounds__(256)
void gemm_mma_kernel(const float* __restrict__ A, const float* __restrict__ B,
                     float* __restrict__ C, int N, int K) {
    extern __shared__ char smc[];
    float* Asm[2] = { (float*)smc, (float*)(smc + G_STAGE) };
    float* Bsm[2] = { (float*)(smc + G_ABYTES), (float*)(smc + G_STAGE + G_ABYTES) };
    const unsigned abase0 = smem_u32(Asm[0]);
    const unsigned bbase0 = smem_u32(Bsm[0]);

    const int tid  = threadIdx.x;
    const int lane = tid & 31;
    const int wid  = tid >> 5;
    const int gi   = lane >> 2;
    const int ti   = lane & 3;
    const int warp_m = wid >> 2;    // 0..1
    const int warp_n = wid & 3;     // 0..3
    const int m0 = blockIdx.y * 128;
    const int n0 = blockIdx.x * 128;

    // Staging (raw tf32 copy via cp.async)
    const int ar = tid >> 3, ac4 = tid & 7;          // A: 128 rows x 8 float4
    const int bk = tid >> 5, bc4 = tid & 31;         // B: 32 rows x 32 float4
    auto stage = [&](int t, int buf) {
        const unsigned ab = abase0 + buf * G_STAGE;
        const unsigned bb = bbase0 + buf * G_STAGE;
        const float* Ag = A + (size_t)m0 * K + t * 32;
        const float* Bg = B + (size_t)(t * 32) * N + n0;
        #pragma unroll
        for (int i = 0; i < 4; i++) {
            int r = ar + i * 32;
            cp16(ab + r * (G_LDSA * 4) + ac4 * 16, Ag + (size_t)r * K + ac4 * 4);
        }
        #pragma unroll
        for (int i = 0; i < 4; i++) {
            int k = bk + i * 8;
            cp16(bb + k * (G_LDSB * 4) + bc4 * 16, Bg + (size_t)k * N + bc4 * 4);
        }
    };

    float acc[4][4][4];
    #pragma unroll
    for (int i = 0; i < 4; i++)
        #pragma unroll
        for (int j = 0; j < 4; j++)
            acc[i][j][0] = acc[i][j][1] = acc[i][j][2] = acc[i][j][3] = 0.0f;

    const int KT = K >> 5;
    stage(0, 0);
    CP_COMMIT();

    for (int t = 0; t < KT; t++) {
        const int buf = t & 1;
        if (t + 1 < KT) stage(t + 1, buf ^ 1);
        CP_COMMIT();
        CP_WAIT(1);
        __syncthreads();

        const float* As = Asm[buf];
        const float* Bs = Bsm[buf];
        #pragma unroll
        for (int s = 0; s < 4; s++) {
            float af[4][4];
            float bf[4][2];
            #pragma unroll
            for (int mi = 0; mi < 4; mi++) {
                const int rm = warp_m * 64 + mi * 16;
                af[mi][0] = As[(rm + gi)     * G_LDSA + s * 8 + ti];
                af[mi][1] = As[(rm + gi + 8) * G_LDSA + s * 8 + ti];
                af[mi][2] = As[(rm + gi)     * G_LDSA + s * 8 + ti + 4];
                af[mi][3] = As[(rm + gi + 8) * G_LDSA + s * 8 + ti + 4];
            }
            #pragma unroll
            for (int nj = 0; nj < 4; nj++) {
                const int nn = warp_n * 32 + nj * 8;
                bf[nj][0] = Bs[(s * 8 + ti)     * G_LDSB + nn + gi];
                bf[nj][1] = Bs[(s * 8 + ti + 4) * G_LDSB + nn + gi];
            }
            #pragma unroll
            for (int mi = 0; mi < 4; mi++)
                #pragma unroll
                for (int nj = 0; nj < 4; nj++)
                    mma_m16n8k8(acc[mi][nj], af[mi], bf[nj][0], bf[nj][1]);
        }
        __syncthreads();
    }

    // Epilogue: direct STG.64, optional tf32 rounding of the result
    #pragma unroll
    for (int mi = 0; mi < 4; mi++) {
        const int row = m0 + warp_m * 64 + mi * 16 + gi;
        #pragma unroll
        for (int nj = 0; nj < 4; nj++) {
            const int col = n0 + warp_n * 32 + nj * 8 + 2 * ti;
            float2 v0 = make_float2(acc[mi][nj][0], acc[mi][nj][1]);
            float2 v1 = make_float2(acc[mi][nj][2], acc[mi][nj][3]);
            if (ROUND) {
                v0.x = to_tf32(v0.x); v0.y = to_tf32(v0.y);
                v1.x = to_tf32(v1.x); v1.y = to_tf32(v1.y);
            }
            *(float2*)&C[(size_t)row * N + col]       = v0;
            *(float2*)&C[(size_t)(row + 8) * N + col] = v1;
        }
    }
}

// ---------------------------------------------------------------------------
// Flash attention: raw m16n8k8 tf32 mma, register-resident S and O.
// 128 threads = 4 warps, Br=64, Bc=64. Inputs (g_qkv) already tf32-rounded,
// so K/V staging is a pure cp.async copy.
// ---------------------------------------------------------------------------
#define SLD 72
#define V_OFF (64 * SLD)
#define P_OFF (2 * 64 * SLD)
#define ATTN_SMEM_BYTES ((2 * 64 * SLD + 4 * 16 * SLD) * 4)   // 55296 B

__global__ __launch_bounds__(128)
void flash_attn2_kernel() {
    extern __shared__ float sm[];
    float* Ks = sm;
    float* Vs = sm + V_OFF;

    const int tid  = threadIdx.x;
    const int lane = tid & 31;
    const int wid  = tid >> 5;
    const int gi   = lane >> 2;
    const int ti   = lane & 3;
    const int bh = blockIdx.y;
    const int b = bh >> 4, h = bh & 15;
    const int qb = blockIdx.x;

    const float* qbase = g_qkv + (size_t)(b * SEQ + qb * 64) * QKVN + h * DH;
    const float* kbase = g_qkv + (size_t)(b * SEQ) * QKVN + EMB + h * DH;
    const float* vbase = g_qkv + (size_t)(b * SEQ) * QKVN + 2 * EMB + h * DH;
    const unsigned ksb = smem_u32(Ks);
    const unsigned vsb = smem_u32(Vs);

    // ---- Stage Q (x0.125 — exact on tf32 values) via Ks buffer
    #pragma unroll
    for (int i = tid; i < 64 * 16; i += 128) {
        int r = i >> 4, c = (i & 15) * 4;
        float4 v = *(const float4*)&qbase[(size_t)r * QKVN + c];
        v.x *= 0.125f; v.y *= 0.125f; v.z *= 0.125f; v.w *= 0.125f;
        *(float4*)&Ks[r * SLD + c] = v;
    }
    __syncthreads();

    const int r0 = wid * 16 + gi;
    const int r1 = r0 + 8;

    float qa[8][4];
    #pragma unroll
    for (int kc = 0; kc < 8; kc++) {
        qa[kc][0] = Ks[r0 * SLD + kc * 8 + ti];
        qa[kc][1] = Ks[r1 * SLD + kc * 8 + ti];
        qa[kc][2] = Ks[r0 * SLD + kc * 8 + ti + 4];
        qa[kc][3] = Ks[r1 * SLD + kc * 8 + ti + 4];
    }
    __syncthreads();

    float o[8][4];
    #pragma unroll
    for (int j = 0; j < 8; j++)
        o[j][0] = o[j][1] = o[j][2] = o[j][3] = 0.0f;
    float m0 = -1e30f, m1 = -1e30f, l0 = 0.0f, l1 = 0.0f;

    float* Pw = sm + P_OFF + wid * 16 * SLD;

    for (int jt = 0; jt < SEQ / 64; jt++) {
        // ---- Stage K, V tile: pure 16B async copies
        #pragma unroll
        for (int i = tid; i < 64 * 16; i += 128) {
            int r = i >> 4, c = i & 15;
            size_t g = (size_t)(jt * 64 + r) * QKVN + c * 4;
            unsigned so = r * (SLD * 4) + c * 16;
            cp16(ksb + so, kbase + g);
            cp16(vsb + so, vbase + g);
        }
        CP_COMMIT();
        CP_WAIT(0);
        __syncthreads();

        // ---- S = Q @ K^T
        float s[8][4];
        #pragma unroll
        for (int j = 0; j < 8; j++)
            s[j][0] = s[j][1] = s[j][2] = s[j][3] = 0.0f;
        #pragma unroll
        for (int kc = 0; kc < 8; kc++) {
            #pragma unroll
            for (int j = 0; j < 8; j++) {
                float b0 = Ks[(j * 8 + gi) * SLD + kc * 8 + ti];
                float b1 = Ks[(j * 8 + gi) * SLD + kc * 8 + ti + 4];
                mma_m16n8k8(s[j], qa[kc], b0, b1);
            }
        }

        // ---- Online softmax
        float a0 = -1e30f, a1 = -1e30f;
        #pragma unroll
        for (int j = 0; j < 8; j++) {
            a0 = fmaxf(a0, fmaxf(s[j][0], s[j][1]));
            a1 = fmaxf(a1, fmaxf(s[j][2], s[j][3]));
        }
        a0 = fmaxf(a0, __shfl_xor_sync(0xffffffffu, a0, 1));
        a0 = fmaxf(a0, __shfl_xor_sync(0xffffffffu, a0, 2));
        a1 = fmaxf(a1, __shfl_xor_sync(0xffffffffu, a1, 1));
        a1 = fmaxf(a1, __shfl_xor_sync(0xffffffffu, a1, 2));

        float mn0 = fmaxf(m0, a0), mn1 = fmaxf(m1, a1);
        float c0 = __expf(m0 - mn0), c1 = __expf(m1 - mn1);
        float sum0 = 0.0f, sum1 = 0.0f;
        #pragma unroll
        for (int j = 0; j < 8; j++) {
            float p00 = __expf(s[j][0] - mn0);
            float p01 = __expf(s[j][1] - mn0);
            float p10 = __expf(s[j][2] - mn1);
            float p11 = __expf(s[j][3] - mn1);
            sum0 += p00 + p01;
            sum1 += p10 + p11;
            s[j][0] = to_tf32(p00);
            s[j][1] = to_tf32(p01);
            s[j][2] = to_tf32(p10);
            s[j][3] = to_tf32(p11);
        }
        sum0 += __shfl_xor_sync(0xffffffffu, sum0, 1);
        sum0 += __shfl_xor_sync(0xffffffffu, sum0, 2);
        sum1 += __shfl_xor_sync(0xffffffffu, sum1, 1);
        sum1 += __shfl_xor_sync(0xffffffffu, sum1, 2);

        m0 = mn0; m1 = mn1;
        l0 = l0 * c0 + sum0;
        l1 = l1 * c1 + sum1;

        #pragma unroll
        for (int j = 0; j < 8; j++) {
            o[j][0] *= c0; o[j][1] *= c0;
            o[j][2] *= c1; o[j][3] *= c1;
        }

        // ---- P: C-layout regs -> warp-private smem -> A-layout regs
        #pragma unroll
        for (int j = 0; j < 8; j++) {
            *(float2*)&Pw[gi * SLD + j * 8 + 2 * ti]       = make_float2(s[j][0], s[j][1]);
            *(float2*)&Pw[(gi + 8) * SLD + j * 8 + 2 * ti] = make_float2(s[j][2], s[j][3]);
        }
        __syncwarp();

        // ---- O += P @ V
        #pragma unroll
        for (int kc = 0; kc < 8; kc++) {
            float pa[4];
            pa[0] = Pw[gi * SLD + kc * 8 + ti];
            pa[1] = Pw[(gi + 8) * SLD + kc * 8 + ti];
            pa[2] = Pw[gi * SLD + kc * 8 + ti + 4];
            pa[3] = Pw[(gi + 8) * SLD + kc * 8 + ti + 4];
            #pragma unroll
            for (int j = 0; j < 8; j++) {
                float b0 = Vs[(kc * 8 + ti) * SLD + j * 8 + gi];
                float b1 = Vs[(kc * 8 + ti + 4) * SLD + j * 8 + gi];
                mma_m16n8k8(o[j], pa, b0, b1);
            }
        }
        __syncthreads();
    }

    // ---- Epilogue: normalize, round to tf32 (feeds out-proj GEMM), store
    const float inv0 = 1.0f / l0;
    const float inv1 = 1.0f / l1;
    const size_t row0 = (size_t)(b * SEQ + qb * 64 + r0);
    const size_t row1 = row0 + 8;
    #pragma unroll
    for (int j = 0; j < 8; j++) {
        size_t col = h * DH + j * 8 + 2 * ti;
        *(float2*)&g_att[row0 * EMB + col] =
            make_float2(to_tf32(o[j][0] * inv0), to_tf32(o[j][1] * inv0));
        *(float2*)&g_att[row1 * EMB + col] =
            make_float2(to_tf32(o[j][2] * inv1), to_tf32(o[j][3] * inv1));
    }
}

// ---------------------------------------------------------------------------
// Launch
// ---------------------------------------------------------------------------
extern "C" void kernel_launch(void* const* d_in, const int* in_sizes, int n_in,
                              void* d_out, int out_size) {
    const float* x     = (const float*)d_in[0];   // [4,2048,1024]
    const float* w_qkv = (const float*)d_in[1];   // [1024,3072]
    const float* w_out = (const float*)d_in[2];   // [1024,1024]
    float* out = (float*)d_out;                   // [4,2048,1024]

    float *qkv, *att, *xr, *wq, *wo;
    cudaGetSymbolAddress((void**)&qkv, g_qkv);
    cudaGetSymbolAddress((void**)&att, g_att);
    cudaGetSymbolAddress((void**)&xr,  g_x);
    cudaGetSymbolAddress((void**)&wq,  g_wq);
    cudaGetSymbolAddress((void**)&wo,  g_wo);

    cudaFuncSetAttribute(gemm_mma_kernel<true>,
                         cudaFuncAttributeMaxDynamicSharedMemorySize, GEMM_SMEM_BYTES);
    cudaFuncSetAttribute(gemm_mma_kernel<false>,
                         cudaFuncAttributeMaxDynamicSharedMemorySize, GEMM_SMEM_BYTES);
    cudaFuncSetAttribute(flash_attn2_kernel,
                         cudaFuncAttributeMaxDynamicSharedMemorySize, ATTN_SMEM_BYTES);

    // 0) Pre-round inputs to tf32 (element counts all divisible by 1024)
    round_tf32_kernel<<<(ROWS * EMB) / 1024, 256>>>(x, xr);
    round_tf32_kernel<<<(EMB * QKVN) / 1024, 256>>>(w_qkv, wq);
    round_tf32_kernel<<<(EMB * EMB) / 1024, 256>>>(w_out, wo);

    // 1) QKV projection: [8192,1024] @ [1024,3072] -> g_qkv (tf32-rounded)
    {
        dim3 grid(QKVN / 128, ROWS / 128);
        gemm_mma_kernel<true><<<grid, 256, GEMM_SMEM_BYTES>>>(xr, wq, qkv, QKVN, EMB);
    }
    // 2) Flash attention: g_qkv -> g_att (tf32-rounded)
    {
        dim3 grid(SEQ / 64, BATCH * NH);
        flash_attn2_kernel<<<grid, 128, ATTN_SMEM_BYTES>>>();
    }
    // 3) Output projection: [8192,1024] @ [1024,1024] -> d_out (full fp32)
    {
        dim3 grid(EMB / 128, ROWS / 128);
        gemm_mma_kernel<false><<<grid, 256, GEMM_SMEM_BYTES>>>(att, wo, out, EMB, EMB);
    }
}

// round 7
// speedup vs baseline: 2.6622x; 1.0504x over previous
#include <cuda_runtime.h>
#include <cstdint>

// Problem constants
#define BATCH 4
#define SEQ   2048
#define EMB   1024
#define NH    16
#define DH    64
#define ROWS  (BATCH * SEQ)        // 8192
#define QKVN  (3 * EMB)            // 3072

// Scratch (allocation-guard-safe device globals)
__device__ float g_qkv[(size_t)ROWS * QKVN];   // 96 MB (tf32-rounded)
__device__ float g_att[(size_t)ROWS * EMB];    // 32 MB (tf32-rounded)
__device__ float g_x  [(size_t)ROWS * EMB];    // 32 MB (tf32-rounded x)
__device__ float g_wq [(size_t)EMB * QKVN];    // 12 MB (tf32-rounded w_qkv)
__device__ float g_wo [(size_t)EMB * EMB];     //  4 MB (tf32-rounded w_out)

// ---------------------------------------------------------------------------
// Helpers
// ---------------------------------------------------------------------------
__device__ __forceinline__ float to_tf32(float x) {
    float r;
    asm("cvt.rna.tf32.f32 %0, %1;" : "=f"(r) : "f"(x));
    return r;
}

__device__ __forceinline__ unsigned smem_u32(const void* p) {
    return (unsigned)__cvta_generic_to_shared(p);
}

__device__ __forceinline__ void cp16(unsigned dst, const void* src) {
    asm volatile("cp.async.cg.shared.global [%0], [%1], 16;"
                 :: "r"(dst), "l"(__cvta_generic_to_global(src)));
}
#define CP_COMMIT() asm volatile("cp.async.commit_group;" ::: "memory")
#define CP_WAIT(n)  asm volatile("cp.async.wait_group %0;" :: "n"(n) : "memory")

__device__ __forceinline__ void mma_m16n8k8(float d[4], const float a[4],
                                            float b0, float b1) {
    const unsigned* A = reinterpret_cast<const unsigned*>(a);
    asm volatile(
        "mma.sync.aligned.m16n8k8.row.col.f32.tf32.tf32.f32 "
        "{%0,%1,%2,%3}, {%4,%5,%6,%7}, {%8,%9}, {%0,%1,%2,%3};\n"
        : "+f"(d[0]), "+f"(d[1]), "+f"(d[2]), "+f"(d[3])
        : "r"(A[0]), "r"(A[1]), "r"(A[2]), "r"(A[3]),
          "r"(__float_as_uint(b0)), "r"(__float_as_uint(b1)));
}

// ---------------------------------------------------------------------------
// Pre-round pass: out[i] = tf32(in[i])
// ---------------------------------------------------------------------------
__global__ __launch_bounds__(256)
void round_tf32_kernel(const float* __restrict__ in, float* __restrict__ out) {
    size_t i = ((size_t)blockIdx.x * 256 + threadIdx.x) * 4;
    float4 v = *(const float4*)(in + i);
    v.x = to_tf32(v.x); v.y = to_tf32(v.y);
    v.z = to_tf32(v.z); v.w = to_tf32(v.w);
    *(float4*)(out + i) = v;
}

// ---------------------------------------------------------------------------
// tf32 mma.sync GEMM: C[M,N] = A[M,K] @ B[K,N], inputs pre-rounded to tf32.
// Block tile 128x128, BK=32, 3-stage cp.async pipeline, 256 threads = 8 warps
// (2x4), warp tile 64x32 register-resident. 2 CTAs/SM (reg-capped).
//   A smem: [128][36] floats   18432 B
//   B smem: [32][136] floats   17408 B
// ---------------------------------------------------------------------------
#define G_LDSA 36
#define G_LDSB 136
#define G_ABYTES (128 * G_LDSA * 4)
#define G_STAGE  (G_ABYTES + 32 * G_LDSB * 4)     // 35840
#define G_STAGES 3
#define GEMM_SMEM_BYTES (G_STAGES * G_STAGE)      // 107520

template<bool ROUND>
__global__ __launch_bounds__(256, 2)
void gemm_mma_kernel(const float* __restrict__ A, const float* __restrict__ B,
                     float* __restrict__ C, int N, int K) {
    extern __shared__ char smc[];
    const unsigned abase0 = smem_u32(smc);
    const unsigned bbase0 = abase0 + G_ABYTES;

    const int tid  = threadIdx.x;
    const int lane = tid & 31;
    const int wid  = tid >> 5;
    const int gi   = lane >> 2;
    const int ti   = lane & 3;
    const int warp_m = wid >> 2;    // 0..1
    const int warp_n = wid & 3;     // 0..3
    const int m0 = blockIdx.y * 128;
    const int n0 = blockIdx.x * 128;

    const int ar = tid >> 3, ac4 = tid & 7;          // A: 128 rows x 8 float4
    const int bk = tid >> 5, bc4 = tid & 31;         // B: 32 rows x 32 float4
    auto stage = [&](int t, int buf) {
        const unsigned ab = abase0 + buf * G_STAGE;
        const unsigned bb = bbase0 + buf * G_STAGE;
        const float* Ag = A + (size_t)m0 * K + t * 32;
        const float* Bg = B + (size_t)(t * 32) * N + n0;
        #pragma unroll
        for (int i = 0; i < 4; i++) {
            int r = ar + i * 32;
            cp16(ab + r * (G_LDSA * 4) + ac4 * 16, Ag + (size_t)r * K + ac4 * 4);
        }
        #pragma unroll
        for (int i = 0; i < 4; i++) {
            int k = bk + i * 8;
            cp16(bb + k * (G_LDSB * 4) + bc4 * 16, Bg + (size_t)k * N + bc4 * 4);
        }
    };

    float acc[4][4][4];
    #pragma unroll
    for (int i = 0; i < 4; i++)
        #pragma unroll
        for (int j = 0; j < 4; j++)
            acc[i][j][0] = acc[i][j][1] = acc[i][j][2] = acc[i][j][3] = 0.0f;

    const int KT = K >> 5;
    stage(0, 0); CP_COMMIT();
    stage(1, 1); CP_COMMIT();

    for (int t = 0; t < KT; t++) {
        const int buf = t % G_STAGES;
        const int nt = t + 2;
        if (nt < KT) stage(nt, nt % G_STAGES);
        CP_COMMIT();            // empty group when nt >= KT (keeps wait math uniform)
        CP_WAIT(2);
        __syncthreads();

        const float* As = (const float*)(smc + buf * G_STAGE);
        const float* Bs = (const float*)(smc + buf * G_STAGE + G_ABYTES);
        #pragma unroll
        for (int s = 0; s < 4; s++) {
            float af[4][4];
            float bf[4][2];
            #pragma unroll
            for (int mi = 0; mi < 4; mi++) {
                const int rm = warp_m * 64 + mi * 16;
                af[mi][0] = As[(rm + gi)     * G_LDSA + s * 8 + ti];
                af[mi][1] = As[(rm + gi + 8) * G_LDSA + s * 8 + ti];
                af[mi][2] = As[(rm + gi)     * G_LDSA + s * 8 + ti + 4];
                af[mi][3] = As[(rm + gi + 8) * G_LDSA + s * 8 + ti + 4];
            }
            #pragma unroll
            for (int nj = 0; nj < 4; nj++) {
                const int nn = warp_n * 32 + nj * 8;
                bf[nj][0] = Bs[(s * 8 + ti)     * G_LDSB + nn + gi];
                bf[nj][1] = Bs[(s * 8 + ti + 4) * G_LDSB + nn + gi];
            }
            #pragma unroll
            for (int mi = 0; mi < 4; mi++)
                #pragma unroll
                for (int nj = 0; nj < 4; nj++)
                    mma_m16n8k8(acc[mi][nj], af[mi], bf[nj][0], bf[nj][1]);
        }
        __syncthreads();
    }

    #pragma unroll
    for (int mi = 0; mi < 4; mi++) {
        const int row = m0 + warp_m * 64 + mi * 16 + gi;
        #pragma unroll
        for (int nj = 0; nj < 4; nj++) {
            const int col = n0 + warp_n * 32 + nj * 8 + 2 * ti;
            float2 v0 = make_float2(acc[mi][nj][0], acc[mi][nj][1]);
            float2 v1 = make_float2(acc[mi][nj][2], acc[mi][nj][3]);
            if (ROUND) {
                v0.x = to_tf32(v0.x); v0.y = to_tf32(v0.y);
                v1.x = to_tf32(v1.x); v1.y = to_tf32(v1.y);
            }
            *(float2*)&C[(size_t)row * N + col]       = v0;
            *(float2*)&C[(size_t)(row + 8) * N + col] = v1;
        }
    }
}

// ---------------------------------------------------------------------------
// Flash attention: raw m16n8k8 tf32 mma, register-resident S and O.
// 128 threads = 4 warps, Br=64, Bc=64. Double-buffered K/V with one-tile
// cp.async prefetch. Q staged through the P region so tile-0 prefetch
// overlaps the prologue.
//   smem: K0,K1,V0,V1 (64x72 each) + P (64x72) = 92160 B -> 2 CTAs/SM
// ---------------------------------------------------------------------------
#define SLD 72
#define KV_TILE (64 * SLD)
#define P_OFF   (4 * KV_TILE)
#define ATTN_SMEM_BYTES ((4 * KV_TILE + 64 * SLD) * 4)   // 92160 B

__global__ __launch_bounds__(128)
void flash_attn2_kernel() {
    extern __shared__ float sm[];

    const int tid  = threadIdx.x;
    const int lane = tid & 31;
    const int wid  = tid >> 5;
    const int gi   = lane >> 2;
    const int ti   = lane & 3;
    const int bh = blockIdx.y;
    const int b = bh >> 4, h = bh & 15;
    const int qb = blockIdx.x;

    const float* qbase = g_qkv + (size_t)(b * SEQ + qb * 64) * QKVN + h * DH;
    const float* kbase = g_qkv + (size_t)(b * SEQ) * QKVN + EMB + h * DH;
    const float* vbase = g_qkv + (size_t)(b * SEQ) * QKVN + 2 * EMB + h * DH;
    const unsigned smb = smem_u32(sm);

    // Stage K/V tile jt into buffer buf (pure 16B async copies; tf32 data)
    auto stage_kv = [&](int jt, int buf) {
        const unsigned kb = smb + buf * (KV_TILE * 4);
        const unsigned vb = smb + (2 + buf) * (KV_TILE * 4);
        #pragma unroll
        for (int i = 0; i < 8; i++) {
            int idx = tid + i * 128;
            int r = idx >> 4, c = idx & 15;
            size_t g = (size_t)(jt * 64 + r) * QKVN + c * 4;
            unsigned so = r * (SLD * 4) + c * 16;
            cp16(kb + so, kbase + g);
            cp16(vb + so, vbase + g);
        }
    };

    // Prefetch tile 0 while we stage Q (into the P region, no conflict)
    stage_kv(0, 0);
    CP_COMMIT();

    float* Pq = sm + P_OFF;
    #pragma unroll
    for (int i = tid; i < 64 * 16; i += 128) {
        int r = i >> 4, c = (i & 15) * 4;
        float4 v = *(const float4*)&qbase[(size_t)r * QKVN + c];
        v.x *= 0.125f; v.y *= 0.125f; v.z *= 0.125f; v.w *= 0.125f;
        *(float4*)&Pq[r * SLD + c] = v;
    }
    __syncthreads();

    const int r0 = wid * 16 + gi;
    const int r1 = r0 + 8;

    float qa[8][4];
    #pragma unroll
    for (int kc = 0; kc < 8; kc++) {
        qa[kc][0] = Pq[r0 * SLD + kc * 8 + ti];
        qa[kc][1] = Pq[r1 * SLD + kc * 8 + ti];
        qa[kc][2] = Pq[r0 * SLD + kc * 8 + ti + 4];
        qa[kc][3] = Pq[r1 * SLD + kc * 8 + ti + 4];
    }

    float o[8][4];
    #pragma unroll
    for (int j = 0; j < 8; j++)
        o[j][0] = o[j][1] = o[j][2] = o[j][3] = 0.0f;
    float m0 = -1e30f, m1 = -1e30f, l0 = 0.0f, l1 = 0.0f;

    float* Pw = sm + P_OFF + wid * 16 * SLD;   // warp-private P tile

    for (int jt = 0; jt < SEQ / 64; jt++) {
        const int buf = jt & 1;
        if (jt + 1 < SEQ / 64) stage_kv(jt + 1, buf ^ 1);
        CP_COMMIT();            // empty group at the tail
        CP_WAIT(1);
        __syncthreads();        // tile jt visible; also fences P/Q reuse

        const float* Ks = sm + buf * KV_TILE;
        const float* Vs = sm + (2 + buf) * KV_TILE;

        // ---- S = Q @ K^T
        float s[8][4];
        #pragma unroll
        for (int j = 0; j < 8; j++)
            s[j][0] = s[j][1] = s[j][2] = s[j][3] = 0.0f;
        #pragma unroll
        for (int kc = 0; kc < 8; kc++) {
            #pragma unroll
            for (int j = 0; j < 8; j++) {
                float b0 = Ks[(j * 8 + gi) * SLD + kc * 8 + ti];
                float b1 = Ks[(j * 8 + gi) * SLD + kc * 8 + ti + 4];
                mma_m16n8k8(s[j], qa[kc], b0, b1);
            }
        }

        // ---- Online softmax
        float a0 = -1e30f, a1 = -1e30f;
        #pragma unroll
        for (int j = 0; j < 8; j++) {
            a0 = fmaxf(a0, fmaxf(s[j][0], s[j][1]));
            a1 = fmaxf(a1, fmaxf(s[j][2], s[j][3]));
        }
        a0 = fmaxf(a0, __shfl_xor_sync(0xffffffffu, a0, 1));
        a0 = fmaxf(a0, __shfl_xor_sync(0xffffffffu, a0, 2));
        a1 = fmaxf(a1, __shfl_xor_sync(0xffffffffu, a1, 1));
        a1 = fmaxf(a1, __shfl_xor_sync(0xffffffffu, a1, 2));

        float mn0 = fmaxf(m0, a0), mn1 = fmaxf(m1, a1);
        float c0 = __expf(m0 - mn0), c1 = __expf(m1 - mn1);
        float sum0 = 0.0f, sum1 = 0.0f;
        #pragma unroll
        for (int j = 0; j < 8; j++) {
            float p00 = __expf(s[j][0] - mn0);
            float p01 = __expf(s[j][1] - mn0);
            float p10 = __expf(s[j][2] - mn1);
            float p11 = __expf(s[j][3] - mn1);
            sum0 += p00 + p01;
            sum1 += p10 + p11;
            s[j][0] = to_tf32(p00);
            s[j][1] = to_tf32(p01);
            s[j][2] = to_tf32(p10);
            s[j][3] = to_tf32(p11);
        }
        sum0 += __shfl_xor_sync(0xffffffffu, sum0, 1);
        sum0 += __shfl_xor_sync(0xffffffffu, sum0, 2);
        sum1 += __shfl_xor_sync(0xffffffffu, sum1, 1);
        sum1 += __shfl_xor_sync(0xffffffffu, sum1, 2);

        m0 = mn0; m1 = mn1;
        l0 = l0 * c0 + sum0;
        l1 = l1 * c1 + sum1;

        #pragma unroll
        for (int j = 0; j < 8; j++) {
            o[j][0] *= c0; o[j][1] *= c0;
            o[j][2] *= c1; o[j][3] *= c1;
        }

        // ---- P: C-layout regs -> warp-private smem -> A-layout regs
        #pragma unroll
        for (int j = 0; j < 8; j++) {
            *(float2*)&Pw[gi * SLD + j * 8 + 2 * ti]       = make_float2(s[j][0], s[j][1]);
            *(float2*)&Pw[(gi + 8) * SLD + j * 8 + 2 * ti] = make_float2(s[j][2], s[j][3]);
        }
        __syncwarp();

        // ---- O += P @ V
        #pragma unroll
        for (int kc = 0; kc < 8; kc++) {
            float pa[4];
            pa[0] = Pw[gi * SLD + kc * 8 + ti];
            pa[1] = Pw[(gi + 8) * SLD + kc * 8 + ti];
            pa[2] = Pw[gi * SLD + kc * 8 + ti + 4];
            pa[3] = Pw[(gi + 8) * SLD + kc * 8 + ti + 4];
            #pragma unroll
            for (int j = 0; j < 8; j++) {
                float b0 = Vs[(kc * 8 + ti) * SLD + j * 8 + gi];
                float b1 = Vs[(kc * 8 + ti + 4) * SLD + j * 8 + gi];
                mma_m16n8k8(o[j], pa, b0, b1);
            }
        }
        __syncthreads();   // all reads of buf done before its next overwrite
    }

    // ---- Epilogue: normalize, round to tf32 (feeds out-proj GEMM), store
    const float inv0 = 1.0f / l0;
    const float inv1 = 1.0f / l1;
    const size_t row0 = (size_t)(b * SEQ + qb * 64 + r0);
    const size_t row1 = row0 + 8;
    #pragma unroll
    for (int j = 0; j < 8; j++) {
        size_t col = h * DH + j * 8 + 2 * ti;
        *(float2*)&g_att[row0 * EMB + col] =
            make_float2(to_tf32(o[j][0] * inv0), to_tf32(o[j][1] * inv0));
        *(float2*)&g_att[row1 * EMB + col] =
            make_float2(to_tf32(o[j][2] * inv1), to_tf32(o[j][3] * inv1));
    }
}

// ---------------------------------------------------------------------------
// Launch
// ---------------------------------------------------------------------------
extern "C" void kernel_launch(void* const* d_in, const int* in_sizes, int n_in,
                              void* d_out, int out_size) {
    const float* x     = (const float*)d_in[0];   // [4,2048,1024]
    const float* w_qkv = (const float*)d_in[1];   // [1024,3072]
    const float* w_out = (const float*)d_in[2];   // [1024,1024]
    float* out = (float*)d_out;                   // [4,2048,1024]

    float *qkv, *att, *xr, *wq, *wo;
    cudaGetSymbolAddress((void**)&qkv, g_qkv);
    cudaGetSymbolAddress((void**)&att, g_att);
    cudaGetSymbolAddress((void**)&xr,  g_x);
    cudaGetSymbolAddress((void**)&wq,  g_wq);
    cudaGetSymbolAddress((void**)&wo,  g_wo);

    cudaFuncSetAttribute(gemm_mma_kernel<true>,
                         cudaFuncAttributeMaxDynamicSharedMemorySize, GEMM_SMEM_BYTES);
    cudaFuncSetAttribute(gemm_mma_kernel<false>,
                         cudaFuncAttributeMaxDynamicSharedMemorySize, GEMM_SMEM_BYTES);
    cudaFuncSetAttribute(flash_attn2_kernel,
                         cudaFuncAttributeMaxDynamicSharedMemorySize, ATTN_SMEM_BYTES);

    // 0) Pre-round inputs to tf32
    round_tf32_kernel<<<(ROWS * EMB) / 1024, 256>>>(x, xr);
    round_tf32_kernel<<<(EMB * QKVN) / 1024, 256>>>(w_qkv, wq);
    round_tf32_kernel<<<(EMB * EMB) / 1024, 256>>>(w_out, wo);

    // 1) QKV projection: [8192,1024] @ [1024,3072] -> g_qkv (tf32-rounded)
    {
        dim3 grid(QKVN / 128, ROWS / 128);
        gemm_mma_kernel<true><<<grid, 256, GEMM_SMEM_BYTES>>>(xr, wq, qkv, QKVN, EMB);
    }
    // 2) Flash attention: g_qkv -> g_att (tf32-rounded)
    {
        dim3 grid(SEQ / 64, BATCH * NH);
        flash_attn2_kernel<<<grid, 128, ATTN_SMEM_BYTES>>>();
    }
    // 3) Output projection: [8192,1024] @ [1024,1024] -> d_out (full fp32)
    {
        dim3 grid(EMB / 128, ROWS / 128);
        gemm_mma_kernel<false><<<grid, 256, GEMM_SMEM_BYTES>>>(att, wo, out, EMB, EMB);
    }
}

// round 8
// speedup vs baseline: 2.8506x; 1.0708x over previous
#include <cuda_runtime.h>
#include <cstdint>

// Problem constants
#define BATCH 4
#define SEQ   2048
#define EMB   1024
#define NH    16
#define DH    64
#define ROWS  (BATCH * SEQ)        // 8192
#define QKVN  (3 * EMB)            // 3072

// Scratch (allocation-guard-safe device globals)
__device__ float g_qkv[(size_t)ROWS * QKVN];   // 96 MB (tf32-rounded)
__device__ float g_att[(size_t)ROWS * EMB];    // 32 MB (tf32-rounded)
__device__ float g_x  [(size_t)ROWS * EMB];    // 32 MB (tf32-rounded x)
__device__ float g_wq [(size_t)EMB * QKVN];    // 12 MB (tf32-rounded w_qkv)
__device__ float g_wo [(size_t)EMB * EMB];     //  4 MB (tf32-rounded w_out)

// ---------------------------------------------------------------------------
// Helpers
// ---------------------------------------------------------------------------
__device__ __forceinline__ float to_tf32(float x) {
    float r;
    asm("cvt.rna.tf32.f32 %0, %1;" : "=f"(r) : "f"(x));
    return r;
}

__device__ __forceinline__ unsigned smem_u32(const void* p) {
    return (unsigned)__cvta_generic_to_shared(p);
}

__device__ __forceinline__ void cp16(unsigned dst, const void* src) {
    asm volatile("cp.async.cg.shared.global [%0], [%1], 16;"
                 :: "r"(dst), "l"(__cvta_generic_to_global(src)));
}
#define CP_COMMIT() asm volatile("cp.async.commit_group;" ::: "memory")
#define CP_WAIT(n)  asm volatile("cp.async.wait_group %0;" :: "n"(n) : "memory")

__device__ __forceinline__ void mma_m16n8k8(float d[4], const float a[4],
                                            float b0, float b1) {
    const unsigned* A = reinterpret_cast<const unsigned*>(a);
    asm volatile(
        "mma.sync.aligned.m16n8k8.row.col.f32.tf32.tf32.f32 "
        "{%0,%1,%2,%3}, {%4,%5,%6,%7}, {%8,%9}, {%0,%1,%2,%3};\n"
        : "+f"(d[0]), "+f"(d[1]), "+f"(d[2]), "+f"(d[3])
        : "r"(A[0]), "r"(A[1]), "r"(A[2]), "r"(A[3]),
          "r"(__float_as_uint(b0)), "r"(__float_as_uint(b1)));
}

// ---------------------------------------------------------------------------
// Pre-round pass: out[i] = tf32(in[i])
// ---------------------------------------------------------------------------
__global__ __launch_bounds__(256)
void round_tf32_kernel(const float* __restrict__ in, float* __restrict__ out) {
    size_t i = ((size_t)blockIdx.x * 256 + threadIdx.x) * 4;
    float4 v = *(const float4*)(in + i);
    v.x = to_tf32(v.x); v.y = to_tf32(v.y);
    v.z = to_tf32(v.z); v.w = to_tf32(v.w);
    *(float4*)(out + i) = v;
}

// ---------------------------------------------------------------------------
// tf32 mma.sync GEMM: C[M,N] = A[M,K] @ B[K,N], inputs pre-rounded to tf32.
// Block tile 128x128, BK=32, 3-stage cp.async pipeline, single barrier per
// k-tile. 256 threads = 8 warps (2x4), warp tile 64x32. 2 CTAs/SM.
// ---------------------------------------------------------------------------
#define G_LDSA 36
#define G_LDSB 136
#define G_ABYTES (128 * G_LDSA * 4)
#define G_STAGE  (G_ABYTES + 32 * G_LDSB * 4)     // 35840
#define G_STAGES 3
#define GEMM_SMEM_BYTES (G_STAGES * G_STAGE)      // 107520

template<bool ROUND>
__global__ __launch_bounds__(256, 2)
void gemm_mma_kernel(const float* __restrict__ A, const float* __restrict__ B,
                     float* __restrict__ C, int N, int K) {
    extern __shared__ char smc[];
    const unsigned abase0 = smem_u32(smc);
    const unsigned bbase0 = abase0 + G_ABYTES;

    const int tid  = threadIdx.x;
    const int lane = tid & 31;
    const int wid  = tid >> 5;
    const int gi   = lane >> 2;
    const int ti   = lane & 3;
    const int warp_m = wid >> 2;    // 0..1
    const int warp_n = wid & 3;     // 0..3
    const int m0 = blockIdx.y * 128;
    const int n0 = blockIdx.x * 128;

    const int ar = tid >> 3, ac4 = tid & 7;          // A: 128 rows x 8 float4
    const int bk = tid >> 5, bc4 = tid & 31;         // B: 32 rows x 32 float4
    auto stage = [&](int t, int buf) {
        const unsigned ab = abase0 + buf * G_STAGE;
        const unsigned bb = bbase0 + buf * G_STAGE;
        const float* Ag = A + (size_t)m0 * K + t * 32;
        const float* Bg = B + (size_t)(t * 32) * N + n0;
        #pragma unroll
        for (int i = 0; i < 4; i++) {
            int r = ar + i * 32;
            cp16(ab + r * (G_LDSA * 4) + ac4 * 16, Ag + (size_t)r * K + ac4 * 4);
        }
        #pragma unroll
        for (int i = 0; i < 4; i++) {
            int k = bk + i * 8;
            cp16(bb + k * (G_LDSB * 4) + bc4 * 16, Bg + (size_t)k * N + bc4 * 4);
        }
    };

    float acc[4][4][4];
    #pragma unroll
    for (int i = 0; i < 4; i++)
        #pragma unroll
        for (int j = 0; j < 4; j++)
            acc[i][j][0] = acc[i][j][1] = acc[i][j][2] = acc[i][j][3] = 0.0f;

    const int KT = K >> 5;
    stage(0, 0); CP_COMMIT();
    stage(1, 1); CP_COMMIT();

    for (int t = 0; t < KT; t++) {
        const int buf = t % G_STAGES;
        // Pending groups here: {t, t+1} (or just {t} on the last iteration).
        if (t + 1 < KT) { CP_WAIT(1); } else { CP_WAIT(0); }
        __syncthreads();     // all threads done reading buf (t+2)%3's old data
        if (t + 2 < KT) { stage(t + 2, (t + 2) % G_STAGES); CP_COMMIT(); }

        const float* As = (const float*)(smc + buf * G_STAGE);
        const float* Bs = (const float*)(smc + buf * G_STAGE + G_ABYTES);
        #pragma unroll
        for (int s = 0; s < 4; s++) {
            float af[4][4];
            float bf[4][2];
            #pragma unroll
            for (int mi = 0; mi < 4; mi++) {
                const int rm = warp_m * 64 + mi * 16;
                af[mi][0] = As[(rm + gi)     * G_LDSA + s * 8 + ti];
                af[mi][1] = As[(rm + gi + 8) * G_LDSA + s * 8 + ti];
                af[mi][2] = As[(rm + gi)     * G_LDSA + s * 8 + ti + 4];
                af[mi][3] = As[(rm + gi + 8) * G_LDSA + s * 8 + ti + 4];
            }
            #pragma unroll
            for (int nj = 0; nj < 4; nj++) {
                const int nn = warp_n * 32 + nj * 8;
                bf[nj][0] = Bs[(s * 8 + ti)     * G_LDSB + nn + gi];
                bf[nj][1] = Bs[(s * 8 + ti + 4) * G_LDSB + nn + gi];
            }
            #pragma unroll
            for (int mi = 0; mi < 4; mi++)
                #pragma unroll
                for (int nj = 0; nj < 4; nj++)
                    mma_m16n8k8(acc[mi][nj], af[mi], bf[nj][0], bf[nj][1]);
        }
    }

    #pragma unroll
    for (int mi = 0; mi < 4; mi++) {
        const int row = m0 + warp_m * 64 + mi * 16 + gi;
        #pragma unroll
        for (int nj = 0; nj < 4; nj++) {
            const int col = n0 + warp_n * 32 + nj * 8 + 2 * ti;
            float2 v0 = make_float2(acc[mi][nj][0], acc[mi][nj][1]);
            float2 v1 = make_float2(acc[mi][nj][2], acc[mi][nj][3]);
            if (ROUND) {
                v0.x = to_tf32(v0.x); v0.y = to_tf32(v0.y);
                v1.x = to_tf32(v1.x); v1.y = to_tf32(v1.y);
            }
            *(float2*)&C[(size_t)row * N + col]       = v0;
            *(float2*)&C[(size_t)(row + 8) * N + col] = v1;
        }
    }
}

// ---------------------------------------------------------------------------
// Flash attention: Br=128, Bc=64. 256 threads = 8 warps, each warp owns a
// 16-row query slice. Register-resident S and O, double-buffered K/V with
// one-tile cp.async prefetch, single barrier per KV tile.
//   smem: K0,K1,V0,V1 (64x72 each) + P (128x72) = 110592 B -> 2 CTAs/SM
// ---------------------------------------------------------------------------
#define SLD 72
#define KV_TILE (64 * SLD)
#define P_OFF   (4 * KV_TILE)
#define ATTN_SMEM_BYTES ((4 * KV_TILE + 128 * SLD) * 4)   // 110592 B

__global__ __launch_bounds__(256, 2)
void flash_attn2_kernel() {
    extern __shared__ float sm[];

    const int tid  = threadIdx.x;
    const int lane = tid & 31;
    const int wid  = tid >> 5;          // 0..7
    const int gi   = lane >> 2;
    const int ti   = lane & 3;
    const int bh = blockIdx.y;
    const int b = bh >> 4, h = bh & 15;
    const int qb = blockIdx.x;          // 128-row query tile

    const float* qbase = g_qkv + (size_t)(b * SEQ + qb * 128) * QKVN + h * DH;
    const float* kbase = g_qkv + (size_t)(b * SEQ) * QKVN + EMB + h * DH;
    const float* vbase = g_qkv + (size_t)(b * SEQ) * QKVN + 2 * EMB + h * DH;
    const unsigned smb = smem_u32(sm);

    // Stage K/V tile jt into buffer buf (pure 16B async copies; tf32 data)
    auto stage_kv = [&](int jt, int buf) {
        const unsigned kb = smb + buf * (KV_TILE * 4);
        const unsigned vb = smb + (2 + buf) * (KV_TILE * 4);
        #pragma unroll
        for (int i = 0; i < 4; i++) {
            int idx = tid + i * 256;
            int r = idx >> 4, c = idx & 15;
            size_t g = (size_t)(jt * 64 + r) * QKVN + c * 4;
            unsigned so = r * (SLD * 4) + c * 16;
            cp16(kb + so, kbase + g);
            cp16(vb + so, vbase + g);
        }
    };

    // Prefetch tile 0 while we stage Q (through the P region)
    stage_kv(0, 0);
    CP_COMMIT();

    float* Pq = sm + P_OFF;
    #pragma unroll
    for (int i = tid; i < 128 * 16; i += 256) {
        int r = i >> 4, c = (i & 15) * 4;
        float4 v = *(const float4*)&qbase[(size_t)r * QKVN + c];
        v.x *= 0.125f; v.y *= 0.125f; v.z *= 0.125f; v.w *= 0.125f;
        *(float4*)&Pq[r * SLD + c] = v;
    }
    __syncthreads();

    const int r0 = wid * 16 + gi;       // warp-local query rows (0..127)
    const int r1 = r0 + 8;

    float qa[8][4];
    #pragma unroll
    for (int kc = 0; kc < 8; kc++) {
        qa[kc][0] = Pq[r0 * SLD + kc * 8 + ti];
        qa[kc][1] = Pq[r1 * SLD + kc * 8 + ti];
        qa[kc][2] = Pq[r0 * SLD + kc * 8 + ti + 4];
        qa[kc][3] = Pq[r1 * SLD + kc * 8 + ti + 4];
    }

    float o[8][4];
    #pragma unroll
    for (int j = 0; j < 8; j++)
        o[j][0] = o[j][1] = o[j][2] = o[j][3] = 0.0f;
    float m0 = -1e30f, m1 = -1e30f, l0 = 0.0f, l1 = 0.0f;

    float* Pw = sm + P_OFF + wid * 16 * SLD;   // warp-private P tile

    const int NT = SEQ / 64;
    for (int jt = 0; jt < NT; jt++) {
        const int buf = jt & 1;
        CP_WAIT(0);             // only tile jt's group is in flight here
        __syncthreads();        // everyone done reading buf^1's old data + Pq/Pw
        if (jt + 1 < NT) { stage_kv(jt + 1, buf ^ 1); CP_COMMIT(); }

        const float* Ks = sm + buf * KV_TILE;
        const float* Vs = sm + (2 + buf) * KV_TILE;

        // ---- S = Q @ K^T
        float s[8][4];
        #pragma unroll
        for (int j = 0; j < 8; j++)
            s[j][0] = s[j][1] = s[j][2] = s[j][3] = 0.0f;
        #pragma unroll
        for (int kc = 0; kc < 8; kc++) {
            #pragma unroll
            for (int j = 0; j < 8; j++) {
                float b0 = Ks[(j * 8 + gi) * SLD + kc * 8 + ti];
                float b1 = Ks[(j * 8 + gi) * SLD + kc * 8 + ti + 4];
                mma_m16n8k8(s[j], qa[kc], b0, b1);
            }
        }

        // ---- Online softmax
        float a0 = -1e30f, a1 = -1e30f;
        #pragma unroll
        for (int j = 0; j < 8; j++) {
            a0 = fmaxf(a0, fmaxf(s[j][0], s[j][1]));
            a1 = fmaxf(a1, fmaxf(s[j][2], s[j][3]));
        }
        a0 = fmaxf(a0, __shfl_xor_sync(0xffffffffu, a0, 1));
        a0 = fmaxf(a0, __shfl_xor_sync(0xffffffffu, a0, 2));
        a1 = fmaxf(a1, __shfl_xor_sync(0xffffffffu, a1, 1));
        a1 = fmaxf(a1, __shfl_xor_sync(0xffffffffu, a1, 2));

        float mn0 = fmaxf(m0, a0), mn1 = fmaxf(m1, a1);
        float c0 = __expf(m0 - mn0), c1 = __expf(m1 - mn1);
        float sum0 = 0.0f, sum1 = 0.0f;
        #pragma unroll
        for (int j = 0; j < 8; j++) {
            float p00 = __expf(s[j][0] - mn0);
            float p01 = __expf(s[j][1] - mn0);
            float p10 = __expf(s[j][2] - mn1);
            float p11 = __expf(s[j][3] - mn1);
            sum0 += p00 + p01;
            sum1 += p10 + p11;
            s[j][0] = to_tf32(p00);
            s[j][1] = to_tf32(p01);
            s[j][2] = to_tf32(p10);
            s[j][3] = to_tf32(p11);
        }
        sum0 += __shfl_xor_sync(0xffffffffu, sum0, 1);
        sum0 += __shfl_xor_sync(0xffffffffu, sum0, 2);
        sum1 += __shfl_xor_sync(0xffffffffu, sum1, 1);
        sum1 += __shfl_xor_sync(0xffffffffu, sum1, 2);

        m0 = mn0; m1 = mn1;
        l0 = l0 * c0 + sum0;
        l1 = l1 * c1 + sum1;

        #pragma unroll
        for (int j = 0; j < 8; j++) {
            o[j][0] *= c0; o[j][1] *= c0;
            o[j][2] *= c1; o[j][3] *= c1;
        }

        // ---- P: C-layout regs -> warp-private smem -> A-layout regs
        #pragma unroll
        for (int j = 0; j < 8; j++) {
            *(float2*)&Pw[gi * SLD + j * 8 + 2 * ti]       = make_float2(s[j][0], s[j][1]);
            *(float2*)&Pw[(gi + 8) * SLD + j * 8 + 2 * ti] = make_float2(s[j][2], s[j][3]);
        }
        __syncwarp();

        // ---- O += P @ V
        #pragma unroll
        for (int kc = 0; kc < 8; kc++) {
            float pa[4];
            pa[0] = Pw[gi * SLD + kc * 8 + ti];
            pa[1] = Pw[(gi + 8) * SLD + kc * 8 + ti];
            pa[2] = Pw[gi * SLD + kc * 8 + ti + 4];
            pa[3] = Pw[(gi + 8) * SLD + kc * 8 + ti + 4];
            #pragma unroll
            for (int j = 0; j < 8; j++) {
                float b0 = Vs[(kc * 8 + ti) * SLD + j * 8 + gi];
                float b1 = Vs[(kc * 8 + ti + 4) * SLD + j * 8 + gi];
                mma_m16n8k8(o[j], pa, b0, b1);
            }
        }
    }

    // ---- Epilogue: normalize, round to tf32 (feeds out-proj GEMM), store
    const float inv0 = 1.0f / l0;
    const float inv1 = 1.0f / l1;
    const size_t row0 = (size_t)(b * SEQ + qb * 128 + r0);
    const size_t row1 = row0 + 8;
    #pragma unroll
    for (int j = 0; j < 8; j++) {
        size_t col = h * DH + j * 8 + 2 * ti;
        *(float2*)&g_att[row0 * EMB + col] =
            make_float2(to_tf32(o[j][0] * inv0), to_tf32(o[j][1] * inv0));
        *(float2*)&g_att[row1 * EMB + col] =
            make_float2(to_tf32(o[j][2] * inv1), to_tf32(o[j][3] * inv1));
    }
}

// ---------------------------------------------------------------------------
// Launch
// ---------------------------------------------------------------------------
extern "C" void kernel_launch(void* const* d_in, const int* in_sizes, int n_in,
                              void* d_out, int out_size) {
    const float* x     = (const float*)d_in[0];   // [4,2048,1024]
    const float* w_qkv = (const float*)d_in[1];   // [1024,3072]
    const float* w_out = (const float*)d_in[2];   // [1024,1024]
    float* out = (float*)d_out;                   // [4,2048,1024]

    float *qkv, *att, *xr, *wq, *wo;
    cudaGetSymbolAddress((void**)&qkv, g_qkv);
    cudaGetSymbolAddress((void**)&att, g_att);
    cudaGetSymbolAddress((void**)&xr,  g_x);
    cudaGetSymbolAddress((void**)&wq,  g_wq);
    cudaGetSymbolAddress((void**)&wo,  g_wo);

    cudaFuncSetAttribute(gemm_mma_kernel<true>,
                         cudaFuncAttributeMaxDynamicSharedMemorySize, GEMM_SMEM_BYTES);
    cudaFuncSetAttribute(gemm_mma_kernel<false>,
                         cudaFuncAttributeMaxDynamicSharedMemorySize, GEMM_SMEM_BYTES);
    cudaFuncSetAttribute(flash_attn2_kernel,
                         cudaFuncAttributeMaxDynamicSharedMemorySize, ATTN_SMEM_BYTES);

    // 0) Pre-round inputs to tf32
    round_tf32_kernel<<<(ROWS * EMB) / 1024, 256>>>(x, xr);
    round_tf32_kernel<<<(EMB * QKVN) / 1024, 256>>>(w_qkv, wq);
    round_tf32_kernel<<<(EMB * EMB) / 1024, 256>>>(w_out, wo);

    // 1) QKV projection: [8192,1024] @ [1024,3072] -> g_qkv (tf32-rounded)
    {
        dim3 grid(QKVN / 128, ROWS / 128);
        gemm_mma_kernel<true><<<grid, 256, GEMM_SMEM_BYTES>>>(xr, wq, qkv, QKVN, EMB);
    }
    // 2) Flash attention: g_qkv -> g_att (tf32-rounded)
    {
        dim3 grid(SEQ / 128, BATCH * NH);
        flash_attn2_kernel<<<grid, 256, ATTN_SMEM_BYTES>>>();
    }
    // 3) Output projection: [8192,1024] @ [1024,1024] -> d_out (full fp32)
    {
        dim3 grid(EMB / 128, ROWS / 128);
        gemm_mma_kernel<false><<<grid, 256, GEMM_SMEM_BYTES>>>(att, wo, out, EMB, EMB);
    }
}

// round 10
// speedup vs baseline: 3.3075x; 1.1603x over previous
#include <cuda_runtime.h>
#include <cstdint>

// Problem constants
#define BATCH 4
#define SEQ   2048
#define EMB   1024
#define NH    16
#define DH    64
#define ROWS  (BATCH * SEQ)        // 8192
#define QKVN  (3 * EMB)            // 3072

// Scratch (allocation-guard-safe device globals)
__device__ float g_qkv[(size_t)ROWS * QKVN];   // 96 MB (tf32-rounded)
__device__ float g_att[(size_t)ROWS * EMB];    // 32 MB (tf32-rounded)
__device__ float g_x  [(size_t)ROWS * EMB];    // 32 MB (tf32-rounded x)
__device__ float g_wq [(size_t)EMB * QKVN];    // 12 MB (tf32-rounded w_qkv)
__device__ float g_wo [(size_t)EMB * EMB];     //  4 MB (tf32-rounded w_out)

// ---------------------------------------------------------------------------
// Helpers
// ---------------------------------------------------------------------------
__device__ __forceinline__ float to_tf32(float x) {
    float r;
    asm("cvt.rna.tf32.f32 %0, %1;" : "=f"(r) : "f"(x));
    return r;
}

__device__ __forceinline__ float ex2(float x) {
    float r;
    asm("ex2.approx.f32 %0, %1;" : "=f"(r) : "f"(x));
    return r;
}

__device__ __forceinline__ unsigned smem_u32(const void* p) {
    return (unsigned)__cvta_generic_to_shared(p);
}

__device__ __forceinline__ void cp16(unsigned dst, const void* src) {
    asm volatile("cp.async.cg.shared.global [%0], [%1], 16;"
                 :: "r"(dst), "l"(__cvta_generic_to_global(src)));
}
#define CP_COMMIT() asm volatile("cp.async.commit_group;" ::: "memory")
#define CP_WAIT(n)  asm volatile("cp.async.wait_group %0;" :: "n"(n) : "memory")

__device__ __forceinline__ void mma_m16n8k8(float d[4], const float a[4],
                                            float b0, float b1) {
    const unsigned* A = reinterpret_cast<const unsigned*>(a);
    asm volatile(
        "mma.sync.aligned.m16n8k8.row.col.f32.tf32.tf32.f32 "
        "{%0,%1,%2,%3}, {%4,%5,%6,%7}, {%8,%9}, {%0,%1,%2,%3};\n"
        : "+f"(d[0]), "+f"(d[1]), "+f"(d[2]), "+f"(d[3])
        : "r"(A[0]), "r"(A[1]), "r"(A[2]), "r"(A[3]),
          "r"(__float_as_uint(b0)), "r"(__float_as_uint(b1)));
}

// ---------------------------------------------------------------------------
// Pre-round pass: out[i] = tf32(in[i])
// ---------------------------------------------------------------------------
__global__ __launch_bounds__(256)
void round_tf32_kernel(const float* __restrict__ in, float* __restrict__ out) {
    size_t i = ((size_t)blockIdx.x * 256 + threadIdx.x) * 4;
    float4 v = *(const float4*)(in + i);
    v.x = to_tf32(v.x); v.y = to_tf32(v.y);
    v.z = to_tf32(v.z); v.w = to_tf32(v.w);
    *(float4*)(out + i) = v;
}

// ---------------------------------------------------------------------------
// tf32 mma.sync GEMM: C[M,N] = A[M,K] @ B[K,N], inputs pre-rounded to tf32.
// Block tile 128x128, BK=32, 3-stage cp.async pipeline. 128 threads = 4 warps
// (2x2), warp tile 64x64 register-resident (128 LDS / 128 MMA per k-tile:
// balanced LSU vs tensor). 2 CTAs/SM.
// ---------------------------------------------------------------------------
#define G_LDSA 36
#define G_LDSB 136
#define G_ABYTES (128 * G_LDSA * 4)
#define G_STAGE  (G_ABYTES + 32 * G_LDSB * 4)     // 35840
#define G_STAGES 3
#define GEMM_SMEM_BYTES (G_STAGES * G_STAGE)      // 107520

template<bool ROUND>
__global__ __launch_bounds__(128, 2)
void gemm_mma_kernel(const float* __restrict__ A, const float* __restrict__ B,
                     float* __restrict__ C, int N, int K) {
    extern __shared__ char smc[];
    const unsigned abase0 = smem_u32(smc);
    const unsigned bbase0 = abase0 + G_ABYTES;

    const int tid  = threadIdx.x;
    const int lane = tid & 31;
    const int wid  = tid >> 5;
    const int gi   = lane >> 2;
    const int ti   = lane & 3;
    const int warp_m = wid >> 1;    // 0..1
    const int warp_n = wid & 1;     // 0..1
    const int m0 = blockIdx.y * 128;
    const int n0 = blockIdx.x * 128;

    auto stage = [&](int t, int buf) {
        const unsigned ab = abase0 + buf * G_STAGE;
        const unsigned bb = bbase0 + buf * G_STAGE;
        const float* Ag = A + (size_t)m0 * K + t * 32;
        const float* Bg = B + (size_t)(t * 32) * N + n0;
        #pragma unroll
        for (int i = 0; i < 8; i++) {           // A: 128 rows x 8 float4
            int idx = tid + i * 128;
            int r = idx >> 3, c4 = idx & 7;
            cp16(ab + r * (G_LDSA * 4) + c4 * 16, Ag + (size_t)r * K + c4 * 4);
        }
        #pragma unroll
        for (int i = 0; i < 8; i++) {           // B: 32 rows x 32 float4
            int idx = tid + i * 128;
            int k = idx >> 5, c4 = idx & 31;
            cp16(bb + k * (G_LDSB * 4) + c4 * 16, Bg + (size_t)k * N + c4 * 4);
        }
    };

    float acc[4][8][4];
    #pragma unroll
    for (int i = 0; i < 4; i++)
        #pragma unroll
        for (int j = 0; j < 8; j++)
            acc[i][j][0] = acc[i][j][1] = acc[i][j][2] = acc[i][j][3] = 0.0f;

    const int KT = K >> 5;
    stage(0, 0); CP_COMMIT();
    stage(1, 1); CP_COMMIT();

    for (int t = 0; t < KT; t++) {
        const int buf = t % G_STAGES;
        if (t + 1 < KT) { CP_WAIT(1); } else { CP_WAIT(0); }
        __syncthreads();
        if (t + 2 < KT) { stage(t + 2, (t + 2) % G_STAGES); CP_COMMIT(); }

        const float* As = (const float*)(smc + buf * G_STAGE);
        const float* Bs = (const float*)(smc + buf * G_STAGE + G_ABYTES);
        #pragma unroll
        for (int s = 0; s < 4; s++) {
            float af[4][4];
            float bf[8][2];
            #pragma unroll
            for (int mi = 0; mi < 4; mi++) {
                const int rm = warp_m * 64 + mi * 16;
                af[mi][0] = As[(rm + gi)     * G_LDSA + s * 8 + ti];
                af[mi][1] = As[(rm + gi + 8) * G_LDSA + s * 8 + ti];
                af[mi][2] = As[(rm + gi)     * G_LDSA + s * 8 + ti + 4];
                af[mi][3] = As[(rm + gi + 8) * G_LDSA + s * 8 + ti + 4];
            }
            #pragma unroll
            for (int nj = 0; nj < 8; nj++) {
                const int nn = warp_n * 64 + nj * 8;
                bf[nj][0] = Bs[(s * 8 + ti)     * G_LDSB + nn + gi];
                bf[nj][1] = Bs[(s * 8 + ti + 4) * G_LDSB + nn + gi];
            }
            #pragma unroll
            for (int mi = 0; mi < 4; mi++)
                #pragma unroll
                for (int nj = 0; nj < 8; nj++)
                    mma_m16n8k8(acc[mi][nj], af[mi], bf[nj][0], bf[nj][1]);
        }
    }

    #pragma unroll
    for (int mi = 0; mi < 4; mi++) {
        const int row = m0 + warp_m * 64 + mi * 16 + gi;
        #pragma unroll
        for (int nj = 0; nj < 8; nj++) {
            const int col = n0 + warp_n * 64 + nj * 8 + 2 * ti;
            float2 v0 = make_float2(acc[mi][nj][0], acc[mi][nj][1]);
            float2 v1 = make_float2(acc[mi][nj][2], acc[mi][nj][3]);
            if (ROUND) {
                v0.x = to_tf32(v0.x); v0.y = to_tf32(v0.y);
                v1.x = to_tf32(v1.x); v1.y = to_tf32(v1.y);
            }
            *(float2*)&C[(size_t)row * N + col]       = v0;
            *(float2*)&C[(size_t)(row + 8) * N + col] = v1;
        }
    }
}

// ---------------------------------------------------------------------------
// Flash attention: Br=128, Bc=64. 128 threads = 4 warps, each warp owns a
// 32-row query slice (two m16 halves) so every K/V b-fragment is reused by
// 2 MMAs. Register-resident S and O, double-buffered K/V via cp.async,
// exp2-based softmax (log2e folded into Q scale).
//   smem: K0,K1,V0,V1 (64x72 each) + P (128x72) = 110592 B -> 2 CTAs/SM
// ---------------------------------------------------------------------------
#define SLD 72
#define KV_TILE (64 * SLD)
#define P_OFF   (4 * KV_TILE)
#define ATTN_SMEM_BYTES ((4 * KV_TILE + 128 * SLD) * 4)   // 110592 B
#define QSCALE  (0.125f * 1.4426950408889634f)            // log2e / sqrt(dh)

__global__ __launch_bounds__(128, 2)
void flash_attn2_kernel() {
    extern __shared__ float sm[];

    const int tid  = threadIdx.x;
    const int lane = tid & 31;
    const int wid  = tid >> 5;          // 0..3
    const int gi   = lane >> 2;
    const int ti   = lane & 3;
    const int bh = blockIdx.y;
    const int b = bh >> 4, h = bh & 15;
    const int qb = blockIdx.x;          // 128-row query tile

    const float* qbase = g_qkv + (size_t)(b * SEQ + qb * 128) * QKVN + h * DH;
    const float* kbase = g_qkv + (size_t)(b * SEQ) * QKVN + EMB + h * DH;
    const float* vbase = g_qkv + (size_t)(b * SEQ) * QKVN + 2 * EMB + h * DH;
    const unsigned smb = smem_u32(sm);

    auto stage_kv = [&](int jt, int buf) {
        const unsigned kb = smb + buf * (KV_TILE * 4);
        const unsigned vb = smb + (2 + buf) * (KV_TILE * 4);
        #pragma unroll
        for (int i = 0; i < 8; i++) {
            int idx = tid + i * 128;
            int r = idx >> 4, c = idx & 15;
            size_t g = (size_t)(jt * 64 + r) * QKVN + c * 4;
            unsigned so = r * (SLD * 4) + c * 16;
            cp16(kb + so, kbase + g);
            cp16(vb + so, vbase + g);
        }
    };

    // Prefetch tile 0 while we stage Q (through the P region)
    stage_kv(0, 0);
    CP_COMMIT();

    float* Pq = sm + P_OFF;
    #pragma unroll
    for (int i = tid; i < 128 * 16; i += 128) {
        int r = i >> 4, c = (i & 15) * 4;
        float4 v = *(const float4*)&qbase[(size_t)r * QKVN + c];
        v.x = to_tf32(v.x * QSCALE);
        v.y = to_tf32(v.y * QSCALE);
        v.z = to_tf32(v.z * QSCALE);
        v.w = to_tf32(v.w * QSCALE);
        *(float4*)&Pq[r * SLD + c] = v;
    }
    __syncthreads();

    // Warp owns rows [wid*32, wid*32+32): half A = +{gi, gi+8}, half B = +16.
    const int rA = wid * 32 + gi;
    const int rB = rA + 16;

    float qa[2][8][4];
    #pragma unroll
    for (int kc = 0; kc < 8; kc++) {
        qa[0][kc][0] = Pq[rA * SLD + kc * 8 + ti];
        qa[0][kc][1] = Pq[(rA + 8) * SLD + kc * 8 + ti];
        qa[0][kc][2] = Pq[rA * SLD + kc * 8 + ti + 4];
        qa[0][kc][3] = Pq[(rA + 8) * SLD + kc * 8 + ti + 4];
        qa[1][kc][0] = Pq[rB * SLD + kc * 8 + ti];
        qa[1][kc][1] = Pq[(rB + 8) * SLD + kc * 8 + ti];
        qa[1][kc][2] = Pq[rB * SLD + kc * 8 + ti + 4];
        qa[1][kc][3] = Pq[(rB + 8) * SLD + kc * 8 + ti + 4];
    }

    float o[2][8][4];
    #pragma unroll
    for (int hh = 0; hh < 2; hh++)
        #pragma unroll
        for (int j = 0; j < 8; j++)
            o[hh][j][0] = o[hh][j][1] = o[hh][j][2] = o[hh][j][3] = 0.0f;
    float mrow[2][2] = {{-1e30f, -1e30f}, {-1e30f, -1e30f}};
    float lrow[2][2] = {{0.0f, 0.0f}, {0.0f, 0.0f}};

    float* Pw = sm + P_OFF + wid * 32 * SLD;   // warp-private 32-row P tile

    const int NT = SEQ / 64;
    for (int jt = 0; jt < NT; jt++) {
        const int buf = jt & 1;
        CP_WAIT(0);
        __syncthreads();
        if (jt + 1 < NT) { stage_kv(jt + 1, buf ^ 1); CP_COMMIT(); }

        const float* Ks = sm + buf * KV_TILE;
        const float* Vs = sm + (2 + buf) * KV_TILE;

        // ---- S = Q @ K^T  (both halves share every K b-fragment)
        float s[2][8][4];
        #pragma unroll
        for (int hh = 0; hh < 2; hh++)
            #pragma unroll
            for (int j = 0; j < 8; j++)
                s[hh][j][0] = s[hh][j][1] = s[hh][j][2] = s[hh][j][3] = 0.0f;
        #pragma unroll
        for (int kc = 0; kc < 8; kc++) {
            #pragma unroll
            for (int j = 0; j < 8; j++) {
                float b0 = Ks[(j * 8 + gi) * SLD + kc * 8 + ti];
                float b1 = Ks[(j * 8 + gi) * SLD + kc * 8 + ti + 4];
                mma_m16n8k8(s[0][j], qa[0][kc], b0, b1);
                mma_m16n8k8(s[1][j], qa[1][kc], b0, b1);
            }
        }

        // ---- Online softmax (base-2), per half
        #pragma unroll
        for (int hh = 0; hh < 2; hh++) {
            float a0 = -1e30f, a1 = -1e30f;
            #pragma unroll
            for (int j = 0; j < 8; j++) {
                a0 = fmaxf(a0, fmaxf(s[hh][j][0], s[hh][j][1]));
                a1 = fmaxf(a1, fmaxf(s[hh][j][2], s[hh][j][3]));
            }
            a0 = fmaxf(a0, __shfl_xor_sync(0xffffffffu, a0, 1));
            a0 = fmaxf(a0, __shfl_xor_sync(0xffffffffu, a0, 2));
            a1 = fmaxf(a1, __shfl_xor_sync(0xffffffffu, a1, 1));
            a1 = fmaxf(a1, __shfl_xor_sync(0xffffffffu, a1, 2));

            float mn0 = fmaxf(mrow[hh][0], a0), mn1 = fmaxf(mrow[hh][1], a1);
            float c0 = ex2(mrow[hh][0] - mn0), c1 = ex2(mrow[hh][1] - mn1);
            float sum0 = 0.0f, sum1 = 0.0f;
            #pragma unroll
            for (int j = 0; j < 8; j++) {
                float p00 = ex2(s[hh][j][0] - mn0);
                float p01 = ex2(s[hh][j][1] - mn0);
                float p10 = ex2(s[hh][j][2] - mn1);
                float p11 = ex2(s[hh][j][3] - mn1);
                sum0 += p00 + p01;
                sum1 += p10 + p11;
                s[hh][j][0] = to_tf32(p00);
                s[hh][j][1] = to_tf32(p01);
                s[hh][j][2] = to_tf32(p10);
                s[hh][j][3] = to_tf32(p11);
            }
            sum0 += __shfl_xor_sync(0xffffffffu, sum0, 1);
            sum0 += __shfl_xor_sync(0xffffffffu, sum0, 2);
            sum1 += __shfl_xor_sync(0xffffffffu, sum1, 1);
            sum1 += __shfl_xor_sync(0xffffffffu, sum1, 2);

            mrow[hh][0] = mn0; mrow[hh][1] = mn1;
            lrow[hh][0] = lrow[hh][0] * c0 + sum0;
            lrow[hh][1] = lrow[hh][1] * c1 + sum1;

            #pragma unroll
            for (int j = 0; j < 8; j++) {
                o[hh][j][0] *= c0; o[hh][j][1] *= c0;
                o[hh][j][2] *= c1; o[hh][j][3] *= c1;
            }

            // P: C-layout regs -> warp-private smem (rows +16*hh)
            #pragma unroll
            for (int j = 0; j < 8; j++) {
                *(float2*)&Pw[(hh * 16 + gi) * SLD + j * 8 + 2 * ti] =
                    make_float2(s[hh][j][0], s[hh][j][1]);
                *(float2*)&Pw[(hh * 16 + gi + 8) * SLD + j * 8 + 2 * ti] =
                    make_float2(s[hh][j][2], s[hh][j][3]);
            }
        }
        __syncwarp();

        // ---- O += P @ V  (both halves share every V b-fragment)
        #pragma unroll
        for (int kc = 0; kc < 8; kc++) {
            float pa0[4], pa1[4];
            pa0[0] = Pw[gi * SLD + kc * 8 + ti];
            pa0[1] = Pw[(gi + 8) * SLD + kc * 8 + ti];
            pa0[2] = Pw[gi * SLD + kc * 8 + ti + 4];
            pa0[3] = Pw[(gi + 8) * SLD + kc * 8 + ti + 4];
            pa1[0] = Pw[(16 + gi) * SLD + kc * 8 + ti];
            pa1[1] = Pw[(16 + gi + 8) * SLD + kc * 8 + ti];
            pa1[2] = Pw[(16 + gi) * SLD + kc * 8 + ti + 4];
            pa1[3] = Pw[(16 + gi + 8) * SLD + kc * 8 + ti + 4];
            #pragma unroll
            for (int j = 0; j < 8; j++) {
                float b0 = Vs[(kc * 8 + ti) * SLD + j * 8 + gi];
                float b1 = Vs[(kc * 8 + ti + 4) * SLD + j * 8 + gi];
                mma_m16n8k8(o[0][j], pa0, b0, b1);
                mma_m16n8k8(o[1][j], pa1, b0, b1);
            }
        }
    }

    // ---- Epilogue: normalize, round to tf32 (feeds out-proj GEMM), store
    #pragma unroll
    for (int hh = 0; hh < 2; hh++) {
        const float inv0 = 1.0f / lrow[hh][0];
        const float inv1 = 1.0f / lrow[hh][1];
        const size_t row0 = (size_t)(b * SEQ + qb * 128 + wid * 32 + hh * 16 + gi);
        const size_t row1 = row0 + 8;
        #pragma unroll
        for (int j = 0; j < 8; j++) {
            size_t col = h * DH + j * 8 + 2 * ti;
            *(float2*)&g_att[row0 * EMB + col] =
                make_float2(to_tf32(o[hh][j][0] * inv0), to_tf32(o[hh][j][1] * inv0));
            *(float2*)&g_att[row1 * EMB + col] =
                make_float2(to_tf32(o[hh][j][2] * inv1), to_tf32(o[hh][j][3] * inv1));
        }
    }
}

// ---------------------------------------------------------------------------
// Launch
// ---------------------------------------------------------------------------
extern "C" void kernel_launch(void* const* d_in, const int* in_sizes, int n_in,
                              void* d_out, int out_size) {
    const float* x     = (const float*)d_in[0];   // [4,2048,1024]
    const float* w_qkv = (const float*)d_in[1];   // [1024,3072]
    const float* w_out = (const float*)d_in[2];   // [1024,1024]
    float* out = (float*)d_out;                   // [4,2048,1024]

    float *qkv, *att, *xr, *wq, *wo;
    cudaGetSymbolAddress((void**)&qkv, g_qkv);
    cudaGetSymbolAddress((void**)&att, g_att);
    cudaGetSymbolAddress((void**)&xr,  g_x);
    cudaGetSymbolAddress((void**)&wq,  g_wq);
    cudaGetSymbolAddress((void**)&wo,  g_wo);

    cudaFuncSetAttribute(gemm_mma_kernel<true>,
                         cudaFuncAttributeMaxDynamicSharedMemorySize, GEMM_SMEM_BYTES);
    cudaFuncSetAttribute(gemm_mma_kernel<false>,
                         cudaFuncAttributeMaxDynamicSharedMemorySize, GEMM_SMEM_BYTES);
    cudaFuncSetAttribute(flash_attn2_kernel,
                         cudaFuncAttributeMaxDynamicSharedMemorySize, ATTN_SMEM_BYTES);

    // 0) Pre-round inputs to tf32
    round_tf32_kernel<<<(ROWS * EMB) / 1024, 256>>>(x, xr);
    round_tf32_kernel<<<(EMB * QKVN) / 1024, 256>>>(w_qkv, wq);
    round_tf32_kernel<<<(EMB * EMB) / 1024, 256>>>(w_out, wo);

    // 1) QKV projection: [8192,1024] @ [1024,3072] -> g_qkv (tf32-rounded)
    {
        dim3 grid(QKVN / 128, ROWS / 128);
        gemm_mma_kernel<true><<<grid, 128, GEMM_SMEM_BYTES>>>(xr, wq, qkv, QKVN, EMB);
    }
    // 2) Flash attention: g_qkv -> g_att (tf32-rounded)
    {
        dim3 grid(SEQ / 128, BATCH * NH);
        flash_attn2_kernel<<<grid, 128, ATTN_SMEM_BYTES>>>();
    }
    // 3) Output projection: [8192,1024] @ [1024,1024] -> d_out (full fp32)
    {
        dim3 grid(EMB / 128, ROWS / 128);
        gemm_mma_kernel<false><<<grid, 128, GEMM_SMEM_BYTES>>>(att, wo, out, EMB, EMB);
    }
}

// round 12
// speedup vs baseline: 3.9993x; 1.2091x over previous
#include <cuda_runtime.h>
#include <cuda_fp16.h>
#include <cstdint>

// Problem constants
#define BATCH 4
#define SEQ   2048
#define EMB   1024
#define NH    16
#define DH    64
#define ROWS  (BATCH * SEQ)        // 8192
#define QKVN  (3 * EMB)            // 3072

// Scratch (allocation-guard-safe device globals), fp16 datapath
__device__ __half g_xh [(size_t)ROWS * EMB];    // x, fp16            16 MB
__device__ __half g_wqT[(size_t)QKVN * EMB];    // w_qkv^T [3072][1024] 6 MB
__device__ __half g_woT[(size_t)EMB * EMB];     // w_out^T [1024][1024] 2 MB
__device__ __half g_qkv[(size_t)ROWS * QKVN];   // qkv, fp16           48 MB
__device__ __half g_vT [(size_t)ROWS * EMB];    // V^T per (b,h): [bh][64][2048] 16 MB
__device__ __half g_att[(size_t)ROWS * EMB];    // attention out, fp16 16 MB

// ---------------------------------------------------------------------------
// Helpers
// ---------------------------------------------------------------------------
__device__ __forceinline__ float ex2(float x) {
    float r;
    asm("ex2.approx.f32 %0, %1;" : "=f"(r) : "f"(x));
    return r;
}

__device__ __forceinline__ unsigned smem_u32(const void* p) {
    return (unsigned)__cvta_generic_to_shared(p);
}

__device__ __forceinline__ void cp16(unsigned dst, const void* src) {
    asm volatile("cp.async.cg.shared.global [%0], [%1], 16;"
                 :: "r"(dst), "l"(__cvta_generic_to_global(src)));
}
#define CP_COMMIT() asm volatile("cp.async.commit_group;" ::: "memory")
#define CP_WAIT(n)  asm volatile("cp.async.wait_group %0;" :: "n"(n) : "memory")

// fp16 m16n8k16: D(f32) += A(f16) @ B(f16)
__device__ __forceinline__ void mma_f16(float d[4], const unsigned a[4],
                                        unsigned b0, unsigned b1) {
    asm volatile(
        "mma.sync.aligned.m16n8k16.row.col.f32.f16.f16.f32 "
        "{%0,%1,%2,%3}, {%4,%5,%6,%7}, {%8,%9}, {%0,%1,%2,%3};\n"
        : "+f"(d[0]), "+f"(d[1]), "+f"(d[2]), "+f"(d[3])
        : "r"(a[0]), "r"(a[1]), "r"(a[2]), "r"(a[3]), "r"(b0), "r"(b1));
}

__device__ __forceinline__ unsigned pack_h2(float lo, float hi) {
    __half2 h = __floats2half2_rn(lo, hi);
    return *reinterpret_cast<unsigned*>(&h);
}

// ---------------------------------------------------------------------------
// Prep kernels
// ---------------------------------------------------------------------------
// f32 -> f16 copy (8 floats / thread)
__global__ __launch_bounds__(256)
void cvt_h_kernel(const float* __restrict__ in, __half* __restrict__ out) {
    size_t i = ((size_t)blockIdx.x * 256 + threadIdx.x) * 8;
    float4 v0 = *(const float4*)(in + i);
    float4 v1 = *(const float4*)(in + i + 4);
    uint4 o;
    o.x = pack_h2(v0.x, v0.y); o.y = pack_h2(v0.z, v0.w);
    o.z = pack_h2(v1.x, v1.y); o.w = pack_h2(v1.z, v1.w);
    *(uint4*)(out + i) = o;
}

// f32 [R][C] -> f16 [C][R] (transpose + convert), 32x32 tiles, block (32,8)
__global__ __launch_bounds__(256)
void transpose_h_kernel(const float* __restrict__ in, __half* __restrict__ out,
                        int R, int C) {
    __shared__ float tile[32][33];
    const int tx = threadIdx.x, ty = threadIdx.y;
    const int c0 = blockIdx.x * 32, r0 = blockIdx.y * 32;
    #pragma unroll
    for (int i = 0; i < 4; i++)
        tile[ty + i * 8][tx] = in[(size_t)(r0 + ty + i * 8) * C + c0 + tx];
    __syncthreads();
    #pragma unroll
    for (int i = 0; i < 4; i++)
        out[(size_t)(c0 + ty + i * 8) * R + r0 + tx] =
            __float2half_rn(tile[tx][ty + i * 8]);
}

// V transpose: g_qkv V region [t][d] -> g_vT [bh][d][t], 64x64 fp16 tiles
__global__ __launch_bounds__(128)
void transpose_v_kernel() {
    __shared__ __half tile[64 * 74];
    const int tid = threadIdx.x;
    const int bh = blockIdx.y;
    const int b = bh >> 4, h = bh & 15;
    const int t0 = blockIdx.x * 64;
    const __half* src = g_qkv + (size_t)(b * SEQ + t0) * QKVN + 2 * EMB + h * DH;
    __half* dst = g_vT + (size_t)bh * DH * SEQ + t0;

    unsigned* tw = (unsigned*)tile;   // only even half-index accesses via u32
    #pragma unroll
    for (int i = 0; i < 16; i++) {    // 2048 half2 slots: 64 t-rows x 32
        int idx = tid + i * 128;
        int r = idx >> 5, c2 = idx & 31;
        unsigned v = *(const unsigned*)(src + (size_t)r * QKVN + c2 * 2);
        tw[(r * 74 + c2 * 2) >> 1] = v;
    }
    __syncthreads();
    const unsigned short* th = (const unsigned short*)tile;
    #pragma unroll
    for (int i = 0; i < 16; i++) {    // 2048 half2 slots: 64 d-rows x 32
        int idx = tid + i * 128;
        int d = idx >> 5, tc = idx & 31;
        unsigned lo = th[(2 * tc) * 74 + d];
        unsigned hi = th[(2 * tc + 1) * 74 + d];
        *(unsigned*)(dst + (size_t)d * SEQ + 2 * tc) = lo | (hi << 16);
    }
}

// ---------------------------------------------------------------------------
// fp16 GEMM: C[M,N] = A[M,K] @ Bt[N,K]^T. A, Bt fp16 k-major. BK=64.
// Block tile 128x128, 3-stage cp.async, 128 threads = 4 warps (2x2),
// warp tile 64x64, m16n8k16. Smem rows: 64 halfs + 8 pad = 144 B.
// ---------------------------------------------------------------------------
#define H_ROWB 144                         // bytes per smem row
#define H_ROWW 36                          // u32 words per smem row
#define G_TILEB (128 * H_ROWB)             // 18432 B (A or Bt tile)
#define G_STAGE (2 * G_TILEB)              // 36864 B
#define G_STAGES 3
#define GEMM_SMEM_BYTES (G_STAGES * G_STAGE)   // 110592 B

template<bool HALF_OUT>
__global__ __launch_bounds__(128, 2)
void gemm_f16_kernel(const __half* __restrict__ A, const __half* __restrict__ Bt,
                     void* __restrict__ Cv, int N, int K) {
    extern __shared__ char smc[];
    const unsigned abase0 = smem_u32(smc);
    const unsigned bbase0 = abase0 + G_TILEB;

    const int tid  = threadIdx.x;
    const int lane = tid & 31;
    const int wid  = tid >> 5;
    const int gi   = lane >> 2;
    const int ti   = lane & 3;
    const int warp_m = wid >> 1;
    const int warp_n = wid & 1;
    const int m0 = blockIdx.y * 128;
    const int n0 = blockIdx.x * 128;

    auto stage = [&](int t, int buf) {
        const unsigned ab = abase0 + buf * G_STAGE;
        const unsigned bb = bbase0 + buf * G_STAGE;
        const __half* Ag = A  + (size_t)m0 * K + t * 64;
        const __half* Bg = Bt + (size_t)n0 * K + t * 64;
        #pragma unroll
        for (int i = 0; i < 8; i++) {          // 1024 16B chunks each
            int idx = tid + i * 128;
            int r = idx >> 3, c = idx & 7;     // 128 rows x 8 chunks
            cp16(ab + r * H_ROWB + c * 16, Ag + (size_t)r * K + c * 8);
            cp16(bb + r * H_ROWB + c * 16, Bg + (size_t)r * K + c * 8);
        }
    };

    float acc[4][8][4];
    #pragma unroll
    for (int i = 0; i < 4; i++)
        #pragma unroll
        for (int j = 0; j < 8; j++)
            acc[i][j][0] = acc[i][j][1] = acc[i][j][2] = acc[i][j][3] = 0.0f;

    const int KT = K >> 6;                     // 16 k-tiles
    stage(0, 0); CP_COMMIT();
    stage(1, 1); CP_COMMIT();

    for (int t = 0; t < KT; t++) {
        const int buf = t % G_STAGES;
        if (t + 1 < KT) { CP_WAIT(1); } else { CP_WAIT(0); }
        __syncthreads();
        if (t + 2 < KT) { stage(t + 2, (t + 2) % G_STAGES); CP_COMMIT(); }

        const unsigned* As = (const unsigned*)(smc + buf * G_STAGE);
        const unsigned* Bs = (const unsigned*)(smc + buf * G_STAGE + G_TILEB);
        #pragma unroll
        for (int s = 0; s < 4; s++) {          // 4 x k16 steps
            unsigned af[4][4];
            unsigned bf[8][2];
            #pragma unroll
            for (int mi = 0; mi < 4; mi++) {
                const int rm = warp_m * 64 + mi * 16;
                const int w = s * 8 + ti;
                af[mi][0] = As[(rm + gi)     * H_ROWW + w];
                af[mi][1] = As[(rm + gi + 8) * H_ROWW + w];
                af[mi][2] = As[(rm + gi)     * H_ROWW + w + 4];
                af[mi][3] = As[(rm + gi + 8) * H_ROWW + w + 4];
            }
            #pragma unroll
            for (int nj = 0; nj < 8; nj++) {
                const int rn = warp_n * 64 + nj * 8 + gi;
                const int w = s * 8 + ti;
                bf[nj][0] = Bs[rn * H_ROWW + w];
                bf[nj][1] = Bs[rn * H_ROWW + w + 4];
            }
            #pragma unroll
            for (int mi = 0; mi < 4; mi++)
                #pragma unroll
                for (int nj = 0; nj < 8; nj++)
                    mma_f16(acc[mi][nj], af[mi], bf[nj][0], bf[nj][1]);
        }
    }

    #pragma unroll
    for (int mi = 0; mi < 4; mi++) {
        const int row = m0 + warp_m * 64 + mi * 16 + gi;
        #pragma unroll
        for (int nj = 0; nj < 8; nj++) {
            const int col = n0 + warp_n * 64 + nj * 8 + 2 * ti;
            if (HALF_OUT) {
                __half* C = (__half*)Cv;
                *(unsigned*)&C[(size_t)row * N + col] =
                    pack_h2(acc[mi][nj][0], acc[mi][nj][1]);
                *(unsigned*)&C[(size_t)(row + 8) * N + col] =
                    pack_h2(acc[mi][nj][2], acc[mi][nj][3]);
            } else {
                float* C = (float*)Cv;
                *(float2*)&C[(size_t)row * N + col] =
                    make_float2(acc[mi][nj][0], acc[mi][nj][1]);
                *(float2*)&C[(size_t)(row + 8) * N + col] =
                    make_float2(acc[mi][nj][2], acc[mi][nj][3]);
            }
        }
    }
}

// ---------------------------------------------------------------------------
// Flash attention, fp16 m16n8k16. Br=128, Bc=64, 128 threads = 4 warps,
// warp owns 32 query rows (2 m16 halves sharing every K/V b-fragment).
// P stays in registers (C-frag packs directly into A-frag for k16).
// V consumed as V^T.
//   smem: K0,K1,Vt0,Vt1 (64x144B) + Q (128x144B) = 55296 B
// ---------------------------------------------------------------------------
#define KV_TILEB (64 * H_ROWB)             // 9216 B
#define AQ_OFF   (4 * KV_TILEB)
#define ATTN_SMEM_BYTES (4 * KV_TILEB + 128 * H_ROWB)   // 55296 B
#define QSCALE  (0.125f * 1.4426950408889634f)          // log2e / sqrt(dh)

__global__ __launch_bounds__(128, 2)
void flash_attn_f16_kernel() {
    extern __shared__ char smc[];
    const unsigned smb = smem_u32(smc);

    const int tid  = threadIdx.x;
    const int lane = tid & 31;
    const int wid  = tid >> 5;          // 0..3
    const int gi   = lane >> 2;
    const int ti   = lane & 3;
    const int bh = blockIdx.y;
    const int b = bh >> 4, h = bh & 15;
    const int qb = blockIdx.x;          // 128-row query tile

    const __half* qbase = g_qkv + (size_t)(b * SEQ + qb * 128) * QKVN + h * DH;
    const __half* kbase = g_qkv + (size_t)(b * SEQ) * QKVN + EMB + h * DH;
    const __half* vtbase = g_vT + (size_t)bh * DH * SEQ;

    // 64-row x 64-half tiles = 512 16B chunks each (BUGFIX: was 1024)
    auto stage_kv = [&](int jt, int buf) {
        const unsigned kb = smb + buf * KV_TILEB;
        const unsigned vb = smb + (2 + buf) * KV_TILEB;
        #pragma unroll
        for (int i = 0; i < 4; i++) {
            int idx = tid + i * 128;    // 0..511
            int r = idx >> 3, c = idx & 7;
            cp16(kb + r * H_ROWB + c * 16,
                 kbase + (size_t)(jt * 64 + r) * QKVN + c * 8);
            cp16(vb + r * H_ROWB + c * 16,
                 vtbase + (size_t)r * SEQ + jt * 64 + c * 8);
        }
    };

    // Prefetch tile 0, stage Q (128 rows x 8 chunks = 1024)
    stage_kv(0, 0);
    CP_COMMIT();
    {
        const unsigned qsm = smb + AQ_OFF;
        #pragma unroll
        for (int i = 0; i < 8; i++) {
            int idx = tid + i * 128;
            int r = idx >> 3, c = idx & 7;
            cp16(qsm + r * H_ROWB + c * 16, qbase + (size_t)r * QKVN + c * 8);
        }
        CP_COMMIT();
    }
    CP_WAIT(0);
    __syncthreads();

    // Warp rows [wid*32, wid*32+32): half 0 = +{gi,gi+8}, half 1 = +16.
    const unsigned* Qw = (const unsigned*)(smc + AQ_OFF);
    unsigned qa[2][4][4];
    #pragma unroll
    for (int kc = 0; kc < 4; kc++) {
        #pragma unroll
        for (int hh = 0; hh < 2; hh++) {
            const int r = wid * 32 + hh * 16 + gi;
            const int w = kc * 8 + ti;
            qa[hh][kc][0] = Qw[r * H_ROWW + w];
            qa[hh][kc][1] = Qw[(r + 8) * H_ROWW + w];
            qa[hh][kc][2] = Qw[r * H_ROWW + w + 4];
            qa[hh][kc][3] = Qw[(r + 8) * H_ROWW + w + 4];
        }
    }

    float o[2][8][4];
    #pragma unroll
    for (int hh = 0; hh < 2; hh++)
        #pragma unroll
        for (int j = 0; j < 8; j++)
            o[hh][j][0] = o[hh][j][1] = o[hh][j][2] = o[hh][j][3] = 0.0f;
    float mrow[2][2] = {{-1e30f, -1e30f}, {-1e30f, -1e30f}};
    float lrow[2][2] = {{0.0f, 0.0f}, {0.0f, 0.0f}};

    const int NT = SEQ / 64;
    for (int jt = 0; jt < NT; jt++) {
        const int buf = jt & 1;
        if (jt > 0) {
            CP_WAIT(0);
            __syncthreads();
        }
        if (jt + 1 < NT) { stage_kv(jt + 1, buf ^ 1); CP_COMMIT(); }

        const unsigned* Ks = (const unsigned*)(smc + buf * KV_TILEB);
        const unsigned* Vs = (const unsigned*)(smc + (2 + buf) * KV_TILEB);

        // ---- S = Q @ K^T  (n = t 64-wide: 8 tiles; k = d: 4 k16 steps)
        float s[2][8][4];
        #pragma unroll
        for (int hh = 0; hh < 2; hh++)
            #pragma unroll
            for (int j = 0; j < 8; j++)
                s[hh][j][0] = s[hh][j][1] = s[hh][j][2] = s[hh][j][3] = 0.0f;
        #pragma unroll
        for (int kc = 0; kc < 4; kc++) {
            #pragma unroll
            for (int j = 0; j < 8; j++) {
                const int rn = j * 8 + gi;
                const int w = kc * 8 + ti;
                unsigned b0 = Ks[rn * H_ROWW + w];
                unsigned b1 = Ks[rn * H_ROWW + w + 4];
                mma_f16(s[0][j], qa[0][kc], b0, b1);
                mma_f16(s[1][j], qa[1][kc], b0, b1);
            }
        }

        // ---- Online softmax (base-2, 1/sqrt(dh) folded into exp argument)
        unsigned pa[2][4][4];     // P packed directly as PV A-fragments
        #pragma unroll
        for (int hh = 0; hh < 2; hh++) {
            float a0 = -1e30f, a1 = -1e30f;
            #pragma unroll
            for (int j = 0; j < 8; j++) {
                a0 = fmaxf(a0, fmaxf(s[hh][j][0], s[hh][j][1]));
                a1 = fmaxf(a1, fmaxf(s[hh][j][2], s[hh][j][3]));
            }
            a0 = fmaxf(a0, __shfl_xor_sync(0xffffffffu, a0, 1));
            a0 = fmaxf(a0, __shfl_xor_sync(0xffffffffu, a0, 2));
            a1 = fmaxf(a1, __shfl_xor_sync(0xffffffffu, a1, 1));
            a1 = fmaxf(a1, __shfl_xor_sync(0xffffffffu, a1, 2));

            float mn0 = fmaxf(mrow[hh][0], a0), mn1 = fmaxf(mrow[hh][1], a1);
            float c0 = ex2((mrow[hh][0] - mn0) * QSCALE);
            float c1 = ex2((mrow[hh][1] - mn1) * QSCALE);
            float z0 = mn0 * QSCALE, z1 = mn1 * QSCALE;
            float sum0 = 0.0f, sum1 = 0.0f;
            #pragma unroll
            for (int j = 0; j < 8; j++) {
                float p00 = ex2(fmaf(s[hh][j][0], QSCALE, -z0));
                float p01 = ex2(fmaf(s[hh][j][1], QSCALE, -z0));
                float p10 = ex2(fmaf(s[hh][j][2], QSCALE, -z1));
                float p11 = ex2(fmaf(s[hh][j][3], QSCALE, -z1));
                sum0 += p00 + p01;
                sum1 += p10 + p11;
                s[hh][j][0] = p00; s[hh][j][1] = p01;
                s[hh][j][2] = p10; s[hh][j][3] = p11;
            }
            sum0 += __shfl_xor_sync(0xffffffffu, sum0, 1);
            sum0 += __shfl_xor_sync(0xffffffffu, sum0, 2);
            sum1 += __shfl_xor_sync(0xffffffffu, sum1, 1);
            sum1 += __shfl_xor_sync(0xffffffffu, sum1, 2);

            mrow[hh][0] = mn0; mrow[hh][1] = mn1;
            lrow[hh][0] = lrow[hh][0] * c0 + sum0;
            lrow[hh][1] = lrow[hh][1] * c1 + sum1;

            #pragma unroll
            for (int j = 0; j < 8; j++) {
                o[hh][j][0] *= c0; o[hh][j][1] *= c0;
                o[hh][j][2] *= c1; o[hh][j][3] *= c1;
            }
            // Pack P: k16-step kc spans S n-tiles {2kc, 2kc+1}
            #pragma unroll
            for (int kc = 0; kc < 4; kc++) {
                pa[hh][kc][0] = pack_h2(s[hh][2 * kc][0],     s[hh][2 * kc][1]);
                pa[hh][kc][1] = pack_h2(s[hh][2 * kc][2],     s[hh][2 * kc][3]);
                pa[hh][kc][2] = pack_h2(s[hh][2 * kc + 1][0], s[hh][2 * kc + 1][1]);
                pa[hh][kc][3] = pack_h2(s[hh][2 * kc + 1][2], s[hh][2 * kc + 1][3]);
            }
        }

        // ---- O += P @ V  (n = d: 8 tiles; k = t: 4 k16 steps; Vt[d][t])
        #pragma unroll
        for (int kc = 0; kc < 4; kc++) {
            #pragma unroll
            for (int j = 0; j < 8; j++) {
                const int rn = j * 8 + gi;
                const int w = kc * 8 + ti;
                unsigned b0 = Vs[rn * H_ROWW + w];
                unsigned b1 = Vs[rn * H_ROWW + w + 4];
                mma_f16(o[0][j], pa[0][kc], b0, b1);
                mma_f16(o[1][j], pa[1][kc], b0, b1);
            }
        }
    }

    // ---- Epilogue: normalize, fp16 store to g_att (feeds out-proj A)
    #pragma unroll
    for (int hh = 0; hh < 2; hh++) {
        const float inv0 = 1.0f / lrow[hh][0];
        const float inv1 = 1.0f / lrow[hh][1];
        const size_t row0 = (size_t)(b * SEQ + qb * 128 + wid * 32 + hh * 16 + gi);
        const size_t row1 = row0 + 8;
        #pragma unroll
        for (int j = 0; j < 8; j++) {
            size_t col = h * DH + j * 8 + 2 * ti;
            *(unsigned*)&g_att[row0 * EMB + col] =
                pack_h2(o[hh][j][0] * inv0, o[hh][j][1] * inv0);
            *(unsigned*)&g_att[row1 * EMB + col] =
                pack_h2(o[hh][j][2] * inv1, o[hh][j][3] * inv1);
        }
    }
}

// ---------------------------------------------------------------------------
// Launch
// ---------------------------------------------------------------------------
extern "C" void kernel_launch(void* const* d_in, const int* in_sizes, int n_in,
                              void* d_out, int out_size) {
    const float* x     = (const float*)d_in[0];   // [4,2048,1024]
    const float* w_qkv = (const float*)d_in[1];   // [1024,3072]
    const float* w_out = (const float*)d_in[2];   // [1024,1024]
    float* out = (float*)d_out;                   // [4,2048,1024]

    __half *xh, *wqT, *woT, *qkv, *att;
    cudaGetSymbolAddress((void**)&xh,  g_xh);
    cudaGetSymbolAddress((void**)&wqT, g_wqT);
    cudaGetSymbolAddress((void**)&woT, g_woT);
    cudaGetSymbolAddress((void**)&qkv, g_qkv);
    cudaGetSymbolAddress((void**)&att, g_att);

    cudaFuncSetAttribute(gemm_f16_kernel<true>,
                         cudaFuncAttributeMaxDynamicSharedMemorySize, GEMM_SMEM_BYTES);
    cudaFuncSetAttribute(gemm_f16_kernel<false>,
                         cudaFuncAttributeMaxDynamicSharedMemorySize, GEMM_SMEM_BYTES);
    cudaFuncSetAttribute(flash_attn_f16_kernel,
                         cudaFuncAttributeMaxDynamicSharedMemorySize, ATTN_SMEM_BYTES);

    // 0) Convert / transpose inputs to fp16
    cvt_h_kernel<<<(ROWS * EMB) / (256 * 8), 256>>>(x, xh);
    {
        dim3 g(QKVN / 32, EMB / 32);
        transpose_h_kernel<<<g, dim3(32, 8)>>>(w_qkv, wqT, EMB, QKVN);
    }
    {
        dim3 g(EMB / 32, EMB / 32);
        transpose_h_kernel<<<g, dim3(32, 8)>>>(w_out, woT, EMB, EMB);
    }

    // 1) QKV projection -> g_qkv (fp16)
    {
        dim3 grid(QKVN / 128, ROWS / 128);
        gemm_f16_kernel<true><<<grid, 128, GEMM_SMEM_BYTES>>>(xh, wqT, qkv, QKVN, EMB);
    }
    // 1b) V -> V^T per (b,h)
    {
        dim3 grid(SEQ / 64, BATCH * NH);
        transpose_v_kernel<<<grid, 128>>>();
    }
    // 2) Flash attention -> g_att (fp16)
    {
        dim3 grid(SEQ / 128, BATCH * NH);
        flash_attn_f16_kernel<<<grid, 128, ATTN_SMEM_BYTES>>>();
    }
    // 3) Output projection -> d_out (fp32)
    {
        dim3 grid(EMB / 128, ROWS / 128);
        gemm_f16_kernel<false><<<grid, 128, GEMM_SMEM_BYTES>>>(att, woT, out, EMB, EMB);
    }
}

// round 13
// speedup vs baseline: 6.1061x; 1.5268x over previous
#include <cuda_runtime.h>
#include <cuda_fp16.h>
#include <cstdint>

// Problem constants
#define BATCH 4
#define SEQ   2048
#define EMB   1024
#define NH    16
#define DH    64
#define ROWS  (BATCH * SEQ)        // 8192
#define QKVN  (3 * EMB)            // 3072

// Scratch (allocation-guard-safe device globals), fp16 datapath
__device__ __half g_xh [(size_t)ROWS * EMB];    // x, fp16            16 MB
__device__ __half g_wqT[(size_t)QKVN * EMB];    // w_qkv^T [3072][1024] 6 MB
__device__ __half g_woT[(size_t)EMB * EMB];     // w_out^T [1024][1024] 2 MB
__device__ __half g_qkv[(size_t)ROWS * QKVN];   // qkv, fp16           48 MB
__device__ __half g_vT [(size_t)ROWS * EMB];    // V^T per (b,h): [bh][64][2048] 16 MB
__device__ __half g_att[(size_t)ROWS * EMB];    // attention out, fp16 16 MB

// ---------------------------------------------------------------------------
// Helpers
// ---------------------------------------------------------------------------
__device__ __forceinline__ float ex2(float x) {
    float r;
    asm("ex2.approx.f32 %0, %1;" : "=f"(r) : "f"(x));
    return r;
}

__device__ __forceinline__ unsigned smem_u32(const void* p) {
    return (unsigned)__cvta_generic_to_shared(p);
}

__device__ __forceinline__ void cp16(unsigned dst, const void* src) {
    asm volatile("cp.async.cg.shared.global [%0], [%1], 16;"
                 :: "r"(dst), "l"(__cvta_generic_to_global(src)));
}
#define CP_COMMIT() asm volatile("cp.async.commit_group;" ::: "memory")
#define CP_WAIT(n)  asm volatile("cp.async.wait_group %0;" :: "n"(n) : "memory")

// fp16 m16n8k16: D(f32) += A(f16) @ B(f16).
// NOT volatile: no side effects; lets ptxas interleave/pipeline freely.
__device__ __forceinline__ void mma_f16(float d[4], const unsigned a[4],
                                        unsigned b0, unsigned b1) {
    asm("mma.sync.aligned.m16n8k16.row.col.f32.f16.f16.f32 "
        "{%0,%1,%2,%3}, {%4,%5,%6,%7}, {%8,%9}, {%0,%1,%2,%3};\n"
        : "+f"(d[0]), "+f"(d[1]), "+f"(d[2]), "+f"(d[3])
        : "r"(a[0]), "r"(a[1]), "r"(a[2]), "r"(a[3]), "r"(b0), "r"(b1));
}

__device__ __forceinline__ unsigned pack_h2(float lo, float hi) {
    __half2 h = __floats2half2_rn(lo, hi);
    return *reinterpret_cast<unsigned*>(&h);
}

// ---------------------------------------------------------------------------
// Prep kernels
// ---------------------------------------------------------------------------
// f32 -> f16 copy (8 floats / thread)
__global__ __launch_bounds__(256)
void cvt_h_kernel(const float* __restrict__ in, __half* __restrict__ out) {
    size_t i = ((size_t)blockIdx.x * 256 + threadIdx.x) * 8;
    float4 v0 = *(const float4*)(in + i);
    float4 v1 = *(const float4*)(in + i + 4);
    uint4 o;
    o.x = pack_h2(v0.x, v0.y); o.y = pack_h2(v0.z, v0.w);
    o.z = pack_h2(v1.x, v1.y); o.w = pack_h2(v1.z, v1.w);
    *(uint4*)(out + i) = o;
}

// f32 [R][C] -> f16 [C][R] (transpose + convert), 32x32 tiles, block (32,8)
__global__ __launch_bounds__(256)
void transpose_h_kernel(const float* __restrict__ in, __half* __restrict__ out,
                        int R, int C) {
    __shared__ float tile[32][33];
    const int tx = threadIdx.x, ty = threadIdx.y;
    const int c0 = blockIdx.x * 32, r0 = blockIdx.y * 32;
    #pragma unroll
    for (int i = 0; i < 4; i++)
        tile[ty + i * 8][tx] = in[(size_t)(r0 + ty + i * 8) * C + c0 + tx];
    __syncthreads();
    #pragma unroll
    for (int i = 0; i < 4; i++)
        out[(size_t)(c0 + ty + i * 8) * R + r0 + tx] =
            __float2half_rn(tile[tx][ty + i * 8]);
}

// V transpose: g_qkv V region [t][d] -> g_vT [bh][d][t], 64x64 fp16 tiles
__global__ __launch_bounds__(128)
void transpose_v_kernel() {
    __shared__ __half tile[64 * 74];
    const int tid = threadIdx.x;
    const int bh = blockIdx.y;
    const int b = bh >> 4, h = bh & 15;
    const int t0 = blockIdx.x * 64;
    const __half* src = g_qkv + (size_t)(b * SEQ + t0) * QKVN + 2 * EMB + h * DH;
    __half* dst = g_vT + (size_t)bh * DH * SEQ + t0;

    unsigned* tw = (unsigned*)tile;   // only even half-index accesses via u32
    #pragma unroll
    for (int i = 0; i < 16; i++) {    // 2048 half2 slots: 64 t-rows x 32
        int idx = tid + i * 128;
        int r = idx >> 5, c2 = idx & 31;
        unsigned v = *(const unsigned*)(src + (size_t)r * QKVN + c2 * 2);
        tw[(r * 74 + c2 * 2) >> 1] = v;
    }
    __syncthreads();
    const unsigned short* th = (const unsigned short*)tile;
    #pragma unroll
    for (int i = 0; i < 16; i++) {    // 2048 half2 slots: 64 d-rows x 32
        int idx = tid + i * 128;
        int d = idx >> 5, tc = idx & 31;
        unsigned lo = th[(2 * tc) * 74 + d];
        unsigned hi = th[(2 * tc + 1) * 74 + d];
        *(unsigned*)(dst + (size_t)d * SEQ + 2 * tc) = lo | (hi << 16);
    }
}

// ---------------------------------------------------------------------------
// fp16 GEMM: C[M,N] = A[M,K] @ Bt[N,K]^T. A, Bt fp16 k-major. BK=64.
// Block tile 128x128, 3-stage cp.async, 128 threads = 4 warps (2x2),
// warp tile 64x64, m16n8k16. Smem rows: 64 halfs + 8 pad = 144 B.
// ---------------------------------------------------------------------------
#define H_ROWB 144                         // bytes per smem row
#define H_ROWW 36                          // u32 words per smem row
#define G_TILEB (128 * H_ROWB)             // 18432 B (A or Bt tile)
#define G_STAGE (2 * G_TILEB)              // 36864 B
#define G_STAGES 3
#define GEMM_SMEM_BYTES (G_STAGES * G_STAGE)   // 110592 B

template<bool HALF_OUT>
__global__ __launch_bounds__(128, 2)
void gemm_f16_kernel(const __half* __restrict__ A, const __half* __restrict__ Bt,
                     void* __restrict__ Cv, int N, int K) {
    extern __shared__ char smc[];
    const unsigned abase0 = smem_u32(smc);
    const unsigned bbase0 = abase0 + G_TILEB;

    const int tid  = threadIdx.x;
    const int lane = tid & 31;
    const int wid  = tid >> 5;
    const int gi   = lane >> 2;
    const int ti   = lane & 3;
    const int warp_m = wid >> 1;
    const int warp_n = wid & 1;
    const int m0 = blockIdx.y * 128;
    const int n0 = blockIdx.x * 128;

    auto stage = [&](int t, int buf) {
        const unsigned ab = abase0 + buf * G_STAGE;
        const unsigned bb = bbase0 + buf * G_STAGE;
        const __half* Ag = A  + (size_t)m0 * K + t * 64;
        const __half* Bg = Bt + (size_t)n0 * K + t * 64;
        #pragma unroll
        for (int i = 0; i < 8; i++) {          // 1024 16B chunks each
            int idx = tid + i * 128;
            int r = idx >> 3, c = idx & 7;     // 128 rows x 8 chunks
            cp16(ab + r * H_ROWB + c * 16, Ag + (size_t)r * K + c * 8);
            cp16(bb + r * H_ROWB + c * 16, Bg + (size_t)r * K + c * 8);
        }
    };

    float acc[4][8][4];
    #pragma unroll
    for (int i = 0; i < 4; i++)
        #pragma unroll
        for (int j = 0; j < 8; j++)
            acc[i][j][0] = acc[i][j][1] = acc[i][j][2] = acc[i][j][3] = 0.0f;

    const int KT = K >> 6;                     // 16 k-tiles
    stage(0, 0); CP_COMMIT();
    stage(1, 1); CP_COMMIT();

    for (int t = 0; t < KT; t++) {
        const int buf = t % G_STAGES;
        if (t + 1 < KT) { CP_WAIT(1); } else { CP_WAIT(0); }
        __syncthreads();
        if (t + 2 < KT) { stage(t + 2, (t + 2) % G_STAGES); CP_COMMIT(); }

        const unsigned* As = (const unsigned*)(smc + buf * G_STAGE);
        const unsigned* Bs = (const unsigned*)(smc + buf * G_STAGE + G_TILEB);
        #pragma unroll
        for (int s = 0; s < 4; s++) {          // 4 x k16 steps
            unsigned af[4][4];
            unsigned bf[8][2];
            #pragma unroll
            for (int mi = 0; mi < 4; mi++) {
                const int rm = warp_m * 64 + mi * 16;
                const int w = s * 8 + ti;
                af[mi][0] = As[(rm + gi)     * H_ROWW + w];
                af[mi][1] = As[(rm + gi + 8) * H_ROWW + w];
                af[mi][2] = As[(rm + gi)     * H_ROWW + w + 4];
                af[mi][3] = As[(rm + gi + 8) * H_ROWW + w + 4];
            }
            #pragma unroll
            for (int nj = 0; nj < 8; nj++) {
                const int rn = warp_n * 64 + nj * 8 + gi;
                const int w = s * 8 + ti;
                bf[nj][0] = Bs[rn * H_ROWW + w];
                bf[nj][1] = Bs[rn * H_ROWW + w + 4];
            }
            #pragma unroll
            for (int mi = 0; mi < 4; mi++)
                #pragma unroll
                for (int nj = 0; nj < 8; nj++)
                    mma_f16(acc[mi][nj], af[mi], bf[nj][0], bf[nj][1]);
        }
    }

    #pragma unroll
    for (int mi = 0; mi < 4; mi++) {
        const int row = m0 + warp_m * 64 + mi * 16 + gi;
        #pragma unroll
        for (int nj = 0; nj < 8; nj++) {
            const int col = n0 + warp_n * 64 + nj * 8 + 2 * ti;
            if (HALF_OUT) {
                __half* C = (__half*)Cv;
                *(unsigned*)&C[(size_t)row * N + col] =
                    pack_h2(acc[mi][nj][0], acc[mi][nj][1]);
                *(unsigned*)&C[(size_t)(row + 8) * N + col] =
                    pack_h2(acc[mi][nj][2], acc[mi][nj][3]);
            } else {
                float* C = (float*)Cv;
                *(float2*)&C[(size_t)row * N + col] =
                    make_float2(acc[mi][nj][0], acc[mi][nj][1]);
                *(float2*)&C[(size_t)(row + 8) * N + col] =
                    make_float2(acc[mi][nj][2], acc[mi][nj][3]);
            }
        }
    }
}

// ---------------------------------------------------------------------------
// Flash attention, fp16 m16n8k16. Br=128, Bc=64, 128 threads = 4 warps,
// warp owns 32 query rows (2 m16 halves sharing every K/V b-fragment).
// P stays in registers. V consumed as V^T. 3-deep cp.async KV pipeline.
//   smem: K0..K2, Vt0..Vt2 (64x144B each) + Q (128x144B) = 73728 B
// ---------------------------------------------------------------------------
#define KV_TILEB (64 * H_ROWB)             // 9216 B
#define AQ_OFF   (6 * KV_TILEB)
#define ATTN_SMEM_BYTES (6 * KV_TILEB + 128 * H_ROWB)   // 73728 B
#define QSCALE  (0.125f * 1.4426950408889634f)          // log2e / sqrt(dh)

__global__ __launch_bounds__(128, 2)
void flash_attn_f16_kernel() {
    extern __shared__ char smc[];
    const unsigned smb = smem_u32(smc);

    const int tid  = threadIdx.x;
    const int lane = tid & 31;
    const int wid  = tid >> 5;          // 0..3
    const int gi   = lane >> 2;
    const int ti   = lane & 3;
    const int bh = blockIdx.y;
    const int b = bh >> 4, h = bh & 15;
    const int qb = blockIdx.x;          // 128-row query tile

    const __half* qbase = g_qkv + (size_t)(b * SEQ + qb * 128) * QKVN + h * DH;
    const __half* kbase = g_qkv + (size_t)(b * SEQ) * QKVN + EMB + h * DH;
    const __half* vtbase = g_vT + (size_t)bh * DH * SEQ;

    // 64-row x 64-half tiles = 512 16B chunks each
    auto stage_kv = [&](int jt, int buf) {
        const unsigned kb = smb + buf * KV_TILEB;
        const unsigned vb = smb + (3 + buf) * KV_TILEB;
        #pragma unroll
        for (int i = 0; i < 4; i++) {
            int idx = tid + i * 128;    // 0..511
            int r = idx >> 3, c = idx & 7;
            cp16(kb + r * H_ROWB + c * 16,
                 kbase + (size_t)(jt * 64 + r) * QKVN + c * 8);
            cp16(vb + r * H_ROWB + c * 16,
                 vtbase + (size_t)r * SEQ + jt * 64 + c * 8);
        }
    };

    // Prologue: group0 = {KV tile 0, Q}; group1 = {KV tile 1}
    stage_kv(0, 0);
    {
        const unsigned qsm = smb + AQ_OFF;
        #pragma unroll
        for (int i = 0; i < 8; i++) {   // 128 rows x 8 chunks = 1024
            int idx = tid + i * 128;
            int r = idx >> 3, c = idx & 7;
            cp16(qsm + r * H_ROWB + c * 16, qbase + (size_t)r * QKVN + c * 8);
        }
    }
    CP_COMMIT();
    stage_kv(1, 1);
    CP_COMMIT();

    // Wait for group0 (Q + tile 0); group1 may still be in flight.
    CP_WAIT(1);
    __syncthreads();

    // Warp rows [wid*32, wid*32+32): half 0 = +{gi,gi+8}, half 1 = +16.
    const unsigned* Qw = (const unsigned*)(smc + AQ_OFF);
    unsigned qa[2][4][4];
    #pragma unroll
    for (int kc = 0; kc < 4; kc++) {
        #pragma unroll
        for (int hh = 0; hh < 2; hh++) {
            const int r = wid * 32 + hh * 16 + gi;
            const int w = kc * 8 + ti;
            qa[hh][kc][0] = Qw[r * H_ROWW + w];
            qa[hh][kc][1] = Qw[(r + 8) * H_ROWW + w];
            qa[hh][kc][2] = Qw[r * H_ROWW + w + 4];
            qa[hh][kc][3] = Qw[(r + 8) * H_ROWW + w + 4];
        }
    }

    float o[2][8][4];
    #pragma unroll
    for (int hh = 0; hh < 2; hh++)
        #pragma unroll
        for (int j = 0; j < 8; j++)
            o[hh][j][0] = o[hh][j][1] = o[hh][j][2] = o[hh][j][3] = 0.0f;
    float mrow[2][2] = {{-1e30f, -1e30f}, {-1e30f, -1e30f}};
    float lrow[2][2] = {{0.0f, 0.0f}, {0.0f, 0.0f}};

    const int NT = SEQ / 64;
    for (int jt = 0; jt < NT; jt++) {
        const int buf = jt % 3;
        // Tile jt's group is complete once at most one newer group pends.
        if (jt + 1 < NT) { CP_WAIT(1); } else { CP_WAIT(0); }
        __syncthreads();    // also proves buffer (jt+2)%3's old readers done
        if (jt + 2 < NT) { stage_kv(jt + 2, (jt + 2) % 3); CP_COMMIT(); }

        const unsigned* Ks = (const unsigned*)(smc + buf * KV_TILEB);
        const unsigned* Vs = (const unsigned*)(smc + (3 + buf) * KV_TILEB);

        // ---- S = Q @ K^T  (n = t 64-wide: 8 tiles; k = d: 4 k16 steps)
        float s[2][8][4];
        #pragma unroll
        for (int hh = 0; hh < 2; hh++)
            #pragma unroll
            for (int j = 0; j < 8; j++)
                s[hh][j][0] = s[hh][j][1] = s[hh][j][2] = s[hh][j][3] = 0.0f;
        #pragma unroll
        for (int kc = 0; kc < 4; kc++) {
            #pragma unroll
            for (int j = 0; j < 8; j++) {
                const int rn = j * 8 + gi;
                const int w = kc * 8 + ti;
                unsigned b0 = Ks[rn * H_ROWW + w];
                unsigned b1 = Ks[rn * H_ROWW + w + 4];
                mma_f16(s[0][j], qa[0][kc], b0, b1);
                mma_f16(s[1][j], qa[1][kc], b0, b1);
            }
        }

        // ---- Online softmax (base-2, 1/sqrt(dh) folded into exp argument)
        unsigned pa[2][4][4];     // P packed directly as PV A-fragments
        #pragma unroll
        for (int hh = 0; hh < 2; hh++) {
            float a0 = -1e30f, a1 = -1e30f;
            #pragma unroll
            for (int j = 0; j < 8; j++) {
                a0 = fmaxf(a0, fmaxf(s[hh][j][0], s[hh][j][1]));
                a1 = fmaxf(a1, fmaxf(s[hh][j][2], s[hh][j][3]));
            }
            a0 = fmaxf(a0, __shfl_xor_sync(0xffffffffu, a0, 1));
            a0 = fmaxf(a0, __shfl_xor_sync(0xffffffffu, a0, 2));
            a1 = fmaxf(a1, __shfl_xor_sync(0xffffffffu, a1, 1));
            a1 = fmaxf(a1, __shfl_xor_sync(0xffffffffu, a1, 2));

            float mn0 = fmaxf(mrow[hh][0], a0), mn1 = fmaxf(mrow[hh][1], a1);
            float c0 = ex2((mrow[hh][0] - mn0) * QSCALE);
            float c1 = ex2((mrow[hh][1] - mn1) * QSCALE);
            float z0 = mn0 * QSCALE, z1 = mn1 * QSCALE;
            float sum0 = 0.0f, sum1 = 0.0f;
            #pragma unroll
            for (int j = 0; j < 8; j++) {
                float p00 = ex2(fmaf(s[hh][j][0], QSCALE, -z0));
                float p01 = ex2(fmaf(s[hh][j][1], QSCALE, -z0));
                float p10 = ex2(fmaf(s[hh][j][2], QSCALE, -z1));
                float p11 = ex2(fmaf(s[hh][j][3], QSCALE, -z1));
                sum0 += p00 + p01;
                sum1 += p10 + p11;
                s[hh][j][0] = p00; s[hh][j][1] = p01;
                s[hh][j][2] = p10; s[hh][j][3] = p11;
            }
            sum0 += __shfl_xor_sync(0xffffffffu, sum0, 1);
            sum0 += __shfl_xor_sync(0xffffffffu, sum0, 2);
            sum1 += __shfl_xor_sync(0xffffffffu, sum1, 1);
            sum1 += __shfl_xor_sync(0xffffffffu, sum1, 2);

            mrow[hh][0] = mn0; mrow[hh][1] = mn1;
            lrow[hh][0] = lrow[hh][0] * c0 + sum0;
            lrow[hh][1] = lrow[hh][1] * c1 + sum1;

            #pragma unroll
            for (int j = 0; j < 8; j++) {
                o[hh][j][0] *= c0; o[hh][j][1] *= c0;
                o[hh][j][2] *= c1; o[hh][j][3] *= c1;
            }
            // Pack P: k16-step kc spans S n-tiles {2kc, 2kc+1}
            #pragma unroll
            for (int kc = 0; kc < 4; kc++) {
                pa[hh][kc][0] = pack_h2(s[hh][2 * kc][0],     s[hh][2 * kc][1]);
                pa[hh][kc][1] = pack_h2(s[hh][2 * kc][2],     s[hh][2 * kc][3]);
                pa[hh][kc][2] = pack_h2(s[hh][2 * kc + 1][0], s[hh][2 * kc + 1][1]);
                pa[hh][kc][3] = pack_h2(s[hh][2 * kc + 1][2], s[hh][2 * kc + 1][3]);
            }
        }

        // ---- O += P @ V  (n = d: 8 tiles; k = t: 4 k16 steps; Vt[d][t])
        #pragma unroll
        for (int kc = 0; kc < 4; kc++) {
            #pragma unroll
            for (int j = 0; j < 8; j++) {
                const int rn = j * 8 + gi;
                const int w = kc * 8 + ti;
                unsigned b0 = Vs[rn * H_ROWW + w];
                unsigned b1 = Vs[rn * H_ROWW + w + 4];
                mma_f16(o[0][j], pa[0][kc], b0, b1);
                mma_f16(o[1][j], pa[1][kc], b0, b1);
            }
        }
    }

    // ---- Epilogue: normalize, fp16 store to g_att (feeds out-proj A)
    #pragma unroll
    for (int hh = 0; hh < 2; hh++) {
        const float inv0 = 1.0f / lrow[hh][0];
        const float inv1 = 1.0f / lrow[hh][1];
        const size_t row0 = (size_t)(b * SEQ + qb * 128 + wid * 32 + hh * 16 + gi);
        const size_t row1 = row0 + 8;
        #pragma unroll
        for (int j = 0; j < 8; j++) {
            size_t col = h * DH + j * 8 + 2 * ti;
            *(unsigned*)&g_att[row0 * EMB + col] =
                pack_h2(o[hh][j][0] * inv0, o[hh][j][1] * inv0);
            *(unsigned*)&g_att[row1 * EMB + col] =
                pack_h2(o[hh][j][2] * inv1, o[hh][j][3] * inv1);
        }
    }
}

// ---------------------------------------------------------------------------
// Launch
// ---------------------------------------------------------------------------
extern "C" void kernel_launch(void* const* d_in, const int* in_sizes, int n_in,
                              void* d_out, int out_size) {
    const float* x     = (const float*)d_in[0];   // [4,2048,1024]
    const float* w_qkv = (const float*)d_in[1];   // [1024,3072]
    const float* w_out = (const float*)d_in[2];   // [1024,1024]
    float* out = (float*)d_out;                   // [4,2048,1024]

    __half *xh, *wqT, *woT, *qkv, *att;
    cudaGetSymbolAddress((void**)&xh,  g_xh);
    cudaGetSymbolAddress((void**)&wqT, g_wqT);
    cudaGetSymbolAddress((void**)&woT, g_woT);
    cudaGetSymbolAddress((void**)&qkv, g_qkv);
    cudaGetSymbolAddress((void**)&att, g_att);

    cudaFuncSetAttribute(gemm_f16_kernel<true>,
                         cudaFuncAttributeMaxDynamicSharedMemorySize, GEMM_SMEM_BYTES);
    cudaFuncSetAttribute(gemm_f16_kernel<false>,
                         cudaFuncAttributeMaxDynamicSharedMemorySize, GEMM_SMEM_BYTES);
    cudaFuncSetAttribute(flash_attn_f16_kernel,
                         cudaFuncAttributeMaxDynamicSharedMemorySize, ATTN_SMEM_BYTES);

    // 0) Convert / transpose inputs to fp16
    cvt_h_kernel<<<(ROWS * EMB) / (256 * 8), 256>>>(x, xh);
    {
        dim3 g(QKVN / 32, EMB / 32);
        transpose_h_kernel<<<g, dim3(32, 8)>>>(w_qkv, wqT, EMB, QKVN);
    }
    {
        dim3 g(EMB / 32, EMB / 32);
        transpose_h_kernel<<<g, dim3(32, 8)>>>(w_out, woT, EMB, EMB);
    }

    // 1) QKV projection -> g_qkv (fp16)
    {
        dim3 grid(QKVN / 128, ROWS / 128);
        gemm_f16_kernel<true><<<grid, 128, GEMM_SMEM_BYTES>>>(xh, wqT, qkv, QKVN, EMB);
    }
    // 1b) V -> V^T per (b,h)
    {
        dim3 grid(SEQ / 64, BATCH * NH);
        transpose_v_kernel<<<grid, 128>>>();
    }
    // 2) Flash attention -> g_att (fp16)
    {
        dim3 grid(SEQ / 128, BATCH * NH);
        flash_attn_f16_kernel<<<grid, 128, ATTN_SMEM_BYTES>>>();
    }
    // 3) Output projection -> d_out (fp32)
    {
        dim3 grid(EMB / 128, ROWS / 128);
        gemm_f16_kernel<false><<<grid, 128, GEMM_SMEM_BYTES>>>(att, woT, out, EMB, EMB);
    }
}

// round 14
// speedup vs baseline: 6.5569x; 1.0738x over previous
#include <cuda_runtime.h>
#include <cuda_fp16.h>
#include <cstdint>

// Problem constants
#define BATCH 4
#define SEQ   2048
#define EMB   1024
#define NH    16
#define DH    64
#define ROWS  (BATCH * SEQ)        // 8192
#define QKVN  (3 * EMB)            // 3072

// Scratch (allocation-guard-safe device globals), fp16 datapath
__device__ __half g_xh [(size_t)ROWS * EMB];    // x, fp16            16 MB
__device__ __half g_wqT[(size_t)QKVN * EMB];    // w_qkv^T [3072][1024] 6 MB
__device__ __half g_woT[(size_t)EMB * EMB];     // w_out^T [1024][1024] 2 MB
__device__ __half g_qkv[(size_t)ROWS * QKVN];   // qkv, fp16           48 MB
__device__ __half g_vT [(size_t)ROWS * EMB];    // V^T per (b,h): [bh][64][2048] 16 MB
__device__ __half g_att[(size_t)ROWS * EMB];    // attention out, fp16 16 MB

// ---------------------------------------------------------------------------
// Helpers
// ---------------------------------------------------------------------------
__device__ __forceinline__ float ex2(float x) {
    float r;
    asm("ex2.approx.f32 %0, %1;" : "=f"(r) : "f"(x));
    return r;
}

__device__ __forceinline__ unsigned smem_u32(const void* p) {
    return (unsigned)__cvta_generic_to_shared(p);
}

__device__ __forceinline__ void cp16(unsigned dst, const void* src) {
    asm volatile("cp.async.cg.shared.global [%0], [%1], 16;"
                 :: "r"(dst), "l"(__cvta_generic_to_global(src)));
}
#define CP_COMMIT() asm volatile("cp.async.commit_group;" ::: "memory")
#define CP_WAIT(n)  asm volatile("cp.async.wait_group %0;" :: "n"(n) : "memory")

// fp16 m16n8k16: D(f32) += A(f16) @ B(f16). NOT volatile (pure, reorderable).
__device__ __forceinline__ void mma_f16(float d[4], const unsigned a[4],
                                        unsigned b0, unsigned b1) {
    asm("mma.sync.aligned.m16n8k16.row.col.f32.f16.f16.f32 "
        "{%0,%1,%2,%3}, {%4,%5,%6,%7}, {%8,%9}, {%0,%1,%2,%3};\n"
        : "+f"(d[0]), "+f"(d[1]), "+f"(d[2]), "+f"(d[3])
        : "r"(a[0]), "r"(a[1]), "r"(a[2]), "r"(a[3]), "r"(b0), "r"(b1));
}

// ldmatrix x4: four 8x8 fp16 matrices -> 4 regs (lanes 0-7 mat0, 8-15 mat1, ...)
__device__ __forceinline__ void ldsm_x4(unsigned& r0, unsigned& r1,
                                        unsigned& r2, unsigned& r3,
                                        unsigned addr) {
    asm volatile("ldmatrix.sync.aligned.m8n8.x4.shared.b16 {%0,%1,%2,%3}, [%4];"
                 : "=r"(r0), "=r"(r1), "=r"(r2), "=r"(r3) : "r"(addr));
}

__device__ __forceinline__ unsigned pack_h2(float lo, float hi) {
    __half2 h = __floats2half2_rn(lo, hi);
    return *reinterpret_cast<unsigned*>(&h);
}

// ---------------------------------------------------------------------------
// Prep kernels
// ---------------------------------------------------------------------------
__global__ __launch_bounds__(256)
void cvt_h_kernel(const float* __restrict__ in, __half* __restrict__ out) {
    size_t i = ((size_t)blockIdx.x * 256 + threadIdx.x) * 8;
    float4 v0 = *(const float4*)(in + i);
    float4 v1 = *(const float4*)(in + i + 4);
    uint4 o;
    o.x = pack_h2(v0.x, v0.y); o.y = pack_h2(v0.z, v0.w);
    o.z = pack_h2(v1.x, v1.y); o.w = pack_h2(v1.z, v1.w);
    *(uint4*)(out + i) = o;
}

__global__ __launch_bounds__(256)
void transpose_h_kernel(const float* __restrict__ in, __half* __restrict__ out,
                        int R, int C) {
    __shared__ float tile[32][33];
    const int tx = threadIdx.x, ty = threadIdx.y;
    const int c0 = blockIdx.x * 32, r0 = blockIdx.y * 32;
    #pragma unroll
    for (int i = 0; i < 4; i++)
        tile[ty + i * 8][tx] = in[(size_t)(r0 + ty + i * 8) * C + c0 + tx];
    __syncthreads();
    #pragma unroll
    for (int i = 0; i < 4; i++)
        out[(size_t)(c0 + ty + i * 8) * R + r0 + tx] =
            __float2half_rn(tile[tx][ty + i * 8]);
}

// V transpose: g_qkv V region [t][d] -> g_vT [bh][d][t], 64x64 fp16 tiles
__global__ __launch_bounds__(128)
void transpose_v_kernel() {
    __shared__ __half tile[64 * 74];
    const int tid = threadIdx.x;
    const int bh = blockIdx.y;
    const int b = bh >> 4, h = bh & 15;
    const int t0 = blockIdx.x * 64;
    const __half* src = g_qkv + (size_t)(b * SEQ + t0) * QKVN + 2 * EMB + h * DH;
    __half* dst = g_vT + (size_t)bh * DH * SEQ + t0;

    unsigned* tw = (unsigned*)tile;
    #pragma unroll
    for (int i = 0; i < 16; i++) {
        int idx = tid + i * 128;
        int r = idx >> 5, c2 = idx & 31;
        unsigned v = *(const unsigned*)(src + (size_t)r * QKVN + c2 * 2);
        tw[(r * 74 + c2 * 2) >> 1] = v;
    }
    __syncthreads();
    const unsigned short* th = (const unsigned short*)tile;
    #pragma unroll
    for (int i = 0; i < 16; i++) {
        int idx = tid + i * 128;
        int d = idx >> 5, tc = idx & 31;
        unsigned lo = th[(2 * tc) * 74 + d];
        unsigned hi = th[(2 * tc + 1) * 74 + d];
        *(unsigned*)(dst + (size_t)d * SEQ + 2 * tc) = lo | (hi << 16);
    }
}

// ---------------------------------------------------------------------------
// fp16 GEMM: C[M,N] = A[M,K] @ Bt[N,K]^T. A, Bt fp16 k-major. BK=64.
// Block tile 128x128, 3-stage cp.async, 128 threads = 4 warps (2x2),
// warp tile 64x64, m16n8k16, ldmatrix.x4 fragment loads.
// ---------------------------------------------------------------------------
#define H_ROWB 144                         // bytes per smem row
#define G_TILEB (128 * H_ROWB)             // 18432 B (A or Bt tile)
#define G_STAGE (2 * G_TILEB)              // 36864 B
#define G_STAGES 3
#define GEMM_SMEM_BYTES (G_STAGES * G_STAGE)   // 110592 B

template<bool HALF_OUT>
__global__ __launch_bounds__(128, 2)
void gemm_f16_kernel(const __half* __restrict__ A, const __half* __restrict__ Bt,
                     void* __restrict__ Cv, int N, int K) {
    extern __shared__ char smc[];
    const unsigned abase0 = smem_u32(smc);
    const unsigned bbase0 = abase0 + G_TILEB;

    const int tid  = threadIdx.x;
    const int lane = tid & 31;
    const int wid  = tid >> 5;
    const int gi   = lane >> 2;
    const int ti   = lane & 3;
    const int warp_m = wid >> 1;
    const int warp_n = wid & 1;
    const int m0 = blockIdx.y * 128;
    const int n0 = blockIdx.x * 128;

    // ldmatrix per-lane addressing
    const int arow = lane & 15;                         // A: rows 0..15
    const int ahi  = (lane >> 4) << 4;                  // +16B for k+8 half
    const int brow = (lane & 7) + ((lane >> 4) << 3);   // B: rows 0..7 / 8..15
    const int bhi  = ((lane >> 3) & 1) << 4;            // +16B for k+8 half

    auto stage = [&](int t, int buf) {
        const unsigned ab = abase0 + buf * G_STAGE;
        const unsigned bb = bbase0 + buf * G_STAGE;
        const __half* Ag = A  + (size_t)m0 * K + t * 64;
        const __half* Bg = Bt + (size_t)n0 * K + t * 64;
        #pragma unroll
        for (int i = 0; i < 8; i++) {
            int idx = tid + i * 128;
            int r = idx >> 3, c = idx & 7;     // 128 rows x 8 chunks
            cp16(ab + r * H_ROWB + c * 16, Ag + (size_t)r * K + c * 8);
            cp16(bb + r * H_ROWB + c * 16, Bg + (size_t)r * K + c * 8);
        }
    };

    float acc[4][8][4];
    #pragma unroll
    for (int i = 0; i < 4; i++)
        #pragma unroll
        for (int j = 0; j < 8; j++)
            acc[i][j][0] = acc[i][j][1] = acc[i][j][2] = acc[i][j][3] = 0.0f;

    const int KT = K >> 6;                     // 16 k-tiles
    stage(0, 0); CP_COMMIT();
    stage(1, 1); CP_COMMIT();

    for (int t = 0; t < KT; t++) {
        const int buf = t % G_STAGES;
        if (t + 1 < KT) { CP_WAIT(1); } else { CP_WAIT(0); }
        __syncthreads();
        if (t + 2 < KT) { stage(t + 2, (t + 2) % G_STAGES); CP_COMMIT(); }

        const unsigned As_addr = abase0 + buf * G_STAGE;
        const unsigned Bs_addr = bbase0 + buf * G_STAGE;
        #pragma unroll
        for (int s = 0; s < 4; s++) {          // 4 x k16 steps
            unsigned af[4][4];
            unsigned bf[8][2];
            #pragma unroll
            for (int mi = 0; mi < 4; mi++)
                ldsm_x4(af[mi][0], af[mi][1], af[mi][2], af[mi][3],
                        As_addr + (warp_m * 64 + mi * 16 + arow) * H_ROWB
                                + s * 32 + ahi);
            #pragma unroll
            for (int njp = 0; njp < 4; njp++)
                ldsm_x4(bf[2 * njp][0], bf[2 * njp][1],
                        bf[2 * njp + 1][0], bf[2 * njp + 1][1],
                        Bs_addr + (warp_n * 64 + njp * 16 + brow) * H_ROWB
                                + s * 32 + bhi);
            #pragma unroll
            for (int mi = 0; mi < 4; mi++)
                #pragma unroll
                for (int nj = 0; nj < 8; nj++)
                    mma_f16(acc[mi][nj], af[mi], bf[nj][0], bf[nj][1]);
        }
    }

    #pragma unroll
    for (int mi = 0; mi < 4; mi++) {
        const int row = m0 + warp_m * 64 + mi * 16 + gi;
        #pragma unroll
        for (int nj = 0; nj < 8; nj++) {
            const int col = n0 + warp_n * 64 + nj * 8 + 2 * ti;
            if (HALF_OUT) {
                __half* C = (__half*)Cv;
                *(unsigned*)&C[(size_t)row * N + col] =
                    pack_h2(acc[mi][nj][0], acc[mi][nj][1]);
                *(unsigned*)&C[(size_t)(row + 8) * N + col] =
                    pack_h2(acc[mi][nj][2], acc[mi][nj][3]);
            } else {
                float* C = (float*)Cv;
                *(float2*)&C[(size_t)row * N + col] =
                    make_float2(acc[mi][nj][0], acc[mi][nj][1]);
                *(float2*)&C[(size_t)(row + 8) * N + col] =
                    make_float2(acc[mi][nj][2], acc[mi][nj][3]);
            }
        }
    }
}

// ---------------------------------------------------------------------------
// Flash attention, fp16 m16n8k16 + ldmatrix. Br=128, Bc=64, 128 threads =
// 4 warps, warp owns 32 query rows (2 m16 halves sharing every K/V b-frag).
// P stays in registers. V consumed as V^T. 3-deep cp.async KV pipeline.
//   smem: K0..K2, Vt0..Vt2 (64x144B each) + Q (128x144B) = 73728 B
// ---------------------------------------------------------------------------
#define H_ROWW 36
#define KV_TILEB (64 * H_ROWB)             // 9216 B
#define AQ_OFF   (6 * KV_TILEB)
#define ATTN_SMEM_BYTES (6 * KV_TILEB + 128 * H_ROWB)   // 73728 B
#define QSCALE  (0.125f * 1.4426950408889634f)          // log2e / sqrt(dh)

__global__ __launch_bounds__(128, 2)
void flash_attn_f16_kernel() {
    extern __shared__ char smc[];
    const unsigned smb = smem_u32(smc);

    const int tid  = threadIdx.x;
    const int lane = tid & 31;
    const int wid  = tid >> 5;          // 0..3
    const int gi   = lane >> 2;
    const int ti   = lane & 3;
    const int bh = blockIdx.y;
    const int b = bh >> 4, h = bh & 15;
    const int qb = blockIdx.x;          // 128-row query tile

    const __half* qbase = g_qkv + (size_t)(b * SEQ + qb * 128) * QKVN + h * DH;
    const __half* kbase = g_qkv + (size_t)(b * SEQ) * QKVN + EMB + h * DH;
    const __half* vtbase = g_vT + (size_t)bh * DH * SEQ;

    // ldmatrix b-fragment addressing (shared by K and Vt tiles)
    const int brow = (lane & 7) + ((lane >> 4) << 3);
    const int bhi  = ((lane >> 3) & 1) << 4;

    auto stage_kv = [&](int jt, int buf) {
        const unsigned kb = smb + buf * KV_TILEB;
        const unsigned vb = smb + (3 + buf) * KV_TILEB;
        #pragma unroll
        for (int i = 0; i < 4; i++) {
            int idx = tid + i * 128;    // 0..511
            int r = idx >> 3, c = idx & 7;
            cp16(kb + r * H_ROWB + c * 16,
                 kbase + (size_t)(jt * 64 + r) * QKVN + c * 8);
            cp16(vb + r * H_ROWB + c * 16,
                 vtbase + (size_t)r * SEQ + jt * 64 + c * 8);
        }
    };

    // Prologue: group0 = {KV tile 0, Q}; group1 = {KV tile 1}
    stage_kv(0, 0);
    {
        const unsigned qsm = smb + AQ_OFF;
        #pragma unroll
        for (int i = 0; i < 8; i++) {   // 128 rows x 8 chunks
            int idx = tid + i * 128;
            int r = idx >> 3, c = idx & 7;
            cp16(qsm + r * H_ROWB + c * 16, qbase + (size_t)r * QKVN + c * 8);
        }
    }
    CP_COMMIT();
    stage_kv(1, 1);
    CP_COMMIT();

    CP_WAIT(1);
    __syncthreads();

    // Q a-fragments (one-time scalar loads)
    const unsigned* Qw = (const unsigned*)(smc + AQ_OFF);
    unsigned qa[2][4][4];
    #pragma unroll
    for (int kc = 0; kc < 4; kc++) {
        #pragma unroll
        for (int hh = 0; hh < 2; hh++) {
            const int r = wid * 32 + hh * 16 + gi;
            const int w = kc * 8 + ti;
            qa[hh][kc][0] = Qw[r * H_ROWW + w];
            qa[hh][kc][1] = Qw[(r + 8) * H_ROWW + w];
            qa[hh][kc][2] = Qw[r * H_ROWW + w + 4];
            qa[hh][kc][3] = Qw[(r + 8) * H_ROWW + w + 4];
        }
    }

    float o[2][8][4];
    #pragma unroll
    for (int hh = 0; hh < 2; hh++)
        #pragma unroll
        for (int j = 0; j < 8; j++)
            o[hh][j][0] = o[hh][j][1] = o[hh][j][2] = o[hh][j][3] = 0.0f;
    float mrow[2][2] = {{-1e30f, -1e30f}, {-1e30f, -1e30f}};
    float lrow[2][2] = {{0.0f, 0.0f}, {0.0f, 0.0f}};

    const int NT = SEQ / 64;
    for (int jt = 0; jt < NT; jt++) {
        const int buf = jt % 3;
        if (jt + 1 < NT) { CP_WAIT(1); } else { CP_WAIT(0); }
        __syncthreads();
        if (jt + 2 < NT) { stage_kv(jt + 2, (jt + 2) % 3); CP_COMMIT(); }

        const unsigned Ks_addr = smb + buf * KV_TILEB;
        const unsigned Vs_addr = smb + (3 + buf) * KV_TILEB;

        // ---- S = Q @ K^T  (n = t: 8 tiles; k = d: 4 k16 steps)
        float s[2][8][4];
        #pragma unroll
        for (int hh = 0; hh < 2; hh++)
            #pragma unroll
            for (int j = 0; j < 8; j++)
                s[hh][j][0] = s[hh][j][1] = s[hh][j][2] = s[hh][j][3] = 0.0f;
        #pragma unroll
        for (int kc = 0; kc < 4; kc++) {
            unsigned bf[8][2];
            #pragma unroll
            for (int jp = 0; jp < 4; jp++)
                ldsm_x4(bf[2 * jp][0], bf[2 * jp][1],
                        bf[2 * jp + 1][0], bf[2 * jp + 1][1],
                        Ks_addr + (jp * 16 + brow) * H_ROWB + kc * 32 + bhi);
            #pragma unroll
            for (int j = 0; j < 8; j++) {
                mma_f16(s[0][j], qa[0][kc], bf[j][0], bf[j][1]);
                mma_f16(s[1][j], qa[1][kc], bf[j][0], bf[j][1]);
            }
        }

        // ---- Online softmax (base-2, 1/sqrt(dh) folded into exp argument)
        unsigned pa[2][4][4];     // P packed directly as PV A-fragments
        #pragma unroll
        for (int hh = 0; hh < 2; hh++) {
            float a0 = -1e30f, a1 = -1e30f;
            #pragma unroll
            for (int j = 0; j < 8; j++) {
                a0 = fmaxf(a0, fmaxf(s[hh][j][0], s[hh][j][1]));
                a1 = fmaxf(a1, fmaxf(s[hh][j][2], s[hh][j][3]));
            }
            a0 = fmaxf(a0, __shfl_xor_sync(0xffffffffu, a0, 1));
            a0 = fmaxf(a0, __shfl_xor_sync(0xffffffffu, a0, 2));
            a1 = fmaxf(a1, __shfl_xor_sync(0xffffffffu, a1, 1));
            a1 = fmaxf(a1, __shfl_xor_sync(0xffffffffu, a1, 2));

            float mn0 = fmaxf(mrow[hh][0], a0), mn1 = fmaxf(mrow[hh][1], a1);
            float c0 = ex2((mrow[hh][0] - mn0) * QSCALE);
            float c1 = ex2((mrow[hh][1] - mn1) * QSCALE);
            float z0 = mn0 * QSCALE, z1 = mn1 * QSCALE;
            float sum0 = 0.0f, sum1 = 0.0f;
            #pragma unroll
            for (int j = 0; j < 8; j++) {
                float p00 = ex2(fmaf(s[hh][j][0], QSCALE, -z0));
                float p01 = ex2(fmaf(s[hh][j][1], QSCALE, -z0));
                float p10 = ex2(fmaf(s[hh][j][2], QSCALE, -z1));
                float p11 = ex2(fmaf(s[hh][j][3], QSCALE, -z1));
                sum0 += p00 + p01;
                sum1 += p10 + p11;
                s[hh][j][0] = p00; s[hh][j][1] = p01;
                s[hh][j][2] = p10; s[hh][j][3] = p11;
            }
            sum0 += __shfl_xor_sync(0xffffffffu, sum0, 1);
            sum0 += __shfl_xor_sync(0xffffffffu, sum0, 2);
            sum1 += __shfl_xor_sync(0xffffffffu, sum1, 1);
            sum1 += __shfl_xor_sync(0xffffffffu, sum1, 2);

            mrow[hh][0] = mn0; mrow[hh][1] = mn1;
            lrow[hh][0] = lrow[hh][0] * c0 + sum0;
            lrow[hh][1] = lrow[hh][1] * c1 + sum1;

            #pragma unroll
            for (int j = 0; j < 8; j++) {
                o[hh][j][0] *= c0; o[hh][j][1] *= c0;
                o[hh][j][2] *= c1; o[hh][j][3] *= c1;
            }
            #pragma unroll
            for (int kc = 0; kc < 4; kc++) {
                pa[hh][kc][0] = pack_h2(s[hh][2 * kc][0],     s[hh][2 * kc][1]);
                pa[hh][kc][1] = pack_h2(s[hh][2 * kc][2],     s[hh][2 * kc][3]);
                pa[hh][kc][2] = pack_h2(s[hh][2 * kc + 1][0], s[hh][2 * kc + 1][1]);
                pa[hh][kc][3] = pack_h2(s[hh][2 * kc + 1][2], s[hh][2 * kc + 1][3]);
            }
        }

        // ---- O += P @ V  (n = d: 8 tiles; k = t: 4 k16 steps; Vt[d][t])
        #pragma unroll
        for (int kc = 0; kc < 4; kc++) {
            unsigned bf[8][2];
            #pragma unroll
            for (int jp = 0; jp < 4; jp++)
                ldsm_x4(bf[2 * jp][0], bf[2 * jp][1],
                        bf[2 * jp + 1][0], bf[2 * jp + 1][1],
                        Vs_addr + (jp * 16 + brow) * H_ROWB + kc * 32 + bhi);
            #pragma unroll
            for (int j = 0; j < 8; j++) {
                mma_f16(o[0][j], pa[0][kc], bf[j][0], bf[j][1]);
                mma_f16(o[1][j], pa[1][kc], bf[j][0], bf[j][1]);
            }
        }
    }

    // ---- Epilogue: normalize, fp16 store to g_att (feeds out-proj A)
    #pragma unroll
    for (int hh = 0; hh < 2; hh++) {
        const float inv0 = 1.0f / lrow[hh][0];
        const float inv1 = 1.0f / lrow[hh][1];
        const size_t row0 = (size_t)(b * SEQ + qb * 128 + wid * 32 + hh * 16 + gi);
        const size_t row1 = row0 + 8;
        #pragma unroll
        for (int j = 0; j < 8; j++) {
            size_t col = h * DH + j * 8 + 2 * ti;
            *(unsigned*)&g_att[row0 * EMB + col] =
                pack_h2(o[hh][j][0] * inv0, o[hh][j][1] * inv0);
            *(unsigned*)&g_att[row1 * EMB + col] =
                pack_h2(o[hh][j][2] * inv1, o[hh][j][3] * inv1);
        }
    }
}

// ---------------------------------------------------------------------------
// Launch
// ---------------------------------------------------------------------------
extern "C" void kernel_launch(void* const* d_in, const int* in_sizes, int n_in,
                              void* d_out, int out_size) {
    const float* x     = (const float*)d_in[0];   // [4,2048,1024]
    const float* w_qkv = (const float*)d_in[1];   // [1024,3072]
    const float* w_out = (const float*)d_in[2];   // [1024,1024]
    float* out = (float*)d_out;                   // [4,2048,1024]

    __half *xh, *wqT, *woT, *qkv, *att;
    cudaGetSymbolAddress((void**)&xh,  g_xh);
    cudaGetSymbolAddress((void**)&wqT, g_wqT);
    cudaGetSymbolAddress((void**)&woT, g_woT);
    cudaGetSymbolAddress((void**)&qkv, g_qkv);
    cudaGetSymbolAddress((void**)&att, g_att);

    cudaFuncSetAttribute(gemm_f16_kernel<true>,
                         cudaFuncAttributeMaxDynamicSharedMemorySize, GEMM_SMEM_BYTES);
    cudaFuncSetAttribute(gemm_f16_kernel<false>,
                         cudaFuncAttributeMaxDynamicSharedMemorySize, GEMM_SMEM_BYTES);
    cudaFuncSetAttribute(flash_attn_f16_kernel,
                         cudaFuncAttributeMaxDynamicSharedMemorySize, ATTN_SMEM_BYTES);

    // 0) Convert / transpose inputs to fp16
    cvt_h_kernel<<<(ROWS * EMB) / (256 * 8), 256>>>(x, xh);
    {
        dim3 g(QKVN / 32, EMB / 32);
        transpose_h_kernel<<<g, dim3(32, 8)>>>(w_qkv, wqT, EMB, QKVN);
    }
    {
        dim3 g(EMB / 32, EMB / 32);
        transpose_h_kernel<<<g, dim3(32, 8)>>>(w_out, woT, EMB, EMB);
    }

    // 1) QKV projection -> g_qkv (fp16)
    {
        dim3 grid(QKVN / 128, ROWS / 128);
        gemm_f16_kernel<true><<<grid, 128, GEMM_SMEM_BYTES>>>(xh, wqT, qkv, QKVN, EMB);
    }
    // 1b) V -> V^T per (b,h)
    {
        dim3 grid(SEQ / 64, BATCH * NH);
        transpose_v_kernel<<<grid, 128>>>();
    }
    // 2) Flash attention -> g_att (fp16)
    {
        dim3 grid(SEQ / 128, BATCH * NH);
        flash_attn_f16_kernel<<<grid, 128, ATTN_SMEM_BYTES>>>();
    }
    // 3) Output projection -> d_out (fp32)
    {
        dim3 grid(EMB / 128, ROWS / 128);
        gemm_f16_kernel<false><<<grid, 128, GEMM_SMEM_BYTES>>>(att, woT, out, EMB, EMB);
    }
}

// round 15
// speedup vs baseline: 6.8101x; 1.0386x over previous
#include <cuda_runtime.h>
#include <cuda_fp16.h>
#include <cstdint>

// Problem constants
#define BATCH 4
#define SEQ   2048
#define EMB   1024
#define NH    16
#define DH    64
#define ROWS  (BATCH * SEQ)        // 8192
#define QKVN  (3 * EMB)            // 3072

// Scratch (allocation-guard-safe device globals), fp16 datapath
__device__ __half g_xh [(size_t)ROWS * EMB];    // x, fp16            16 MB
__device__ __half g_wqT[(size_t)QKVN * EMB];    // w_qkv^T [3072][1024] 6 MB
__device__ __half g_woT[(size_t)EMB * EMB];     // w_out^T [1024][1024] 2 MB
__device__ __half g_qkv[(size_t)ROWS * QKVN];   // qkv, fp16           48 MB
__device__ __half g_vT [(size_t)ROWS * EMB];    // V^T per (b,h): [bh][64][2048] 16 MB
__device__ __half g_att[(size_t)ROWS * EMB];    // attention out, fp16 16 MB

// ---------------------------------------------------------------------------
// Helpers
// ---------------------------------------------------------------------------
__device__ __forceinline__ float ex2(float x) {
    float r;
    asm("ex2.approx.f32 %0, %1;" : "=f"(r) : "f"(x));
    return r;
}

// f16x2 exp2: two exponentials per MUFU op; result is a packed half2
__device__ __forceinline__ unsigned h2ex2(unsigned x) {
    unsigned r;
    asm("ex2.approx.f16x2 %0, %1;" : "=r"(r) : "r"(x));
    return r;
}

__device__ __forceinline__ unsigned smem_u32(const void* p) {
    return (unsigned)__cvta_generic_to_shared(p);
}

__device__ __forceinline__ void cp16(unsigned dst, const void* src) {
    asm volatile("cp.async.cg.shared.global [%0], [%1], 16;"
                 :: "r"(dst), "l"(__cvta_generic_to_global(src)));
}
#define CP_COMMIT() asm volatile("cp.async.commit_group;" ::: "memory")
#define CP_WAIT(n)  asm volatile("cp.async.wait_group %0;" :: "n"(n) : "memory")

// fp16 m16n8k16: D(f32) += A(f16) @ B(f16). NOT volatile (pure, reorderable).
__device__ __forceinline__ void mma_f16(float d[4], const unsigned a[4],
                                        unsigned b0, unsigned b1) {
    asm("mma.sync.aligned.m16n8k16.row.col.f32.f16.f16.f32 "
        "{%0,%1,%2,%3}, {%4,%5,%6,%7}, {%8,%9}, {%0,%1,%2,%3};\n"
        : "+f"(d[0]), "+f"(d[1]), "+f"(d[2]), "+f"(d[3])
        : "r"(a[0]), "r"(a[1]), "r"(a[2]), "r"(a[3]), "r"(b0), "r"(b1));
}

// ldmatrix x4. NOT volatile (reads ordered by the surrounding barriers).
__device__ __forceinline__ void ldsm_x4(unsigned& r0, unsigned& r1,
                                        unsigned& r2, unsigned& r3,
                                        unsigned addr) {
    asm("ldmatrix.sync.aligned.m8n8.x4.shared.b16 {%0,%1,%2,%3}, [%4];"
        : "=r"(r0), "=r"(r1), "=r"(r2), "=r"(r3) : "r"(addr));
}

__device__ __forceinline__ unsigned pack_h2(float lo, float hi) {
    __half2 h = __floats2half2_rn(lo, hi);
    return *reinterpret_cast<unsigned*>(&h);
}

// ---------------------------------------------------------------------------
// Prep kernels
// ---------------------------------------------------------------------------
__global__ __launch_bounds__(256)
void cvt_h_kernel(const float* __restrict__ in, __half* __restrict__ out) {
    size_t i = ((size_t)blockIdx.x * 256 + threadIdx.x) * 8;
    float4 v0 = *(const float4*)(in + i);
    float4 v1 = *(const float4*)(in + i + 4);
    uint4 o;
    o.x = pack_h2(v0.x, v0.y); o.y = pack_h2(v0.z, v0.w);
    o.z = pack_h2(v1.x, v1.y); o.w = pack_h2(v1.z, v1.w);
    *(uint4*)(out + i) = o;
}

__global__ __launch_bounds__(256)
void transpose_h_kernel(const float* __restrict__ in, __half* __restrict__ out,
                        int R, int C) {
    __shared__ float tile[32][33];
    const int tx = threadIdx.x, ty = threadIdx.y;
    const int c0 = blockIdx.x * 32, r0 = blockIdx.y * 32;
    #pragma unroll
    for (int i = 0; i < 4; i++)
        tile[ty + i * 8][tx] = in[(size_t)(r0 + ty + i * 8) * C + c0 + tx];
    __syncthreads();
    #pragma unroll
    for (int i = 0; i < 4; i++)
        out[(size_t)(c0 + ty + i * 8) * R + r0 + tx] =
            __float2half_rn(tile[tx][ty + i * 8]);
}

// V transpose: g_qkv V region [t][d] -> g_vT [bh][d][t], 64x64 fp16 tiles
__global__ __launch_bounds__(128)
void transpose_v_kernel() {
    __shared__ __half tile[64 * 74];
    const int tid = threadIdx.x;
    const int bh = blockIdx.y;
    const int b = bh >> 4, h = bh & 15;
    const int t0 = blockIdx.x * 64;
    const __half* src = g_qkv + (size_t)(b * SEQ + t0) * QKVN + 2 * EMB + h * DH;
    __half* dst = g_vT + (size_t)bh * DH * SEQ + t0;

    unsigned* tw = (unsigned*)tile;
    #pragma unroll
    for (int i = 0; i < 16; i++) {
        int idx = tid + i * 128;
        int r = idx >> 5, c2 = idx & 31;
        unsigned v = *(const unsigned*)(src + (size_t)r * QKVN + c2 * 2);
        tw[(r * 74 + c2 * 2) >> 1] = v;
    }
    __syncthreads();
    const unsigned short* th = (const unsigned short*)tile;
    #pragma unroll
    for (int i = 0; i < 16; i++) {
        int idx = tid + i * 128;
        int d = idx >> 5, tc = idx & 31;
        unsigned lo = th[(2 * tc) * 74 + d];
        unsigned hi = th[(2 * tc + 1) * 74 + d];
        *(unsigned*)(dst + (size_t)d * SEQ + 2 * tc) = lo | (hi << 16);
    }
}

// ---------------------------------------------------------------------------
// fp16 GEMM: C[M,N] = A[M,K] @ Bt[N,K]^T. A, Bt fp16 k-major. BK=64.
// Block tile 128x128, 3-stage cp.async, 128 threads = 4 warps (2x2),
// warp tile 64x64, m16n8k16, ldmatrix.x4 fragment loads.
// ---------------------------------------------------------------------------
#define H_ROWB 144                         // bytes per smem row
#define G_TILEB (128 * H_ROWB)             // 18432 B (A or Bt tile)
#define G_STAGE (2 * G_TILEB)              // 36864 B
#define G_STAGES 3
#define GEMM_SMEM_BYTES (G_STAGES * G_STAGE)   // 110592 B

template<bool HALF_OUT>
__global__ __launch_bounds__(128, 2)
void gemm_f16_kernel(const __half* __restrict__ A, const __half* __restrict__ Bt,
                     void* __restrict__ Cv, int N, int K) {
    extern __shared__ char smc[];
    const unsigned abase0 = smem_u32(smc);
    const unsigned bbase0 = abase0 + G_TILEB;

    const int tid  = threadIdx.x;
    const int lane = tid & 31;
    const int wid  = tid >> 5;
    const int gi   = lane >> 2;
    const int ti   = lane & 3;
    const int warp_m = wid >> 1;
    const int warp_n = wid & 1;
    const int m0 = blockIdx.y * 128;
    const int n0 = blockIdx.x * 128;

    const int arow = lane & 15;
    const int ahi  = (lane >> 4) << 4;
    const int brow = (lane & 7) + ((lane >> 4) << 3);
    const int bhi  = ((lane >> 3) & 1) << 4;

    auto stage = [&](int t, int buf) {
        const unsigned ab = abase0 + buf * G_STAGE;
        const unsigned bb = bbase0 + buf * G_STAGE;
        const __half* Ag = A  + (size_t)m0 * K + t * 64;
        const __half* Bg = Bt + (size_t)n0 * K + t * 64;
        #pragma unroll
        for (int i = 0; i < 8; i++) {
            int idx = tid + i * 128;
            int r = idx >> 3, c = idx & 7;
            cp16(ab + r * H_ROWB + c * 16, Ag + (size_t)r * K + c * 8);
            cp16(bb + r * H_ROWB + c * 16, Bg + (size_t)r * K + c * 8);
        }
    };

    float acc[4][8][4];
    #pragma unroll
    for (int i = 0; i < 4; i++)
        #pragma unroll
        for (int j = 0; j < 8; j++)
            acc[i][j][0] = acc[i][j][1] = acc[i][j][2] = acc[i][j][3] = 0.0f;

    const int KT = K >> 6;
    stage(0, 0); CP_COMMIT();
    stage(1, 1); CP_COMMIT();

    for (int t = 0; t < KT; t++) {
        const int buf = t % G_STAGES;
        if (t + 1 < KT) { CP_WAIT(1); } else { CP_WAIT(0); }
        __syncthreads();
        if (t + 2 < KT) { stage(t + 2, (t + 2) % G_STAGES); CP_COMMIT(); }

        const unsigned As_addr = abase0 + buf * G_STAGE;
        const unsigned Bs_addr = bbase0 + buf * G_STAGE;
        #pragma unroll
        for (int s = 0; s < 4; s++) {
            unsigned af[4][4];
            unsigned bf[8][2];
            #pragma unroll
            for (int mi = 0; mi < 4; mi++)
                ldsm_x4(af[mi][0], af[mi][1], af[mi][2], af[mi][3],
                        As_addr + (warp_m * 64 + mi * 16 + arow) * H_ROWB
                                + s * 32 + ahi);
            #pragma unroll
            for (int njp = 0; njp < 4; njp++)
                ldsm_x4(bf[2 * njp][0], bf[2 * njp][1],
                        bf[2 * njp + 1][0], bf[2 * njp + 1][1],
                        Bs_addr + (warp_n * 64 + njp * 16 + brow) * H_ROWB
                                + s * 32 + bhi);
            #pragma unroll
            for (int mi = 0; mi < 4; mi++)
                #pragma unroll
                for (int nj = 0; nj < 8; nj++)
                    mma_f16(acc[mi][nj], af[mi], bf[nj][0], bf[nj][1]);
        }
    }

    #pragma unroll
    for (int mi = 0; mi < 4; mi++) {
        const int row = m0 + warp_m * 64 + mi * 16 + gi;
        #pragma unroll
        for (int nj = 0; nj < 8; nj++) {
            const int col = n0 + warp_n * 64 + nj * 8 + 2 * ti;
            if (HALF_OUT) {
                __half* C = (__half*)Cv;
                *(unsigned*)&C[(size_t)row * N + col] =
                    pack_h2(acc[mi][nj][0], acc[mi][nj][1]);
                *(unsigned*)&C[(size_t)(row + 8) * N + col] =
                    pack_h2(acc[mi][nj][2], acc[mi][nj][3]);
            } else {
                float* C = (float*)Cv;
                *(float2*)&C[(size_t)row * N + col] =
                    make_float2(acc[mi][nj][0], acc[mi][nj][1]);
                *(float2*)&C[(size_t)(row + 8) * N + col] =
                    make_float2(acc[mi][nj][2], acc[mi][nj][3]);
            }
        }
    }
}

// ---------------------------------------------------------------------------
// Flash attention, fp16 m16n8k16 + ldmatrix. Br=128, Bc=64, 128 threads =
// 4 warps, warp owns 32 query rows (2 m16 halves sharing every K/V b-frag).
// P in registers; exp2 on f16x2 MUFU; row-sum l via ones-column mma
// (rides the same per-tile rescale as O). 3-deep cp.async KV pipeline.
//   smem: K0..K2, Vt0..Vt2 (64x144B each) + Q (128x144B) = 73728 B
// ---------------------------------------------------------------------------
#define H_ROWW 36
#define KV_TILEB (64 * H_ROWB)             // 9216 B
#define AQ_OFF   (6 * KV_TILEB)
#define ATTN_SMEM_BYTES (6 * KV_TILEB + 128 * H_ROWB)   // 73728 B
#define QSCALE  (0.125f * 1.4426950408889634f)          // log2e / sqrt(dh)

__global__ __launch_bounds__(128, 2)
void flash_attn_f16_kernel() {
    extern __shared__ char smc[];
    const unsigned smb = smem_u32(smc);

    const int tid  = threadIdx.x;
    const int lane = tid & 31;
    const int wid  = tid >> 5;          // 0..3
    const int gi   = lane >> 2;
    const int ti   = lane & 3;
    const int bh = blockIdx.y;
    const int b = bh >> 4, h = bh & 15;
    const int qb = blockIdx.x;          // 128-row query tile

    const __half* qbase = g_qkv + (size_t)(b * SEQ + qb * 128) * QKVN + h * DH;
    const __half* kbase = g_qkv + (size_t)(b * SEQ) * QKVN + EMB + h * DH;
    const __half* vtbase = g_vT + (size_t)bh * DH * SEQ;

    const int brow = (lane & 7) + ((lane >> 4) << 3);
    const int bhi  = ((lane >> 3) & 1) << 4;

    // Ones-column b-fragment: B[t][0]=1 for all t -> lanes with n-col gi==0
    const unsigned bones = (gi == 0) ? 0x3C003C00u : 0u;

    auto stage_kv = [&](int jt, int buf) {
        const unsigned kb = smb + buf * KV_TILEB;
        const unsigned vb = smb + (3 + buf) * KV_TILEB;
        #pragma unroll
        for (int i = 0; i < 4; i++) {
            int idx = tid + i * 128;    // 0..511
            int r = idx >> 3, c = idx & 7;
            cp16(kb + r * H_ROWB + c * 16,
                 kbase + (size_t)(jt * 64 + r) * QKVN + c * 8);
            cp16(vb + r * H_ROWB + c * 16,
                 vtbase + (size_t)r * SEQ + jt * 64 + c * 8);
        }
    };

    // Prologue: group0 = {KV tile 0, Q}; group1 = {KV tile 1}
    stage_kv(0, 0);
    {
        const unsigned qsm = smb + AQ_OFF;
        #pragma unroll
        for (int i = 0; i < 8; i++) {
            int idx = tid + i * 128;
            int r = idx >> 3, c = idx & 7;
            cp16(qsm + r * H_ROWB + c * 16, qbase + (size_t)r * QKVN + c * 8);
        }
    }
    CP_COMMIT();
    stage_kv(1, 1);
    CP_COMMIT();

    CP_WAIT(1);
    __syncthreads();

    // Q a-fragments (one-time scalar loads)
    const unsigned* Qw = (const unsigned*)(smc + AQ_OFF);
    unsigned qa[2][4][4];
    #pragma unroll
    for (int kc = 0; kc < 4; kc++) {
        #pragma unroll
        for (int hh = 0; hh < 2; hh++) {
            const int r = wid * 32 + hh * 16 + gi;
            const int w = kc * 8 + ti;
            qa[hh][kc][0] = Qw[r * H_ROWW + w];
            qa[hh][kc][1] = Qw[(r + 8) * H_ROWW + w];
            qa[hh][kc][2] = Qw[r * H_ROWW + w + 4];
            qa[hh][kc][3] = Qw[(r + 8) * H_ROWW + w + 4];
        }
    }

    float o[2][8][4];
    float osum[2][4];
    #pragma unroll
    for (int hh = 0; hh < 2; hh++) {
        #pragma unroll
        for (int j = 0; j < 8; j++)
            o[hh][j][0] = o[hh][j][1] = o[hh][j][2] = o[hh][j][3] = 0.0f;
        osum[hh][0] = osum[hh][1] = osum[hh][2] = osum[hh][3] = 0.0f;
    }
    float mrow[2][2] = {{-1e30f, -1e30f}, {-1e30f, -1e30f}};

    const int NT = SEQ / 64;
    for (int jt = 0; jt < NT; jt++) {
        const int buf = jt % 3;
        if (jt + 1 < NT) { CP_WAIT(1); } else { CP_WAIT(0); }
        __syncthreads();
        if (jt + 2 < NT) { stage_kv(jt + 2, (jt + 2) % 3); CP_COMMIT(); }

        const unsigned Ks_addr = smb + buf * KV_TILEB;
        const unsigned Vs_addr = smb + (3 + buf) * KV_TILEB;

        // ---- S = Q @ K^T
        float s[2][8][4];
        #pragma unroll
        for (int hh = 0; hh < 2; hh++)
            #pragma unroll
            for (int j = 0; j < 8; j++)
                s[hh][j][0] = s[hh][j][1] = s[hh][j][2] = s[hh][j][3] = 0.0f;
        #pragma unroll
        for (int kc = 0; kc < 4; kc++) {
            unsigned bf[8][2];
            #pragma unroll
            for (int jp = 0; jp < 4; jp++)
                ldsm_x4(bf[2 * jp][0], bf[2 * jp][1],
                        bf[2 * jp + 1][0], bf[2 * jp + 1][1],
                        Ks_addr + (jp * 16 + brow) * H_ROWB + kc * 32 + bhi);
            #pragma unroll
            for (int j = 0; j < 8; j++) {
                mma_f16(s[0][j], qa[0][kc], bf[j][0], bf[j][1]);
                mma_f16(s[1][j], qa[1][kc], bf[j][0], bf[j][1]);
            }
        }

        // ---- Online softmax (base-2). P computed directly in f16x2.
        unsigned pa[2][4][4];     // P packed as PV A-fragments
        #pragma unroll
        for (int hh = 0; hh < 2; hh++) {
            float a0 = -1e30f, a1 = -1e30f;
            #pragma unroll
            for (int j = 0; j < 8; j++) {
                a0 = fmaxf(a0, fmaxf(s[hh][j][0], s[hh][j][1]));
                a1 = fmaxf(a1, fmaxf(s[hh][j][2], s[hh][j][3]));
            }
            a0 = fmaxf(a0, __shfl_xor_sync(0xffffffffu, a0, 1));
            a0 = fmaxf(a0, __shfl_xor_sync(0xffffffffu, a0, 2));
            a1 = fmaxf(a1, __shfl_xor_sync(0xffffffffu, a1, 1));
            a1 = fmaxf(a1, __shfl_xor_sync(0xffffffffu, a1, 2));

            float mn0 = fmaxf(mrow[hh][0], a0), mn1 = fmaxf(mrow[hh][1], a1);
            float c0 = ex2((mrow[hh][0] - mn0) * QSCALE);
            float c1 = ex2((mrow[hh][1] - mn1) * QSCALE);
            float z0 = mn0 * QSCALE, z1 = mn1 * QSCALE;
            mrow[hh][0] = mn0; mrow[hh][1] = mn1;

            // Rescale O and the row-sum accumulator identically
            #pragma unroll
            for (int j = 0; j < 8; j++) {
                o[hh][j][0] *= c0; o[hh][j][1] *= c0;
                o[hh][j][2] *= c1; o[hh][j][3] *= c1;
            }
            osum[hh][0] *= c0; osum[hh][1] *= c0;
            osum[hh][2] *= c1; osum[hh][3] *= c1;

            // P = 2^(s*QSCALE - z) on the f16x2 MUFU path; lands packed.
            #pragma unroll
            for (int j = 0; j < 8; j++) {
                float y0 = fmaf(s[hh][j][0], QSCALE, -z0);
                float y1 = fmaf(s[hh][j][1], QSCALE, -z0);
                float y2 = fmaf(s[hh][j][2], QSCALE, -z1);
                float y3 = fmaf(s[hh][j][3], QSCALE, -z1);
                unsigned ph0 = h2ex2(pack_h2(y0, y1));
                unsigned ph1 = h2ex2(pack_h2(y2, y3));
                const int kc = j >> 1;
                const int pos = (j & 1) << 1;
                pa[hh][kc][pos]     = ph0;
                pa[hh][kc][pos + 1] = ph1;
            }
        }

        // ---- O += P @ V ; osum += P @ ones  (n = d: 8 tiles; k = t: 4 steps)
        #pragma unroll
        for (int kc = 0; kc < 4; kc++) {
            unsigned bf[8][2];
            #pragma unroll
            for (int jp = 0; jp < 4; jp++)
                ldsm_x4(bf[2 * jp][0], bf[2 * jp][1],
                        bf[2 * jp + 1][0], bf[2 * jp + 1][1],
                        Vs_addr + (jp * 16 + brow) * H_ROWB + kc * 32 + bhi);
            #pragma unroll
            for (int j = 0; j < 8; j++) {
                mma_f16(o[0][j], pa[0][kc], bf[j][0], bf[j][1]);
                mma_f16(o[1][j], pa[1][kc], bf[j][0], bf[j][1]);
            }
            mma_f16(osum[0], pa[0][kc], bones, bones);
            mma_f16(osum[1], pa[1][kc], bones, bones);
        }
    }

    // ---- Epilogue: l from the ones-column (quad leader holds col 0)
    #pragma unroll
    for (int hh = 0; hh < 2; hh++) {
        const int qlead = lane & 28;
        const float l0 = __shfl_sync(0xffffffffu, osum[hh][0], qlead);
        const float l1 = __shfl_sync(0xffffffffu, osum[hh][2], qlead);
        const float inv0 = 1.0f / l0;
        const float inv1 = 1.0f / l1;
        const size_t row0 = (size_t)(b * SEQ + qb * 128 + wid * 32 + hh * 16 + gi);
        const size_t row1 = row0 + 8;
        #pragma unroll
        for (int j = 0; j < 8; j++) {
            size_t col = h * DH + j * 8 + 2 * ti;
            *(unsigned*)&g_att[row0 * EMB + col] =
                pack_h2(o[hh][j][0] * inv0, o[hh][j][1] * inv0);
            *(unsigned*)&g_att[row1 * EMB + col] =
                pack_h2(o[hh][j][2] * inv1, o[hh][j][3] * inv1);
        }
    }
}

// ---------------------------------------------------------------------------
// Launch
// ---------------------------------------------------------------------------
extern "C" void kernel_launch(void* const* d_in, const int* in_sizes, int n_in,
                              void* d_out, int out_size) {
    const float* x     = (const float*)d_in[0];   // [4,2048,1024]
    const float* w_qkv = (const float*)d_in[1];   // [1024,3072]
    const float* w_out = (const float*)d_in[2];   // [1024,1024]
    float* out = (float*)d_out;                   // [4,2048,1024]

    __half *xh, *wqT, *woT, *qkv, *att;
    cudaGetSymbolAddress((void**)&xh,  g_xh);
    cudaGetSymbolAddress((void**)&wqT, g_wqT);
    cudaGetSymbolAddress((void**)&woT, g_woT);
    cudaGetSymbolAddress((void**)&qkv, g_qkv);
    cudaGetSymbolAddress((void**)&att, g_att);

    cudaFuncSetAttribute(gemm_f16_kernel<true>,
                         cudaFuncAttributeMaxDynamicSharedMemorySize, GEMM_SMEM_BYTES);
    cudaFuncSetAttribute(gemm_f16_kernel<false>,
                         cudaFuncAttributeMaxDynamicSharedMemorySize, GEMM_SMEM_BYTES);
    cudaFuncSetAttribute(flash_attn_f16_kernel,
                         cudaFuncAttributeMaxDynamicSharedMemorySize, ATTN_SMEM_BYTES);

    // 0) Convert / transpose inputs to fp16
    cvt_h_kernel<<<(ROWS * EMB) / (256 * 8), 256>>>(x, xh);
    {
        dim3 g(QKVN / 32, EMB / 32);
        transpose_h_kernel<<<g, dim3(32, 8)>>>(w_qkv, wqT, EMB, QKVN);
    }
    {
        dim3 g(EMB / 32, EMB / 32);
        transpose_h_kernel<<<g, dim3(32, 8)>>>(w_out, woT, EMB, EMB);
    }

    // 1) QKV projection -> g_qkv (fp16)
    {
        dim3 grid(QKVN / 128, ROWS / 128);
        gemm_f16_kernel<true><<<grid, 128, GEMM_SMEM_BYTES>>>(xh, wqT, qkv, QKVN, EMB);
    }
    // 1b) V -> V^T per (b,h)
    {
        dim3 grid(SEQ / 64, BATCH * NH);
        transpose_v_kernel<<<grid, 128>>>();
    }
    // 2) Flash attention -> g_att (fp16)
    {
        dim3 grid(SEQ / 128, BATCH * NH);
        flash_attn_f16_kernel<<<grid, 128, ATTN_SMEM_BYTES>>>();
    }
    // 3) Output projection -> d_out (fp32)
    {
        dim3 grid(EMB / 128, ROWS / 128);
        gemm_f16_kernel<false><<<grid, 128, GEMM_SMEM_BYTES>>>(att, woT, out, EMB, EMB);
    }
}